// round 11
// baseline (speedup 1.0000x reference)
#include <cuda_runtime.h>
#include <cuda_bf16.h>
#include <math.h>
#include <stdint.h>

// ---------------- problem constants ----------------
#define VOCAB   10000
#define D_GNN   64
#define L_TOK   8
#define DG      256
#define NH      4
#define HD      64
#define N_NODES 8192
#define N_EDGES 2048
#define FD      512
#define ROWS    16384

typedef __nv_bfloat16 bf16;

// ---------------- scratch (static device memory) ----------------
__device__ bf16  g_x   [N_NODES * FD];
__device__ bf16  g_e   [N_EDGES * FD];
__device__ bf16  g_msg [N_EDGES * FD];
__device__ float g_agg [N_NODES * FD];
__device__ bf16  g_h   [N_NODES * FD];
__device__ bf16  g_eh  [N_EDGES * FD];
__device__ bf16  g_zg  [ROWS * DG];
__device__ bf16  g_qkv [ROWS * 3 * DG];
__device__ bf16  g_ao  [ROWS * DG];
__device__ bf16  g_x1  [ROWS * DG];
__device__ bf16  g_ffn [ROWS * 4 * DG];
__device__ bf16  g_x2  [ROWS * DG];
__device__ bf16  g_wmsg [FD * FD];
__device__ bf16  g_wnode[FD * FD];
__device__ bf16  g_lc1w [D_GNN * DG];
__device__ bf16  g_lc2w [DG * D_GNN];
__device__ bf16  g_wo   [DG * DG];
__device__ bf16  g_wf1  [DG * 4 * DG];
__device__ bf16  g_wf2  [4 * DG * DG];
__device__ bf16  g_wqkv [DG * 3 * DG];
__device__ bf16  g_embf [VOCAB * D_GNN];
__device__ int   g_mtok[N_EDGES * L_TOK];
__device__ int   g_mask_mode;

// ---------------- mask dtype detection ----------------
__global__ void detect_mask_kernel(const int* __restrict__ mr) {
    __shared__ int notint, notflt;
    if (threadIdx.x == 0) { notint = 0; notflt = 0; }
    __syncthreads();
    int w = mr[threadIdx.x];
    if (w != 0 && w != 1)          atomicExch(&notint, 1);
    if (w != 0 && w != 0x3F800000) atomicExch(&notflt, 1);
    __syncthreads();
    if (threadIdx.x == 0)
        g_mask_mode = notint ? (notflt ? 2 : 1) : 0;
}

__global__ void mask_kernel(const int* __restrict__ etok, const void* __restrict__ maskraw,
                            float* labels_out) {
    int i = blockIdx.x * blockDim.x + threadIdx.x;
    if (i >= N_EDGES * L_TOK) return;
    int e = i >> 3;
    int t = etok[i];
    bool mr;
    int mode = g_mask_mode;
    if (mode == 0)      mr = ((const int*)maskraw)[e] != 0;
    else if (mode == 1) mr = ((const float*)maskraw)[e] != 0.0f;
    else                mr = ((const unsigned char*)maskraw)[e] != 0;
    bool msk = mr && (t >= 4);
    g_mtok[i] = msk ? 4 : t;
    if (labels_out) labels_out[i] = msk ? (float)t : -100.0f;
}

// ---------------- merged prep ----------------
#define SZ_WMSG  (FD*FD)
#define SZ_WNODE (FD*FD)
#define SZ_LC1   (D_GNN*DG)
#define SZ_LC2   (DG*D_GNN)
#define SZ_WO    (DG*DG)
#define SZ_WF1   (DG*4*DG)
#define SZ_WF2   (4*DG*DG)
#define CW_TOTAL (SZ_WMSG+SZ_WNODE+SZ_LC1+SZ_LC2+SZ_WO+SZ_WF1+SZ_WF2)
#define PREP_TOTAL (CW_TOTAL + VOCAB*D_GNN + DG*DG)

__global__ void prep_all_kernel(const float* Wmsg, const float* Wnode,
                                const float* lc1w, const float* lc2w,
                                const float* Wo, const float* Wf1, const float* Wf2,
                                const float* emb, const float* Wq, const float* Wk,
                                const float* Wv) {
    int i = blockIdx.x * blockDim.x + threadIdx.x;
    if (i >= PREP_TOTAL) return;
    int j = i;
    if (j < SZ_WMSG)  { g_wmsg[j]  = __float2bfloat16_rn(Wmsg[j]);  return; } j -= SZ_WMSG;
    if (j < SZ_WNODE) { g_wnode[j] = __float2bfloat16_rn(Wnode[j]); return; } j -= SZ_WNODE;
    if (j < SZ_LC1)   { g_lc1w[j]  = __float2bfloat16_rn(lc1w[j]);  return; } j -= SZ_LC1;
    if (j < SZ_LC2)   { g_lc2w[j]  = __float2bfloat16_rn(lc2w[j]);  return; } j -= SZ_LC2;
    if (j < SZ_WO)    { g_wo[j]    = __float2bfloat16_rn(Wo[j]);    return; } j -= SZ_WO;
    if (j < SZ_WF1)   { g_wf1[j]   = __float2bfloat16_rn(Wf1[j]);   return; } j -= SZ_WF1;
    if (j < SZ_WF2)   { g_wf2[j]   = __float2bfloat16_rn(Wf2[j]);   return; } j -= SZ_WF2;
    if (j < VOCAB*D_GNN) { g_embf[j] = __float2bfloat16_rn(emb[j]); return; } j -= VOCAB*D_GNN;
    int k = j >> 8, n = j & 255;
    g_wqkv[k * 768 + n]       = __float2bfloat16_rn(Wq[j]);
    g_wqkv[k * 768 + 256 + n] = __float2bfloat16_rn(Wk[j]);
    g_wqkv[k * 768 + 512 + n] = __float2bfloat16_rn(Wv[j]);
}

#define N16 (N_NODES * FD / 8)
#define E16 (N_EDGES * FD / 8)
__global__ void embed_all_kernel(const int* __restrict__ ntok) {
    int i = blockIdx.x * blockDim.x + threadIdx.x;
    if (i >= N16 + E16) return;
    const uint4* tab = (const uint4*)g_embf;
    if (i < N16) {
        ((uint4*)g_x)[i] = tab[ntok[i >> 3] * 8 + (i & 7)];
    } else {
        int j = i - N16;
        ((uint4*)g_e)[j] = tab[g_mtok[j >> 3] * 8 + (j & 7)];
    }
}

__global__ void zero_kernel(float4* __restrict__ p, int n4) {
    int i = blockIdx.x * blockDim.x + threadIdx.x;
    if (i < n4) p[i] = make_float4(0.f, 0.f, 0.f, 0.f);
}

__device__ __forceinline__ void unpack8(uint4 raw, float* v) {
    const __nv_bfloat162* h = (const __nv_bfloat162*)&raw;
    #pragma unroll
    for (int j = 0; j < 4; j++) {
        v[2*j]   = __bfloat162float(h[j].x);
        v[2*j+1] = __bfloat162float(h[j].y);
    }
}

__global__ void scatter_add_kernel(const int* __restrict__ dst) {
    int i = blockIdx.x * blockDim.x + threadIdx.x;
    if (i >= N_EDGES * FD / 8) return;
    int e = i >> 6, c8 = (i & 63) * 8;
    uint4 raw = *(const uint4*)(g_msg + ((size_t)e << 9) + c8);
    float v[8]; unpack8(raw, v);
    float* base = g_agg + (size_t)dst[e] * FD + c8;
    #pragma unroll
    for (int j = 0; j < 8; j++) atomicAdd(base + j, v[j]);
}

__global__ void edge_gather_kernel(const int* __restrict__ src, const int* __restrict__ dst) {
    int i = blockIdx.x * blockDim.x + threadIdx.x;
    if (i >= N_EDGES * FD / 8) return;
    int e = i >> 6, c8 = (i & 63) * 8;
    uint4 ra = *(const uint4*)(g_h + (size_t)src[e] * FD + c8);
    uint4 rb = *(const uint4*)(g_h + (size_t)dst[e] * FD + c8);
    float a[8], b[8]; unpack8(ra, a); unpack8(rb, b);
    __nv_bfloat162 o[4];
    #pragma unroll
    for (int j = 0; j < 4; j++) {
        o[j].x = __float2bfloat16_rn(a[2*j]   + b[2*j]);
        o[j].y = __float2bfloat16_rn(a[2*j+1] + b[2*j+1]);
    }
    *(uint4*)(g_eh + ((size_t)e << 9) + c8) = *(uint4*)o;
}

// ================= common helpers =================
__device__ __forceinline__ void cp_async16(uint32_t dst, const void* src, bool pred) {
    int sz = pred ? 16 : 0;
    asm volatile("cp.async.cg.shared.global [%0], [%1], 16, %2;\n"
                 :: "r"(dst), "l"(src), "r"(sz));
}
__device__ __forceinline__ void cp_commit() { asm volatile("cp.async.commit_group;\n"); }
__device__ __forceinline__ void cp_wait0()  { asm volatile("cp.async.wait_group 0;\n"); }
__device__ __forceinline__ void cp_wait1()  { asm volatile("cp.async.wait_group 1;\n"); }

__device__ __forceinline__ void mma_bf16(float c[4], const uint32_t a[4], const uint32_t b[2]) {
    asm volatile(
        "mma.sync.aligned.m16n8k16.row.col.f32.bf16.bf16.f32 "
        "{%0,%1,%2,%3}, {%4,%5,%6,%7}, {%8,%9}, {%0,%1,%2,%3};"
        : "+f"(c[0]), "+f"(c[1]), "+f"(c[2]), "+f"(c[3])
        : "r"(a[0]), "r"(a[1]), "r"(a[2]), "r"(a[3]), "r"(b[0]), "r"(b[1]));
}

__device__ __forceinline__ void ldsm_x4(uint32_t& r0, uint32_t& r1, uint32_t& r2, uint32_t& r3,
                                        uint32_t addr) {
    asm volatile("ldmatrix.sync.aligned.m8n8.x4.shared.b16 {%0,%1,%2,%3}, [%4];"
                 : "=r"(r0), "=r"(r1), "=r"(r2), "=r"(r3) : "r"(addr));
}
__device__ __forceinline__ void ldsm_x4_t(uint32_t& r0, uint32_t& r1, uint32_t& r2, uint32_t& r3,
                                          uint32_t addr) {
    asm volatile("ldmatrix.sync.aligned.m8n8.x4.trans.shared.b16 {%0,%1,%2,%3}, [%4];"
                 : "=r"(r0), "=r"(r1), "=r"(r2), "=r"(r3) : "r"(addr));
}

// ================= mma.sync bf16 GEMM (mid-network) =================
// block 128x128, 4 warps (128 threads), warp tile 64x64, 3-stage cp.async.
// EPI: 0 plain | 1 +biasf[n] | 2 relu(+extraf[m*ld+n]) | 3 relu(+extrab[gidx[m]*ld+n])
//      4 +extrab[m*ld+n] | 5 gelu

#define TBM 128
#define TBN 128
#define TBK 32
#define ASTRH 40
#define BSTRH 136
#define NSTAGE 3
#define A_STAGE_H (TBM * ASTRH)
#define B_STAGE_H (TBK * BSTRH)
#define GEMM_SMEM_BYTES (NSTAGE * (A_STAGE_H + B_STAGE_H) * 2)

template<int EPI>
__global__ void __launch_bounds__(128, 2)
tmma_k(const bf16* __restrict__ A, const bf16* __restrict__ B, void* __restrict__ Cv,
       int M, int N, int K,
       const float* __restrict__ extraf, const bf16* __restrict__ extrab,
       const int* __restrict__ gidx, int ldex) {
    extern __shared__ bf16 smem[];
    bf16* Asm = smem;
    bf16* Bsm = smem + NSTAGE * A_STAGE_H;

    uint32_t aU = (uint32_t)__cvta_generic_to_shared(Asm);
    uint32_t bU = (uint32_t)__cvta_generic_to_shared(Bsm);

    int tid  = threadIdx.x;
    int lane = tid & 31;
    int warp = tid >> 5;        // 0..3
    int wm = warp & 1;          // 64-row group
    int wn = warp >> 1;         // 64-col group
    int g   = lane >> 2;
    int tig = lane & 3;
    int m0 = blockIdx.y * TBM;
    int n0 = blockIdx.x * TBN;

    float acc[4][8][4] = {};

    auto issue_load = [&](int s, int k0) {
        #pragma unroll
        for (int i = 0; i < 4; i++) {
            int id = tid + i * 128;
            int ar = id >> 2, ak = (id & 3) << 3;
            uint32_t da = aU + (s * A_STAGE_H + ar * ASTRH + ak) * 2;
            cp_async16(da, A + (size_t)(m0 + ar) * K + k0 + ak, true);
            int br = id >> 4, bn = (id & 15) << 3;
            int gn = n0 + bn;
            uint32_t db = bU + (s * B_STAGE_H + br * BSTRH + bn) * 2;
            cp_async16(db, B + (size_t)(k0 + br) * N + gn, gn + 8 <= N);
        }
    };

    int niter = K / TBK;
    issue_load(0, 0);
    cp_commit();
    issue_load(1, TBK);
    cp_commit();

    for (int it = 0; it < niter; it++) {
        if (it == niter - 1) cp_wait0(); else cp_wait1();
        __syncthreads();
        if (it + 2 < niter) {
            issue_load((it + 2) % NSTAGE, (it + 2) * TBK);
            cp_commit();
        }
        int s = it % NSTAGE;
        uint32_t aB = aU + s * A_STAGE_H * 2;
        uint32_t bB = bU + s * B_STAGE_H * 2;
        #pragma unroll
        for (int ks = 0; ks < TBK; ks += 16) {
            uint32_t af[4][4], bfr[8][2];
            #pragma unroll
            for (int mt = 0; mt < 4; mt++) {
                int row = wm * 64 + mt * 16 + (lane & 15);
                uint32_t ad = aB + (row * ASTRH + ks + ((lane >> 4) << 3)) * 2;
                ldsm_x4(af[mt][0], af[mt][1], af[mt][2], af[mt][3], ad);
            }
            #pragma unroll
            for (int bp = 0; bp < 4; bp++) {
                int krow = ks + (lane & 15);
                int ncol = wn * 64 + bp * 16 + ((lane >> 4) << 3);
                uint32_t bd = bB + (krow * BSTRH + ncol) * 2;
                ldsm_x4_t(bfr[2*bp][0], bfr[2*bp][1], bfr[2*bp+1][0], bfr[2*bp+1][1], bd);
            }
            #pragma unroll
            for (int mt = 0; mt < 4; mt++)
                #pragma unroll
                for (int nt = 0; nt < 8; nt++)
                    mma_bf16(acc[mt][nt], af[mt], bfr[nt]);
        }
    }

    bf16* Cb = (bf16*)Cv;

    #pragma unroll
    for (int mt = 0; mt < 4; mt++) {
        #pragma unroll
        for (int half = 0; half < 2; half++) {
            int rib = wm * 64 + mt * 16 + half * 8 + g;
            int r = m0 + rib;
            int ebase = 0;
            if (EPI == 2 || EPI == 4) ebase = r * ldex;
            if (EPI == 3)             ebase = gidx[r] * ldex;

            #pragma unroll
            for (int nt = 0; nt < 8; nt++) {
                int n = n0 + wn * 64 + nt * 8 + 2 * tig;
                float c0 = acc[mt][nt][half * 2 + 0];
                float c1 = acc[mt][nt][half * 2 + 1];
                if (EPI == 1) { c0 += extraf[n]; c1 += extraf[n + 1]; }
                else if (EPI == 2) {
                    c0 = fmaxf(c0 + extraf[ebase + n],     0.0f);
                    c1 = fmaxf(c1 + extraf[ebase + n + 1], 0.0f);
                } else if (EPI == 3) {
                    c0 = fmaxf(c0 + __bfloat162float(extrab[ebase + n]),     0.0f);
                    c1 = fmaxf(c1 + __bfloat162float(extrab[ebase + n + 1]), 0.0f);
                } else if (EPI == 4) {
                    c0 += __bfloat162float(extrab[ebase + n]);
                    c1 += __bfloat162float(extrab[ebase + n + 1]);
                } else if (EPI == 5) {
                    float x = c0;
                    c0 = 0.5f * x * (1.0f + tanhf(0.7978845608028654f * (x + 0.044715f * x * x * x)));
                    x = c1;
                    c1 = 0.5f * x * (1.0f + tanhf(0.7978845608028654f * (x + 0.044715f * x * x * x)));
                }
                if (n + 1 < N) {
                    __nv_bfloat162 p;
                    p.x = __float2bfloat16_rn(c0);
                    p.y = __float2bfloat16_rn(c1);
                    *(__nv_bfloat162*)&Cb[(size_t)r * N + n] = p;
                }
            }
        }
    }
}

// ================= fused persistent LM head (lc2 + logits + softmax) =================
#define LMSTR   144
#define LM_AB   (128 * LMSTR)
#define LM_NTILE 79
#define LM_X2_OFF  LM_AB
#define LM_W2_OFF  (LM_AB + 128 * 528)
#define LM_STAT_OFF (4 * LM_AB)
#define LM_SMEM_TOT (LM_W2_OFF + 256 * 144)

__global__ void __launch_bounds__(256, 1)
lm_fused(float* __restrict__ probs, const float* __restrict__ lc2b) {
    extern __shared__ char smc[];
    uint32_t aU = (uint32_t)__cvta_generic_to_shared(smc);
    uint32_t bU = aU + LM_AB;
    float2* spart = (float2*)(smc + LM_STAT_OFF);
    float2* sstat = spart + 128 * 4;

    int tid = threadIdx.x;
    int lane = tid & 31, warp = tid >> 5;
    int wm = warp & 1, wn = warp >> 1;
    int g = lane >> 2, tig = lane & 3;
    int m0 = blockIdx.x * 128;

    // ---- preamble: y = x2 @ lc2w + b -> A region (bf16) ----
    {
        uint32_t xU = aU + LM_X2_OFF;
        uint32_t wU = aU + LM_W2_OFF;
        const char* X2b = (const char*)g_x2;
        #pragma unroll
        for (int i = 0; i < 16; i++) {
            int id = tid + i * 256;
            int row = id >> 5, c = (id & 31) << 4;
            cp_async16(xU + row * 528 + c, X2b + (size_t)(m0 + row) * 512 + c, true);
        }
        const char* W2b = (const char*)g_lc2w;
        #pragma unroll
        for (int i = 0; i < 8; i++) {
            int id = tid + i * 256;
            int row = id >> 3, c = (id & 7) << 4;
            cp_async16(wU + row * 144 + c, W2b + (size_t)row * 128 + c, true);
        }
        cp_commit(); cp_wait0();
        __syncthreads();

        float yacc[8][4] = {};
        #pragma unroll
        for (int ks = 0; ks < 16; ks++) {
            uint32_t axf[4];
            uint32_t ad = xU + (warp * 16 + (lane & 15)) * 528
                        + (ks * 16 + ((lane >> 4) << 3)) * 2;
            ldsm_x4(axf[0], axf[1], axf[2], axf[3], ad);
            uint32_t bw[8][2];
            #pragma unroll
            for (int p = 0; p < 4; p++) {
                uint32_t bd = wU + (ks * 16 + (lane & 15)) * 144
                            + (p * 16 + ((lane >> 4) << 3)) * 2;
                ldsm_x4_t(bw[2*p][0], bw[2*p][1], bw[2*p+1][0], bw[2*p+1][1], bd);
            }
            #pragma unroll
            for (int nt = 0; nt < 8; nt++)
                mma_bf16(yacc[nt], axf, bw[nt]);
        }
        __syncthreads();

        #pragma unroll
        for (int half = 0; half < 2; half++) {
            int rib = warp * 16 + half * 8 + g;
            #pragma unroll
            for (int nt = 0; nt < 8; nt++) {
                int col = nt * 8 + 2 * tig;
                float v0 = yacc[nt][half * 2 + 0] + lc2b[col];
                float v1 = yacc[nt][half * 2 + 1] + lc2b[col + 1];
                __nv_bfloat162 p;
                p.x = __float2bfloat16_rn(v0);
                p.y = __float2bfloat16_rn(v1);
                *(__nv_bfloat162*)(smc + rib * LMSTR + col * 2) = p;
            }
        }
        __syncthreads();
    }

    auto issue_B = [&](int stage, int t) {
        const char* Bb = (const char*)g_embf;
        #pragma unroll
        for (int i = 0; i < 4; i++) {
            int id = tid + i * 256;
            int row = id >> 3, c = (id & 7) << 4;
            int v = t * 128 + row;
            cp_async16(bU + stage * LM_AB + row * LMSTR + c,
                       Bb + (size_t)v * 128 + c, v < VOCAB);
        }
        cp_commit();
    };

    issue_B(0, 0);
    issue_B(1, 1);

    uint32_t af[4][4][4];
    #pragma unroll
    for (int mt = 0; mt < 4; mt++)
        #pragma unroll
        for (int ks = 0; ks < 4; ks++) {
            uint32_t ad = aU + (wm * 64 + mt * 16 + (lane & 15)) * LMSTR
                        + ks * 32 + ((lane >> 4) << 4);
            ldsm_x4(af[mt][ks][0], af[mt][ks][1], af[mt][ks][2], af[mt][ks][3], ad);
        }

    float rm[8], rs[8];
    #pragma unroll
    for (int s = 0; s < 8; s++) { rm[s] = -1e30f; rs[s] = 0.0f; }

    int brow = (lane & 7) + ((lane >> 4) << 3);
    int bcol16 = ((lane >> 3) & 1) << 4;

    // ======== PASS 1: stats ========
    for (int t = 0; t < LM_NTILE; t++) {
        if (t == LM_NTILE - 1) cp_wait0(); else cp_wait1();
        __syncthreads();
        if (t + 2 < LM_NTILE) issue_B((t + 2) % 3, t + 2);

        uint32_t bB = bU + (t % 3) * LM_AB;
        float acc[4][4][4] = {};
        #pragma unroll
        for (int ks = 0; ks < 4; ks++) {
            uint32_t bfr[4][2];
            #pragma unroll
            for (int p = 0; p < 2; p++) {
                uint32_t bd = bB + (wn * 32 + p * 16 + brow) * LMSTR + ks * 32 + bcol16;
                ldsm_x4(bfr[2*p][0], bfr[2*p][1], bfr[2*p+1][0], bfr[2*p+1][1], bd);
            }
            #pragma unroll
            for (int mt = 0; mt < 4; mt++)
                #pragma unroll
                for (int nt = 0; nt < 4; nt++)
                    mma_bf16(acc[mt][nt], af[mt][ks], bfr[nt]);
        }

        int nb0 = t * 128 + wn * 32 + 2 * tig;
        #pragma unroll
        for (int mt = 0; mt < 4; mt++)
            #pragma unroll
            for (int half = 0; half < 2; half++) {
                int slot = mt * 2 + half;
                float v[8];
                float bm = -1e30f;
                #pragma unroll
                for (int nt = 0; nt < 4; nt++)
                    #pragma unroll
                    for (int j = 0; j < 2; j++) {
                        int n = nb0 + nt * 8 + j;
                        float x = (n < VOCAB) ? acc[mt][nt][half * 2 + j] : -1e30f;
                        v[nt * 2 + j] = x;
                        bm = fmaxf(bm, x);
                    }
                float nm = fmaxf(rm[slot], bm);
                float add = 0.0f;
                #pragma unroll
                for (int j = 0; j < 8; j++) add += __expf(v[j] - nm);
                rs[slot] = rs[slot] * __expf(rm[slot] - nm) + add;
                rm[slot] = nm;
            }
    }

    // ---- reduce stats ----
    #pragma unroll
    for (int slot = 0; slot < 8; slot++) {
        float m = rm[slot], s = rs[slot];
        #pragma unroll
        for (int off = 1; off <= 2; off <<= 1) {
            float om = __shfl_xor_sync(0xffffffffu, m, off);
            float os = __shfl_xor_sync(0xffffffffu, s, off);
            float nm = fmaxf(m, om);
            s = s * __expf(m - nm) + os * __expf(om - nm);
            m = nm;
        }
        int mt = slot >> 1, half = slot & 1;
        int rib = wm * 64 + mt * 16 + half * 8 + g;
        if (tig == 0) spart[rib * 4 + wn] = make_float2(m, s);
    }
    __syncthreads();
    if (tid < 128) {
        float m = -1e30f, s = 0.0f;
        #pragma unroll
        for (int w = 0; w < 4; w++) {
            float2 p = spart[tid * 4 + w];
            float nm = fmaxf(m, p.x);
            s = s * __expf(m - nm) + p.y * __expf(p.x - nm);
            m = nm;
        }
        sstat[tid] = make_float2(m, 1.0f / s);
    }
    __syncthreads();

    float stm[8], sti[8];
    #pragma unroll
    for (int slot = 0; slot < 8; slot++) {
        int mt = slot >> 1, half = slot & 1;
        int rib = wm * 64 + mt * 16 + half * 8 + g;
        float2 st = sstat[rib];
        stm[slot] = st.x; sti[slot] = st.y;
    }

    // ======== PASS 2: recompute + write probs ========
    issue_B(0, 0);
    issue_B(1, 1);
    for (int t = 0; t < LM_NTILE; t++) {
        if (t == LM_NTILE - 1) cp_wait0(); else cp_wait1();
        __syncthreads();
        if (t + 2 < LM_NTILE) issue_B((t + 2) % 3, t + 2);

        uint32_t bB = bU + (t % 3) * LM_AB;
        float acc[4][4][4] = {};
        #pragma unroll
        for (int ks = 0; ks < 4; ks++) {
            uint32_t bfr[4][2];
            #pragma unroll
            for (int p = 0; p < 2; p++) {
                uint32_t bd = bB + (wn * 32 + p * 16 + brow) * LMSTR + ks * 32 + bcol16;
                ldsm_x4(bfr[2*p][0], bfr[2*p][1], bfr[2*p+1][0], bfr[2*p+1][1], bd);
            }
            #pragma unroll
            for (int mt = 0; mt < 4; mt++)
                #pragma unroll
                for (int nt = 0; nt < 4; nt++)
                    mma_bf16(acc[mt][nt], af[mt][ks], bfr[nt]);
        }

        int nb0 = t * 128 + wn * 32 + 2 * tig;
        #pragma unroll
        for (int mt = 0; mt < 4; mt++)
            #pragma unroll
            for (int half = 0; half < 2; half++) {
                int slot = mt * 2 + half;
                int rib = wm * 64 + mt * 16 + half * 8 + g;
                size_t rowoff = (size_t)(m0 + rib) * VOCAB;
                float m = stm[slot], inv = sti[slot];
                #pragma unroll
                for (int nt = 0; nt < 4; nt++) {
                    int n = nb0 + nt * 8;
                    if (n < VOCAB) {
                        float p0 = __expf(acc[mt][nt][half * 2 + 0] - m) * inv;
                        float p1 = __expf(acc[mt][nt][half * 2 + 1] - m) * inv;
                        __stcs((float2*)&probs[rowoff + n], make_float2(p0, p1));
                    }
                }
            }
    }
}

// ---------------- attention ----------------
__global__ void __launch_bounds__(256) attention_kernel() {
    __shared__ float qs[8][DG], ks[8][DG], vs[8][DG];
    int b = blockIdx.x;
    int tid = threadIdx.x;
    for (int i = tid; i < 8 * DG; i += 256) {
        int s = i >> 8, c = i & 255;
        size_t off = (size_t)(b * 8 + s) * 768 + c;
        qs[s][c] = __bfloat162float(g_qkv[off]);
        ks[s][c] = __bfloat162float(g_qkv[off + 256]);
        vs[s][c] = __bfloat162float(g_qkv[off + 512]);
    }
    __syncthreads();

    int h  = tid >> 6;
    int qx = (tid >> 3) & 7;
    int kx = tid & 7;
    float att = 0.0f;
    #pragma unroll
    for (int d = 0; d < HD; d++)
        att += qs[qx][h * HD + d] * ks[kx][h * HD + d];
    att *= 0.125f;

    float mx = att;
    mx = fmaxf(mx, __shfl_xor_sync(0xffffffffu, mx, 4));
    mx = fmaxf(mx, __shfl_xor_sync(0xffffffffu, mx, 2));
    mx = fmaxf(mx, __shfl_xor_sync(0xffffffffu, mx, 1));
    float ex = expf(att - mx);
    float sm = ex;
    sm += __shfl_xor_sync(0xffffffffu, sm, 4);
    sm += __shfl_xor_sync(0xffffffffu, sm, 2);
    sm += __shfl_xor_sync(0xffffffffu, sm, 1);
    float a = ex / sm;

    int lane = tid & 31;
    int base = lane & ~7;
    float a_all[8];
    #pragma unroll
    for (int kk = 0; kk < 8; kk++)
        a_all[kk] = __shfl_sync(0xffffffffu, a, base + kk);

    #pragma unroll
    for (int t2 = 0; t2 < 8; t2++) {
        int d = kx * 8 + t2;
        float o = 0.0f;
        #pragma unroll
        for (int kk = 0; kk < 8; kk++)
            o += a_all[kk] * vs[kk][h * HD + d];
        g_ao[(size_t)(b * 8 + qx) * DG + h * HD + d] = __float2bfloat16_rn(o);
    }
}

// ---------------- host launcher ----------------
template<int EPI>
static void launch_one(const bf16* A, const bf16* B, void* C, int M, int N, int K,
                       const float* extraf, const bf16* extrab,
                       const int* gidx, int ldex) {
    static bool attr_done = false;
    if (!attr_done) {
        cudaFuncSetAttribute(tmma_k<EPI>, cudaFuncAttributeMaxDynamicSharedMemorySize,
                             GEMM_SMEM_BYTES);
        attr_done = true;
    }
    dim3 grid((N + TBN - 1) / TBN, M / TBM), blk(128);
    tmma_k<EPI><<<grid, blk, GEMM_SMEM_BYTES>>>(A, B, C, M, N, K, extraf, extrab, gidx, ldex);
}

static void launch_gemm(int epi, const bf16* A, const bf16* B, void* C,
                        int M, int N, int K,
                        const float* extraf = nullptr, const bf16* extrab = nullptr,
                        const int* gidx = nullptr, int ldex = 0) {
    switch (epi) {
        case 0: launch_one<0>(A, B, C, M, N, K, extraf, extrab, gidx, ldex); break;
        case 1: launch_one<1>(A, B, C, M, N, K, extraf, extrab, gidx, ldex); break;
        case 2: launch_one<2>(A, B, C, M, N, K, extraf, extrab, gidx, ldex); break;
        case 3: launch_one<3>(A, B, C, M, N, K, extraf, extrab, gidx, ldex); break;
        case 4: launch_one<4>(A, B, C, M, N, K, extraf, extrab, gidx, ldex); break;
        case 5: launch_one<5>(A, B, C, M, N, K, extraf, extrab, gidx, ldex); break;
    }
}

template <typename T>
static T* sym_addr(const void* sym) {
    void* p = nullptr;
    cudaGetSymbolAddress(&p, sym);
    return (T*)p;
}

extern "C" void kernel_launch(void* const* d_in, const int* in_sizes, int n_in,
                              void* d_out, int out_size) {
    const int*   node_tokens = (const int*)d_in[0];
    const int*   edge_tokens = (const int*)d_in[1];
    const int*   edge_index  = (const int*)d_in[2];
    const void*  mask_rows   = d_in[3];
    const float* emb    = (const float*)d_in[4];
    const float* W_msg  = (const float*)d_in[5];
    const float* W_node = (const float*)d_in[6];
    const float* lc1_w  = (const float*)d_in[7];
    const float* lc1_b  = (const float*)d_in[8];
    const float* lc2_w  = (const float*)d_in[9];
    const float* lc2_b  = (const float*)d_in[10];
    const float* Wq  = (const float*)d_in[11];
    const float* Wk  = (const float*)d_in[12];
    const float* Wv  = (const float*)d_in[13];
    const float* Wo  = (const float*)d_in[14];
    const float* Wf1 = (const float*)d_in[15];
    const float* Wf2 = (const float*)d_in[16];

    float* out = (float*)d_out;
    bool concat = (out_size != ROWS * VOCAB);
    float* labels_out = concat ? out : nullptr;
    float* probs      = concat ? out + ROWS : out;

    const int* src = edge_index;
    const int* dst = edge_index + N_EDGES;

    bf16* px   = sym_addr<bf16>(g_x);
    bf16* pe   = sym_addr<bf16>(g_e);
    bf16* pmsg = sym_addr<bf16>(g_msg);
    float* pagg= sym_addr<float>(g_agg);
    bf16* ph   = sym_addr<bf16>(g_h);
    bf16* peh  = sym_addr<bf16>(g_eh);
    bf16* pzg  = sym_addr<bf16>(g_zg);
    bf16* pqkv = sym_addr<bf16>(g_qkv);
    bf16* pao  = sym_addr<bf16>(g_ao);
    bf16* px1  = sym_addr<bf16>(g_x1);
    bf16* pffn = sym_addr<bf16>(g_ffn);
    bf16* px2  = sym_addr<bf16>(g_x2);
    bf16* pwmsg = sym_addr<bf16>(g_wmsg);
    bf16* pwnode= sym_addr<bf16>(g_wnode);
    bf16* plc1w = sym_addr<bf16>(g_lc1w);
    bf16* pwo   = sym_addr<bf16>(g_wo);
    bf16* pwf1  = sym_addr<bf16>(g_wf1);
    bf16* pwf2  = sym_addr<bf16>(g_wf2);
    bf16* pwqkv = sym_addr<bf16>(g_wqkv);

    // 1. mask dtype detect + labels/masked tokens
    detect_mask_kernel<<<1, 512>>>((const int*)mask_rows);
    mask_kernel<<<(N_EDGES * L_TOK + 255) / 256, 256>>>(edge_tokens, mask_rows, labels_out);

    // 2. merged prep + embeddings
    prep_all_kernel<<<(PREP_TOTAL + 255) / 256, 256>>>(W_msg, W_node, lc1_w, lc2_w,
                                                       Wo, Wf1, Wf2, emb, Wq, Wk, Wv);
    embed_all_kernel<<<(N16 + E16 + 255) / 256, 256>>>(node_tokens);

    // 3. GNN
    launch_gemm(3, pe, pwmsg, pmsg, N_EDGES, FD, FD, nullptr, px, src, FD);
    zero_kernel<<<(N_NODES * FD / 4 + 255) / 256, 256>>>((float4*)pagg, N_NODES * FD / 4);
    scatter_add_kernel<<<(N_EDGES * FD / 8 + 255) / 256, 256>>>(dst);
    launch_gemm(2, px, pwnode, ph, N_NODES, FD, FD, pagg, nullptr, nullptr, FD);
    edge_gather_kernel<<<(N_EDGES * FD / 8 + 255) / 256, 256>>>(src, dst);

    // 4. lc1
    launch_gemm(1, peh, plc1w, pzg, ROWS, DG, D_GNN, lc1_b);

    // 5. transformer
    launch_gemm(0, pzg, pwqkv, pqkv, ROWS, 3 * DG, DG);
    attention_kernel<<<N_EDGES, 256>>>();
    launch_gemm(4, pao, pwo, px1, ROWS, DG, DG, nullptr, pzg, nullptr, DG);
    launch_gemm(5, px1, pwf1, pffn, ROWS, 4 * DG, DG);
    launch_gemm(4, pffn, pwf2, px2, ROWS, DG, 4 * DG, nullptr, px1, nullptr, DG);

    // 6. fused LM head
    {
        static bool lm_attr = false;
        if (!lm_attr) {
            cudaFuncSetAttribute(lm_fused, cudaFuncAttributeMaxDynamicSharedMemorySize,
                                 LM_SMEM_TOT);
            lm_attr = true;
        }
        lm_fused<<<ROWS / 128, 256, LM_SMEM_TOT>>>(probs, lc2_b);
    }
}

// round 12
// speedup vs baseline: 1.0713x; 1.0713x over previous
#include <cuda_runtime.h>
#include <cuda_bf16.h>
#include <math.h>
#include <stdint.h>

// ---------------- problem constants ----------------
#define VOCAB   10000
#define D_GNN   64
#define L_TOK   8
#define DG      256
#define NH      4
#define HD      64
#define N_NODES 8192
#define N_EDGES 2048
#define FD      512
#define ROWS    16384

typedef __nv_bfloat16 bf16;

// ---------------- scratch (static device memory) ----------------
__device__ bf16  g_x   [N_NODES * FD];
__device__ bf16  g_e   [N_EDGES * FD];
__device__ bf16  g_msg [N_EDGES * FD];
__device__ float g_agg [N_NODES * FD];
__device__ bf16  g_h   [N_NODES * FD];
__device__ bf16  g_eh  [N_EDGES * FD];
__device__ bf16  g_zg  [ROWS * DG];
__device__ bf16  g_qkv [ROWS * 3 * DG];
__device__ bf16  g_ao  [ROWS * DG];
__device__ bf16  g_x1  [ROWS * DG];
__device__ bf16  g_ffn [ROWS * 4 * DG];
__device__ bf16  g_x2  [ROWS * DG];
__device__ bf16  g_wmsg [FD * FD];
__device__ bf16  g_wnode[FD * FD];
__device__ bf16  g_lc1w [D_GNN * DG];
__device__ bf16  g_lc2w [DG * D_GNN];
__device__ bf16  g_wo   [DG * DG];
__device__ bf16  g_wf1  [DG * 4 * DG];
__device__ bf16  g_wf2  [4 * DG * DG];
__device__ bf16  g_wqkv [DG * 3 * DG];
__device__ bf16  g_embf [VOCAB * D_GNN];
__device__ int   g_mtok[N_EDGES * L_TOK];
__device__ int   g_mask_mode;

// ---------------- mask dtype detection ----------------
__global__ void detect_mask_kernel(const int* __restrict__ mr) {
    __shared__ int notint, notflt;
    if (threadIdx.x == 0) { notint = 0; notflt = 0; }
    __syncthreads();
    int w = mr[threadIdx.x];
    if (w != 0 && w != 1)          atomicExch(&notint, 1);
    if (w != 0 && w != 0x3F800000) atomicExch(&notflt, 1);
    __syncthreads();
    if (threadIdx.x == 0)
        g_mask_mode = notint ? (notflt ? 2 : 1) : 0;
}

__global__ void mask_kernel(const int* __restrict__ etok, const void* __restrict__ maskraw,
                            float* labels_out) {
    int i = blockIdx.x * blockDim.x + threadIdx.x;
    if (i >= N_EDGES * L_TOK) return;
    int e = i >> 3;
    int t = etok[i];
    bool mr;
    int mode = g_mask_mode;
    if (mode == 0)      mr = ((const int*)maskraw)[e] != 0;
    else if (mode == 1) mr = ((const float*)maskraw)[e] != 0.0f;
    else                mr = ((const unsigned char*)maskraw)[e] != 0;
    bool msk = mr && (t >= 4);
    g_mtok[i] = msk ? 4 : t;
    if (labels_out) labels_out[i] = msk ? (float)t : -100.0f;
}

// ---------------- merged prep ----------------
#define SZ_WMSG  (FD*FD)
#define SZ_WNODE (FD*FD)
#define SZ_LC1   (D_GNN*DG)
#define SZ_LC2   (DG*D_GNN)
#define SZ_WO    (DG*DG)
#define SZ_WF1   (DG*4*DG)
#define SZ_WF2   (4*DG*DG)
#define CW_TOTAL (SZ_WMSG+SZ_WNODE+SZ_LC1+SZ_LC2+SZ_WO+SZ_WF1+SZ_WF2)
#define PREP_TOTAL (CW_TOTAL + VOCAB*D_GNN + DG*DG)

__global__ void prep_all_kernel(const float* Wmsg, const float* Wnode,
                                const float* lc1w, const float* lc2w,
                                const float* Wo, const float* Wf1, const float* Wf2,
                                const float* emb, const float* Wq, const float* Wk,
                                const float* Wv) {
    int i = blockIdx.x * blockDim.x + threadIdx.x;
    if (i >= PREP_TOTAL) return;
    int j = i;
    if (j < SZ_WMSG)  { g_wmsg[j]  = __float2bfloat16_rn(Wmsg[j]);  return; } j -= SZ_WMSG;
    if (j < SZ_WNODE) { g_wnode[j] = __float2bfloat16_rn(Wnode[j]); return; } j -= SZ_WNODE;
    if (j < SZ_LC1)   { g_lc1w[j]  = __float2bfloat16_rn(lc1w[j]);  return; } j -= SZ_LC1;
    if (j < SZ_LC2)   { g_lc2w[j]  = __float2bfloat16_rn(lc2w[j]);  return; } j -= SZ_LC2;
    if (j < SZ_WO)    { g_wo[j]    = __float2bfloat16_rn(Wo[j]);    return; } j -= SZ_WO;
    if (j < SZ_WF1)   { g_wf1[j]   = __float2bfloat16_rn(Wf1[j]);   return; } j -= SZ_WF1;
    if (j < SZ_WF2)   { g_wf2[j]   = __float2bfloat16_rn(Wf2[j]);   return; } j -= SZ_WF2;
    if (j < VOCAB*D_GNN) { g_embf[j] = __float2bfloat16_rn(emb[j]); return; } j -= VOCAB*D_GNN;
    int k = j >> 8, n = j & 255;
    g_wqkv[k * 768 + n]       = __float2bfloat16_rn(Wq[j]);
    g_wqkv[k * 768 + 256 + n] = __float2bfloat16_rn(Wk[j]);
    g_wqkv[k * 768 + 512 + n] = __float2bfloat16_rn(Wv[j]);
}

#define N16 (N_NODES * FD / 8)
#define E16 (N_EDGES * FD / 8)
__global__ void embed_all_kernel(const int* __restrict__ ntok) {
    int i = blockIdx.x * blockDim.x + threadIdx.x;
    if (i >= N16 + E16) return;
    const uint4* tab = (const uint4*)g_embf;
    if (i < N16) {
        ((uint4*)g_x)[i] = tab[ntok[i >> 3] * 8 + (i & 7)];
    } else {
        int j = i - N16;
        ((uint4*)g_e)[j] = tab[g_mtok[j >> 3] * 8 + (j & 7)];
    }
}

__global__ void zero_kernel(float4* __restrict__ p, int n4) {
    int i = blockIdx.x * blockDim.x + threadIdx.x;
    if (i < n4) p[i] = make_float4(0.f, 0.f, 0.f, 0.f);
}

__device__ __forceinline__ void unpack8(uint4 raw, float* v) {
    const __nv_bfloat162* h = (const __nv_bfloat162*)&raw;
    #pragma unroll
    for (int j = 0; j < 4; j++) {
        v[2*j]   = __bfloat162float(h[j].x);
        v[2*j+1] = __bfloat162float(h[j].y);
    }
}

__global__ void scatter_add_kernel(const int* __restrict__ dst) {
    int i = blockIdx.x * blockDim.x + threadIdx.x;
    if (i >= N_EDGES * FD / 8) return;
    int e = i >> 6, c8 = (i & 63) * 8;
    uint4 raw = *(const uint4*)(g_msg + ((size_t)e << 9) + c8);
    float v[8]; unpack8(raw, v);
    float* base = g_agg + (size_t)dst[e] * FD + c8;
    #pragma unroll
    for (int j = 0; j < 8; j++) atomicAdd(base + j, v[j]);
}

__global__ void edge_gather_kernel(const int* __restrict__ src, const int* __restrict__ dst) {
    int i = blockIdx.x * blockDim.x + threadIdx.x;
    if (i >= N_EDGES * FD / 8) return;
    int e = i >> 6, c8 = (i & 63) * 8;
    uint4 ra = *(const uint4*)(g_h + (size_t)src[e] * FD + c8);
    uint4 rb = *(const uint4*)(g_h + (size_t)dst[e] * FD + c8);
    float a[8], b[8]; unpack8(ra, a); unpack8(rb, b);
    __nv_bfloat162 o[4];
    #pragma unroll
    for (int j = 0; j < 4; j++) {
        o[j].x = __float2bfloat16_rn(a[2*j]   + b[2*j]);
        o[j].y = __float2bfloat16_rn(a[2*j+1] + b[2*j+1]);
    }
    *(uint4*)(g_eh + ((size_t)e << 9) + c8) = *(uint4*)o;
}

// ================= common helpers =================
__device__ __forceinline__ void cp_async16(uint32_t dst, const void* src, bool pred) {
    int sz = pred ? 16 : 0;
    asm volatile("cp.async.cg.shared.global [%0], [%1], 16, %2;\n"
                 :: "r"(dst), "l"(src), "r"(sz));
}
__device__ __forceinline__ void cp_commit() { asm volatile("cp.async.commit_group;\n"); }
__device__ __forceinline__ void cp_wait0()  { asm volatile("cp.async.wait_group 0;\n"); }
__device__ __forceinline__ void cp_wait1()  { asm volatile("cp.async.wait_group 1;\n"); }

__device__ __forceinline__ void mma_bf16(float c[4], const uint32_t a[4], const uint32_t b[2]) {
    asm volatile(
        "mma.sync.aligned.m16n8k16.row.col.f32.bf16.bf16.f32 "
        "{%0,%1,%2,%3}, {%4,%5,%6,%7}, {%8,%9}, {%0,%1,%2,%3};"
        : "+f"(c[0]), "+f"(c[1]), "+f"(c[2]), "+f"(c[3])
        : "r"(a[0]), "r"(a[1]), "r"(a[2]), "r"(a[3]), "r"(b[0]), "r"(b[1]));
}

__device__ __forceinline__ void ldsm_x4(uint32_t& r0, uint32_t& r1, uint32_t& r2, uint32_t& r3,
                                        uint32_t addr) {
    asm volatile("ldmatrix.sync.aligned.m8n8.x4.shared.b16 {%0,%1,%2,%3}, [%4];"
                 : "=r"(r0), "=r"(r1), "=r"(r2), "=r"(r3) : "r"(addr));
}
__device__ __forceinline__ void ldsm_x4_t(uint32_t& r0, uint32_t& r1, uint32_t& r2, uint32_t& r3,
                                          uint32_t addr) {
    asm volatile("ldmatrix.sync.aligned.m8n8.x4.trans.shared.b16 {%0,%1,%2,%3}, [%4];"
                 : "=r"(r0), "=r"(r1), "=r"(r2), "=r"(r3) : "r"(addr));
}

// ================= mma.sync bf16 GEMM (mid-network; R10 proven config) =================
// EPI: 0 plain | 1 +biasf[n] | 2 relu(+extraf[m*ld+n]) | 3 relu(+extrab[gidx[m]*ld+n])
//      4 +extrab[m*ld+n] | 5 gelu

#define TBM 128
#define TBN 128
#define TBK 32
#define ASTRH 40
#define BSTRH 136
#define NSTAGE 3
#define A_STAGE_H (TBM * ASTRH)
#define B_STAGE_H (TBK * BSTRH)
#define GEMM_SMEM_BYTES (NSTAGE * (A_STAGE_H + B_STAGE_H) * 2)

template<int EPI>
__global__ void __launch_bounds__(256)
tmma_k(const bf16* __restrict__ A, const bf16* __restrict__ B, void* __restrict__ Cv,
       int M, int N, int K,
       const float* __restrict__ extraf, const bf16* __restrict__ extrab,
       const int* __restrict__ gidx, int ldex) {
    extern __shared__ bf16 smem[];
    bf16* Asm = smem;
    bf16* Bsm = smem + NSTAGE * A_STAGE_H;

    uint32_t aU = (uint32_t)__cvta_generic_to_shared(Asm);
    uint32_t bU = (uint32_t)__cvta_generic_to_shared(Bsm);

    int tid  = threadIdx.x;
    int lane = tid & 31;
    int warp = tid >> 5;
    int wm = warp & 1;
    int wn = warp >> 1;
    int g   = lane >> 2;
    int tig = lane & 3;
    int m0 = blockIdx.y * TBM;
    int n0 = blockIdx.x * TBN;

    float acc[4][4][4] = {};

    auto issue_load = [&](int s, int k0) {
        #pragma unroll
        for (int i = 0; i < 2; i++) {
            int id = tid + i * 256;
            int ar = id >> 2, ak = (id & 3) << 3;
            uint32_t da = aU + (s * A_STAGE_H + ar * ASTRH + ak) * 2;
            cp_async16(da, A + (size_t)(m0 + ar) * K + k0 + ak, true);
            int br = id >> 4, bn = (id & 15) << 3;
            int gn = n0 + bn;
            uint32_t db = bU + (s * B_STAGE_H + br * BSTRH + bn) * 2;
            cp_async16(db, B + (size_t)(k0 + br) * N + gn, gn + 8 <= N);
        }
    };

    int niter = K / TBK;
    issue_load(0, 0);
    cp_commit();
    issue_load(1, TBK);
    cp_commit();

    for (int it = 0; it < niter; it++) {
        if (it == niter - 1) cp_wait0(); else cp_wait1();
        __syncthreads();
        if (it + 2 < niter) {
            issue_load((it + 2) % NSTAGE, (it + 2) * TBK);
            cp_commit();
        }
        int s = it % NSTAGE;
        uint32_t aB = aU + s * A_STAGE_H * 2;
        uint32_t bB = bU + s * B_STAGE_H * 2;
        #pragma unroll
        for (int ks = 0; ks < TBK; ks += 16) {
            uint32_t af[4][4], bfr[4][2];
            #pragma unroll
            for (int mt = 0; mt < 4; mt++) {
                int row = wm * 64 + mt * 16 + (lane & 15);
                uint32_t ad = aB + (row * ASTRH + ks + ((lane >> 4) << 3)) * 2;
                ldsm_x4(af[mt][0], af[mt][1], af[mt][2], af[mt][3], ad);
            }
            #pragma unroll
            for (int bp = 0; bp < 2; bp++) {
                int krow = ks + (lane & 15);
                int ncol = wn * 32 + bp * 16 + ((lane >> 4) << 3);
                uint32_t bd = bB + (krow * BSTRH + ncol) * 2;
                ldsm_x4_t(bfr[2*bp][0], bfr[2*bp][1], bfr[2*bp+1][0], bfr[2*bp+1][1], bd);
            }
            #pragma unroll
            for (int mt = 0; mt < 4; mt++)
                #pragma unroll
                for (int nt = 0; nt < 4; nt++)
                    mma_bf16(acc[mt][nt], af[mt], bfr[nt]);
        }
    }

    bf16* Cb = (bf16*)Cv;

    #pragma unroll
    for (int mt = 0; mt < 4; mt++) {
        #pragma unroll
        for (int half = 0; half < 2; half++) {
            int rib = wm * 64 + mt * 16 + half * 8 + g;
            int r = m0 + rib;
            int ebase = 0;
            if (EPI == 2 || EPI == 4) ebase = r * ldex;
            if (EPI == 3)             ebase = gidx[r] * ldex;

            #pragma unroll
            for (int nt = 0; nt < 4; nt++) {
                int n = n0 + wn * 32 + nt * 8 + 2 * tig;
                float c0 = acc[mt][nt][half * 2 + 0];
                float c1 = acc[mt][nt][half * 2 + 1];
                if (EPI == 1) { c0 += extraf[n]; c1 += extraf[n + 1]; }
                else if (EPI == 2) {
                    c0 = fmaxf(c0 + extraf[ebase + n],     0.0f);
                    c1 = fmaxf(c1 + extraf[ebase + n + 1], 0.0f);
                } else if (EPI == 3) {
                    c0 = fmaxf(c0 + __bfloat162float(extrab[ebase + n]),     0.0f);
                    c1 = fmaxf(c1 + __bfloat162float(extrab[ebase + n + 1]), 0.0f);
                } else if (EPI == 4) {
                    c0 += __bfloat162float(extrab[ebase + n]);
                    c1 += __bfloat162float(extrab[ebase + n + 1]);
                } else if (EPI == 5) {
                    float x = c0;
                    c0 = 0.5f * x * (1.0f + tanhf(0.7978845608028654f * (x + 0.044715f * x * x * x)));
                    x = c1;
                    c1 = 0.5f * x * (1.0f + tanhf(0.7978845608028654f * (x + 0.044715f * x * x * x)));
                }
                if (n + 1 < N) {
                    __nv_bfloat162 p;
                    p.x = __float2bfloat16_rn(c0);
                    p.y = __float2bfloat16_rn(c1);
                    *(__nv_bfloat162*)&Cb[(size_t)r * N + n] = p;
                }
            }
        }
    }
}

// ================= fused persistent LM head, M=64 rows/CTA (grid 256, 2 CTA/SM) =================
#define LMSTR    144
#define LM_A_B   (64 * LMSTR)                  // 9216  (A/y region)
#define LM_BSTG  (128 * LMSTR)                 // 18432 (one B stage)
#define LM_B_OFF LM_A_B
#define LM_NTILE 79
#define LM_X2_OFF  LM_A_B                      // preamble x2 (overlaps B; preamble-only)
#define LM_W2_OFF  (LM_A_B + 64 * 528)         // 43008
#define LM_STAT_OFF (LM_W2_OFF + 256 * 144)    // 79872
#define LM_SMEM_TOT (LM_STAT_OFF + 64 * 4 * 8 + 64 * 8)   // 82432

__global__ void __launch_bounds__(256, 2)
lm_fused(float* __restrict__ probs, const float* __restrict__ lc2b) {
    extern __shared__ char smc[];
    uint32_t aU = (uint32_t)__cvta_generic_to_shared(smc);
    uint32_t bU = aU + LM_B_OFF;
    float2* spart = (float2*)(smc + LM_STAT_OFF);    // [64][4]
    float2* sstat = spart + 64 * 4;                  // [64]

    int tid = threadIdx.x;
    int lane = tid & 31, warp = tid >> 5;
    int wm = warp & 1, wn = warp >> 1;
    int g = lane >> 2, tig = lane & 3;
    int m0 = blockIdx.x * 64;

    // ---- preamble: y[64,64] = x2[64,256] @ lc2w + b -> A region ----
    {
        uint32_t xU = aU + LM_X2_OFF;
        uint32_t wU = aU + LM_W2_OFF;
        const char* X2b = (const char*)g_x2;
        #pragma unroll
        for (int i = 0; i < 8; i++) {
            int id = tid + i * 256;
            int row = id >> 5, c = (id & 31) << 4;
            cp_async16(xU + row * 528 + c, X2b + (size_t)(m0 + row) * 512 + c, true);
        }
        const char* W2b = (const char*)g_lc2w;
        #pragma unroll
        for (int i = 0; i < 8; i++) {
            int id = tid + i * 256;
            int row = id >> 3, c = (id & 7) << 4;
            cp_async16(wU + row * 144 + c, W2b + (size_t)row * 128 + c, true);
        }
        cp_commit(); cp_wait0();
        __syncthreads();

        int pw_r = warp & 3;      // 16-row group
        int pw_c = warp >> 2;     // 32-col group
        float yacc[4][4] = {};
        #pragma unroll
        for (int ks = 0; ks < 16; ks++) {
            uint32_t axf[4];
            uint32_t ad = xU + (pw_r * 16 + (lane & 15)) * 528
                        + (ks * 16 + ((lane >> 4) << 3)) * 2;
            ldsm_x4(axf[0], axf[1], axf[2], axf[3], ad);
            uint32_t bw[4][2];
            #pragma unroll
            for (int p = 0; p < 2; p++) {
                uint32_t bd = wU + (ks * 16 + (lane & 15)) * 144
                            + (pw_c * 32 + p * 16 + ((lane >> 4) << 3)) * 2;
                ldsm_x4_t(bw[2*p][0], bw[2*p][1], bw[2*p+1][0], bw[2*p+1][1], bd);
            }
            #pragma unroll
            for (int nt = 0; nt < 4; nt++)
                mma_bf16(yacc[nt], axf, bw[nt]);
        }
        __syncthreads();   // all x2/lc2w reads done before A-region write / B stream

        #pragma unroll
        for (int half = 0; half < 2; half++) {
            int rib = pw_r * 16 + half * 8 + g;
            #pragma unroll
            for (int nt = 0; nt < 4; nt++) {
                int col = pw_c * 32 + nt * 8 + 2 * tig;
                float v0 = yacc[nt][half * 2 + 0] + lc2b[col];
                float v1 = yacc[nt][half * 2 + 1] + lc2b[col + 1];
                __nv_bfloat162 p;
                p.x = __float2bfloat16_rn(v0);
                p.y = __float2bfloat16_rn(v1);
                *(__nv_bfloat162*)(smc + rib * LMSTR + col * 2) = p;
            }
        }
        __syncthreads();
    }

    auto issue_B = [&](int stage, int t) {
        const char* Bb = (const char*)g_embf;
        #pragma unroll
        for (int i = 0; i < 4; i++) {
            int id = tid + i * 256;
            int row = id >> 3, c = (id & 7) << 4;
            int v = t * 128 + row;
            cp_async16(bU + stage * LM_BSTG + row * LMSTR + c,
                       Bb + (size_t)v * 128 + c, v < VOCAB);
        }
        cp_commit();
    };

    issue_B(0, 0);
    issue_B(1, 1);

    // preload A fragments (4 ksteps x 2 mt)
    uint32_t af[2][4][4];
    #pragma unroll
    for (int mt = 0; mt < 2; mt++)
        #pragma unroll
        for (int ks = 0; ks < 4; ks++) {
            uint32_t ad = aU + (wm * 32 + mt * 16 + (lane & 15)) * LMSTR
                        + ks * 32 + ((lane >> 4) << 4);
            ldsm_x4(af[mt][ks][0], af[mt][ks][1], af[mt][ks][2], af[mt][ks][3], ad);
        }

    float rm[4], rs[4];
    #pragma unroll
    for (int s = 0; s < 4; s++) { rm[s] = -1e30f; rs[s] = 0.0f; }

    int brow = (lane & 7) + ((lane >> 4) << 3);
    int bcol16 = ((lane >> 3) & 1) << 4;

    // ======== PASS 1: stats ========
    for (int t = 0; t < LM_NTILE; t++) {
        if (t == LM_NTILE - 1) cp_wait0(); else cp_wait1();
        __syncthreads();
        if (t + 2 < LM_NTILE) issue_B((t + 2) % 3, t + 2);

        uint32_t bB = bU + (t % 3) * LM_BSTG;
        float acc[2][4][4] = {};
        #pragma unroll
        for (int ks = 0; ks < 4; ks++) {
            uint32_t bfr[4][2];
            #pragma unroll
            for (int p = 0; p < 2; p++) {
                uint32_t bd = bB + (wn * 32 + p * 16 + brow) * LMSTR + ks * 32 + bcol16;
                ldsm_x4(bfr[2*p][0], bfr[2*p][1], bfr[2*p+1][0], bfr[2*p+1][1], bd);
            }
            #pragma unroll
            for (int mt = 0; mt < 2; mt++)
                #pragma unroll
                for (int nt = 0; nt < 4; nt++)
                    mma_bf16(acc[mt][nt], af[mt][ks], bfr[nt]);
        }

        int nb0 = t * 128 + wn * 32 + 2 * tig;
        #pragma unroll
        for (int mt = 0; mt < 2; mt++)
            #pragma unroll
            for (int half = 0; half < 2; half++) {
                int slot = mt * 2 + half;
                float v[8];
                float bm = -1e30f;
                #pragma unroll
                for (int nt = 0; nt < 4; nt++)
                    #pragma unroll
                    for (int j = 0; j < 2; j++) {
                        int n = nb0 + nt * 8 + j;
                        float x = (n < VOCAB) ? acc[mt][nt][half * 2 + j] : -1e30f;
                        v[nt * 2 + j] = x;
                        bm = fmaxf(bm, x);
                    }
                float nm = fmaxf(rm[slot], bm);
                float add = 0.0f;
                #pragma unroll
                for (int j = 0; j < 8; j++) add += __expf(v[j] - nm);
                rs[slot] = rs[slot] * __expf(rm[slot] - nm) + add;
                rm[slot] = nm;
            }
    }

    // ---- reduce stats ----
    #pragma unroll
    for (int slot = 0; slot < 4; slot++) {
        float m = rm[slot], s = rs[slot];
        #pragma unroll
        for (int off = 1; off <= 2; off <<= 1) {
            float om = __shfl_xor_sync(0xffffffffu, m, off);
            float os = __shfl_xor_sync(0xffffffffu, s, off);
            float nm = fmaxf(m, om);
            s = s * __expf(m - nm) + os * __expf(om - nm);
            m = nm;
        }
        int mt = slot >> 1, half = slot & 1;
        int rib = wm * 32 + mt * 16 + half * 8 + g;
        if (tig == 0) spart[rib * 4 + wn] = make_float2(m, s);
    }
    __syncthreads();
    if (tid < 64) {
        float m = -1e30f, s = 0.0f;
        #pragma unroll
        for (int w = 0; w < 4; w++) {
            float2 p = spart[tid * 4 + w];
            float nm = fmaxf(m, p.x);
            s = s * __expf(m - nm) + p.y * __expf(p.x - nm);
            m = nm;
        }
        sstat[tid] = make_float2(m, 1.0f / s);
    }
    __syncthreads();

    float stm[4], sti[4];
    #pragma unroll
    for (int slot = 0; slot < 4; slot++) {
        int mt = slot >> 1, half = slot & 1;
        int rib = wm * 32 + mt * 16 + half * 8 + g;
        float2 st = sstat[rib];
        stm[slot] = st.x; sti[slot] = st.y;
    }

    // ======== PASS 2: recompute + write probs ========
    issue_B(0, 0);
    issue_B(1, 1);
    for (int t = 0; t < LM_NTILE; t++) {
        if (t == LM_NTILE - 1) cp_wait0(); else cp_wait1();
        __syncthreads();
        if (t + 2 < LM_NTILE) issue_B((t + 2) % 3, t + 2);

        uint32_t bB = bU + (t % 3) * LM_BSTG;
        float acc[2][4][4] = {};
        #pragma unroll
        for (int ks = 0; ks < 4; ks++) {
            uint32_t bfr[4][2];
            #pragma unroll
            for (int p = 0; p < 2; p++) {
                uint32_t bd = bB + (wn * 32 + p * 16 + brow) * LMSTR + ks * 32 + bcol16;
                ldsm_x4(bfr[2*p][0], bfr[2*p][1], bfr[2*p+1][0], bfr[2*p+1][1], bd);
            }
            #pragma unroll
            for (int mt = 0; mt < 2; mt++)
                #pragma unroll
                for (int nt = 0; nt < 4; nt++)
                    mma_bf16(acc[mt][nt], af[mt][ks], bfr[nt]);
        }

        int nb0 = t * 128 + wn * 32 + 2 * tig;
        #pragma unroll
        for (int mt = 0; mt < 2; mt++)
            #pragma unroll
            for (int half = 0; half < 2; half++) {
                int slot = mt * 2 + half;
                int rib = wm * 32 + mt * 16 + half * 8 + g;
                size_t rowoff = (size_t)(m0 + rib) * VOCAB;
                float m = stm[slot], inv = sti[slot];
                #pragma unroll
                for (int nt = 0; nt < 4; nt++) {
                    int n = nb0 + nt * 8;
                    if (n < VOCAB) {
                        float p0 = __expf(acc[mt][nt][half * 2 + 0] - m) * inv;
                        float p1 = __expf(acc[mt][nt][half * 2 + 1] - m) * inv;
                        __stcs((float2*)&probs[rowoff + n], make_float2(p0, p1));
                    }
                }
            }
    }
}

// ---------------- attention ----------------
__global__ void __launch_bounds__(256) attention_kernel() {
    __shared__ float qs[8][DG], ks[8][DG], vs[8][DG];
    int b = blockIdx.x;
    int tid = threadIdx.x;
    for (int i = tid; i < 8 * DG; i += 256) {
        int s = i >> 8, c = i & 255;
        size_t off = (size_t)(b * 8 + s) * 768 + c;
        qs[s][c] = __bfloat162float(g_qkv[off]);
        ks[s][c] = __bfloat162float(g_qkv[off + 256]);
        vs[s][c] = __bfloat162float(g_qkv[off + 512]);
    }
    __syncthreads();

    int h  = tid >> 6;
    int qx = (tid >> 3) & 7;
    int kx = tid & 7;
    float att = 0.0f;
    #pragma unroll
    for (int d = 0; d < HD; d++)
        att += qs[qx][h * HD + d] * ks[kx][h * HD + d];
    att *= 0.125f;

    float mx = att;
    mx = fmaxf(mx, __shfl_xor_sync(0xffffffffu, mx, 4));
    mx = fmaxf(mx, __shfl_xor_sync(0xffffffffu, mx, 2));
    mx = fmaxf(mx, __shfl_xor_sync(0xffffffffu, mx, 1));
    float ex = expf(att - mx);
    float sm = ex;
    sm += __shfl_xor_sync(0xffffffffu, sm, 4);
    sm += __shfl_xor_sync(0xffffffffu, sm, 2);
    sm += __shfl_xor_sync(0xffffffffu, sm, 1);
    float a = ex / sm;

    int lane = tid & 31;
    int base = lane & ~7;
    float a_all[8];
    #pragma unroll
    for (int kk = 0; kk < 8; kk++)
        a_all[kk] = __shfl_sync(0xffffffffu, a, base + kk);

    #pragma unroll
    for (int t2 = 0; t2 < 8; t2++) {
        int d = kx * 8 + t2;
        float o = 0.0f;
        #pragma unroll
        for (int kk = 0; kk < 8; kk++)
            o += a_all[kk] * vs[kk][h * HD + d];
        g_ao[(size_t)(b * 8 + qx) * DG + h * HD + d] = __float2bfloat16_rn(o);
    }
}

// ---------------- host launcher ----------------
template<int EPI>
static void launch_one(const bf16* A, const bf16* B, void* C, int M, int N, int K,
                       const float* extraf, const bf16* extrab,
                       const int* gidx, int ldex) {
    static bool attr_done = false;
    if (!attr_done) {
        cudaFuncSetAttribute(tmma_k<EPI>, cudaFuncAttributeMaxDynamicSharedMemorySize,
                             GEMM_SMEM_BYTES);
        attr_done = true;
    }
    dim3 grid((N + TBN - 1) / TBN, M / TBM), blk(256);
    tmma_k<EPI><<<grid, blk, GEMM_SMEM_BYTES>>>(A, B, C, M, N, K, extraf, extrab, gidx, ldex);
}

static void launch_gemm(int epi, const bf16* A, const bf16* B, void* C,
                        int M, int N, int K,
                        const float* extraf = nullptr, const bf16* extrab = nullptr,
                        const int* gidx = nullptr, int ldex = 0) {
    switch (epi) {
        case 0: launch_one<0>(A, B, C, M, N, K, extraf, extrab, gidx, ldex); break;
        case 1: launch_one<1>(A, B, C, M, N, K, extraf, extrab, gidx, ldex); break;
        case 2: launch_one<2>(A, B, C, M, N, K, extraf, extrab, gidx, ldex); break;
        case 3: launch_one<3>(A, B, C, M, N, K, extraf, extrab, gidx, ldex); break;
        case 4: launch_one<4>(A, B, C, M, N, K, extraf, extrab, gidx, ldex); break;
        case 5: launch_one<5>(A, B, C, M, N, K, extraf, extrab, gidx, ldex); break;
    }
}

template <typename T>
static T* sym_addr(const void* sym) {
    void* p = nullptr;
    cudaGetSymbolAddress(&p, sym);
    return (T*)p;
}

extern "C" void kernel_launch(void* const* d_in, const int* in_sizes, int n_in,
                              void* d_out, int out_size) {
    const int*   node_tokens = (const int*)d_in[0];
    const int*   edge_tokens = (const int*)d_in[1];
    const int*   edge_index  = (const int*)d_in[2];
    const void*  mask_rows   = d_in[3];
    const float* emb    = (const float*)d_in[4];
    const float* W_msg  = (const float*)d_in[5];
    const float* W_node = (const float*)d_in[6];
    const float* lc1_w  = (const float*)d_in[7];
    const float* lc1_b  = (const float*)d_in[8];
    const float* lc2_w  = (const float*)d_in[9];
    const float* lc2_b  = (const float*)d_in[10];
    const float* Wq  = (const float*)d_in[11];
    const float* Wk  = (const float*)d_in[12];
    const float* Wv  = (const float*)d_in[13];
    const float* Wo  = (const float*)d_in[14];
    const float* Wf1 = (const float*)d_in[15];
    const float* Wf2 = (const float*)d_in[16];

    float* out = (float*)d_out;
    bool concat = (out_size != ROWS * VOCAB);
    float* labels_out = concat ? out : nullptr;
    float* probs      = concat ? out + ROWS : out;

    const int* src = edge_index;
    const int* dst = edge_index + N_EDGES;

    bf16* px   = sym_addr<bf16>(g_x);
    bf16* pe   = sym_addr<bf16>(g_e);
    bf16* pmsg = sym_addr<bf16>(g_msg);
    float* pagg= sym_addr<float>(g_agg);
    bf16* ph   = sym_addr<bf16>(g_h);
    bf16* peh  = sym_addr<bf16>(g_eh);
    bf16* pzg  = sym_addr<bf16>(g_zg);
    bf16* pqkv = sym_addr<bf16>(g_qkv);
    bf16* pao  = sym_addr<bf16>(g_ao);
    bf16* px1  = sym_addr<bf16>(g_x1);
    bf16* pffn = sym_addr<bf16>(g_ffn);
    bf16* px2  = sym_addr<bf16>(g_x2);
    bf16* pwmsg = sym_addr<bf16>(g_wmsg);
    bf16* pwnode= sym_addr<bf16>(g_wnode);
    bf16* plc1w = sym_addr<bf16>(g_lc1w);
    bf16* pwo   = sym_addr<bf16>(g_wo);
    bf16* pwf1  = sym_addr<bf16>(g_wf1);
    bf16* pwf2  = sym_addr<bf16>(g_wf2);
    bf16* pwqkv = sym_addr<bf16>(g_wqkv);

    // 1. mask dtype detect + labels/masked tokens
    detect_mask_kernel<<<1, 512>>>((const int*)mask_rows);
    mask_kernel<<<(N_EDGES * L_TOK + 255) / 256, 256>>>(edge_tokens, mask_rows, labels_out);

    // 2. merged prep + embeddings
    prep_all_kernel<<<(PREP_TOTAL + 255) / 256, 256>>>(W_msg, W_node, lc1_w, lc2_w,
                                                       Wo, Wf1, Wf2, emb, Wq, Wk, Wv);
    embed_all_kernel<<<(N16 + E16 + 255) / 256, 256>>>(node_tokens);

    // 3. GNN
    launch_gemm(3, pe, pwmsg, pmsg, N_EDGES, FD, FD, nullptr, px, src, FD);
    zero_kernel<<<(N_NODES * FD / 4 + 255) / 256, 256>>>((float4*)pagg, N_NODES * FD / 4);
    scatter_add_kernel<<<(N_EDGES * FD / 8 + 255) / 256, 256>>>(dst);
    launch_gemm(2, px, pwnode, ph, N_NODES, FD, FD, pagg, nullptr, nullptr, FD);
    edge_gather_kernel<<<(N_EDGES * FD / 8 + 255) / 256, 256>>>(src, dst);

    // 4. lc1
    launch_gemm(1, peh, plc1w, pzg, ROWS, DG, D_GNN, lc1_b);

    // 5. transformer
    launch_gemm(0, pzg, pwqkv, pqkv, ROWS, 3 * DG, DG);
    attention_kernel<<<N_EDGES, 256>>>();
    launch_gemm(4, pao, pwo, px1, ROWS, DG, DG, nullptr, pzg, nullptr, DG);
    launch_gemm(5, px1, pwf1, pffn, ROWS, 4 * DG, DG);
    launch_gemm(4, pffn, pwf2, px2, ROWS, DG, 4 * DG, nullptr, px1, nullptr, DG);

    // 6. fused LM head (M=64 rows/CTA, grid 256, 2 CTAs/SM)
    {
        static bool lm_attr = false;
        if (!lm_attr) {
            cudaFuncSetAttribute(lm_fused, cudaFuncAttributeMaxDynamicSharedMemorySize,
                                 LM_SMEM_TOT);
            lm_attr = true;
        }
        lm_fused<<<ROWS / 64, 256, LM_SMEM_TOT>>>(probs, lc2_b);
    }
}

// round 13
// speedup vs baseline: 1.0995x; 1.0264x over previous
#include <cuda_runtime.h>
#include <cuda_bf16.h>
#include <math.h>
#include <stdint.h>

// ---------------- problem constants ----------------
#define VOCAB   10000
#define D_GNN   64
#define L_TOK   8
#define DG      256
#define NH      4
#define HD      64
#define N_NODES 8192
#define N_EDGES 2048
#define FD      512
#define ROWS    16384

typedef __nv_bfloat16 bf16;

// ---------------- scratch (static device memory) ----------------
__device__ bf16  g_x   [N_NODES * FD];
__device__ bf16  g_e   [N_EDGES * FD];
__device__ float g_agg [N_NODES * FD];
__device__ bf16  g_h   [N_NODES * FD];
__device__ bf16  g_eh  [N_EDGES * FD];
__device__ bf16  g_zg  [ROWS * DG];
__device__ bf16  g_qkv [ROWS * 3 * DG];
__device__ bf16  g_ao  [ROWS * DG];
__device__ bf16  g_x1  [ROWS * DG];
__device__ bf16  g_ffn [ROWS * 4 * DG];
__device__ bf16  g_x2  [ROWS * DG];
__device__ bf16  g_wmsg [FD * FD];
__device__ bf16  g_wnode[FD * FD];
__device__ bf16  g_lc1w [D_GNN * DG];
__device__ bf16  g_lc2w [DG * D_GNN];
__device__ bf16  g_wo   [DG * DG];
__device__ bf16  g_wf1  [DG * 4 * DG];
__device__ bf16  g_wf2  [4 * DG * DG];
__device__ bf16  g_wqkv [DG * 3 * DG];
__device__ bf16  g_embf [VOCAB * D_GNN];
__device__ int   g_mtok[N_EDGES * L_TOK];
__device__ int   g_mask_mode;

// ---------------- mask dtype detection ----------------
__global__ void detect_mask_kernel(const int* __restrict__ mr) {
    __shared__ int notint, notflt;
    if (threadIdx.x == 0) { notint = 0; notflt = 0; }
    __syncthreads();
    int w = mr[threadIdx.x];
    if (w != 0 && w != 1)          atomicExch(&notint, 1);
    if (w != 0 && w != 0x3F800000) atomicExch(&notflt, 1);
    __syncthreads();
    if (threadIdx.x == 0)
        g_mask_mode = notint ? (notflt ? 2 : 1) : 0;
}

__global__ void mask_kernel(const int* __restrict__ etok, const void* __restrict__ maskraw,
                            float* labels_out) {
    int i = blockIdx.x * blockDim.x + threadIdx.x;
    if (i >= N_EDGES * L_TOK) return;
    int e = i >> 3;
    int t = etok[i];
    bool mr;
    int mode = g_mask_mode;
    if (mode == 0)      mr = ((const int*)maskraw)[e] != 0;
    else if (mode == 1) mr = ((const float*)maskraw)[e] != 0.0f;
    else                mr = ((const unsigned char*)maskraw)[e] != 0;
    bool msk = mr && (t >= 4);
    g_mtok[i] = msk ? 4 : t;
    if (labels_out) labels_out[i] = msk ? (float)t : -100.0f;
}

// ---------------- merged prep ----------------
#define SZ_WMSG  (FD*FD)
#define SZ_WNODE (FD*FD)
#define SZ_LC1   (D_GNN*DG)
#define SZ_LC2   (DG*D_GNN)
#define SZ_WO    (DG*DG)
#define SZ_WF1   (DG*4*DG)
#define SZ_WF2   (4*DG*DG)
#define CW_TOTAL (SZ_WMSG+SZ_WNODE+SZ_LC1+SZ_LC2+SZ_WO+SZ_WF1+SZ_WF2)
#define PREP_TOTAL (CW_TOTAL + VOCAB*D_GNN + DG*DG)

__global__ void prep_all_kernel(const float* Wmsg, const float* Wnode,
                                const float* lc1w, const float* lc2w,
                                const float* Wo, const float* Wf1, const float* Wf2,
                                const float* emb, const float* Wq, const float* Wk,
                                const float* Wv) {
    int i = blockIdx.x * blockDim.x + threadIdx.x;
    if (i >= PREP_TOTAL) return;
    int j = i;
    if (j < SZ_WMSG)  { g_wmsg[j]  = __float2bfloat16_rn(Wmsg[j]);  return; } j -= SZ_WMSG;
    if (j < SZ_WNODE) { g_wnode[j] = __float2bfloat16_rn(Wnode[j]); return; } j -= SZ_WNODE;
    if (j < SZ_LC1)   { g_lc1w[j]  = __float2bfloat16_rn(lc1w[j]);  return; } j -= SZ_LC1;
    if (j < SZ_LC2)   { g_lc2w[j]  = __float2bfloat16_rn(lc2w[j]);  return; } j -= SZ_LC2;
    if (j < SZ_WO)    { g_wo[j]    = __float2bfloat16_rn(Wo[j]);    return; } j -= SZ_WO;
    if (j < SZ_WF1)   { g_wf1[j]   = __float2bfloat16_rn(Wf1[j]);   return; } j -= SZ_WF1;
    if (j < SZ_WF2)   { g_wf2[j]   = __float2bfloat16_rn(Wf2[j]);   return; } j -= SZ_WF2;
    if (j < VOCAB*D_GNN) { g_embf[j] = __float2bfloat16_rn(emb[j]); return; } j -= VOCAB*D_GNN;
    int k = j >> 8, n = j & 255;
    g_wqkv[k * 768 + n]       = __float2bfloat16_rn(Wq[j]);
    g_wqkv[k * 768 + 256 + n] = __float2bfloat16_rn(Wk[j]);
    g_wqkv[k * 768 + 512 + n] = __float2bfloat16_rn(Wv[j]);
}

#define N16 (N_NODES * FD / 8)
#define E16 (N_EDGES * FD / 8)
__global__ void embed_all_kernel(const int* __restrict__ ntok) {
    int i = blockIdx.x * blockDim.x + threadIdx.x;
    if (i >= N16 + E16) return;
    const uint4* tab = (const uint4*)g_embf;
    if (i < N16) {
        ((uint4*)g_x)[i] = tab[ntok[i >> 3] * 8 + (i & 7)];
    } else {
        int j = i - N16;
        ((uint4*)g_e)[j] = tab[g_mtok[j >> 3] * 8 + (j & 7)];
    }
}

__global__ void zero_kernel(float4* __restrict__ p, int n4) {
    int i = blockIdx.x * blockDim.x + threadIdx.x;
    if (i < n4) p[i] = make_float4(0.f, 0.f, 0.f, 0.f);
}

__device__ __forceinline__ void unpack8(uint4 raw, float* v) {
    const __nv_bfloat162* h = (const __nv_bfloat162*)&raw;
    #pragma unroll
    for (int j = 0; j < 4; j++) {
        v[2*j]   = __bfloat162float(h[j].x);
        v[2*j+1] = __bfloat162float(h[j].y);
    }
}

__global__ void edge_gather_kernel(const int* __restrict__ src, const int* __restrict__ dst) {
    int i = blockIdx.x * blockDim.x + threadIdx.x;
    if (i >= N_EDGES * FD / 8) return;
    int e = i >> 6, c8 = (i & 63) * 8;
    uint4 ra = *(const uint4*)(g_h + (size_t)src[e] * FD + c8);
    uint4 rb = *(const uint4*)(g_h + (size_t)dst[e] * FD + c8);
    float a[8], b[8]; unpack8(ra, a); unpack8(rb, b);
    __nv_bfloat162 o[4];
    #pragma unroll
    for (int j = 0; j < 4; j++) {
        o[j].x = __float2bfloat16_rn(a[2*j]   + b[2*j]);
        o[j].y = __float2bfloat16_rn(a[2*j+1] + b[2*j+1]);
    }
    *(uint4*)(g_eh + ((size_t)e << 9) + c8) = *(uint4*)o;
}

// ================= common helpers =================
__device__ __forceinline__ void cp_async16(uint32_t dst, const void* src, bool pred) {
    int sz = pred ? 16 : 0;
    asm volatile("cp.async.cg.shared.global [%0], [%1], 16, %2;\n"
                 :: "r"(dst), "l"(src), "r"(sz));
}
__device__ __forceinline__ void cp_commit() { asm volatile("cp.async.commit_group;\n"); }
__device__ __forceinline__ void cp_wait0()  { asm volatile("cp.async.wait_group 0;\n"); }
__device__ __forceinline__ void cp_wait1()  { asm volatile("cp.async.wait_group 1;\n"); }

__device__ __forceinline__ void mma_bf16(float c[4], const uint32_t a[4], const uint32_t b[2]) {
    asm volatile(
        "mma.sync.aligned.m16n8k16.row.col.f32.bf16.bf16.f32 "
        "{%0,%1,%2,%3}, {%4,%5,%6,%7}, {%8,%9}, {%0,%1,%2,%3};"
        : "+f"(c[0]), "+f"(c[1]), "+f"(c[2]), "+f"(c[3])
        : "r"(a[0]), "r"(a[1]), "r"(a[2]), "r"(a[3]), "r"(b[0]), "r"(b[1]));
}

__device__ __forceinline__ void ldsm_x4(uint32_t& r0, uint32_t& r1, uint32_t& r2, uint32_t& r3,
                                        uint32_t addr) {
    asm volatile("ldmatrix.sync.aligned.m8n8.x4.shared.b16 {%0,%1,%2,%3}, [%4];"
                 : "=r"(r0), "=r"(r1), "=r"(r2), "=r"(r3) : "r"(addr));
}
__device__ __forceinline__ void ldsm_x4_t(uint32_t& r0, uint32_t& r1, uint32_t& r2, uint32_t& r3,
                                          uint32_t addr) {
    asm volatile("ldmatrix.sync.aligned.m8n8.x4.trans.shared.b16 {%0,%1,%2,%3}, [%4];"
                 : "=r"(r0), "=r"(r1), "=r"(r2), "=r"(r3) : "r"(addr));
}

// ================= mma.sync bf16 GEMM (mid-network), TBK=64 =================
// EPI: 0 plain | 1 +biasf[n] | 2 relu(+extraf[m*ld+n]) |
//      3 relu(c + extrab[gidx[m]*ld+n]) -> atomicAdd(aggout[gidx2[m]*ld+n])  [no C write]
//      4 +extrab[m*ld+n] | 5 gelu

#define TBM 128
#define TBN 128
#define TBK 64
#define ASTRH 72      // A row stride (bf16): bank start 4r mod 32 -> conflict-free
#define BSTRH 136
#define NSTAGE 3
#define A_STAGE_H (TBM * ASTRH)     // 9216
#define B_STAGE_H (TBK * BSTRH)     // 8704
#define GEMM_SMEM_BYTES (NSTAGE * (A_STAGE_H + B_STAGE_H) * 2)   // 107520

template<int EPI>
__global__ void __launch_bounds__(256)
tmma_k(const bf16* __restrict__ A, const bf16* __restrict__ B, void* __restrict__ Cv,
       int M, int N, int K,
       const float* __restrict__ extraf, const bf16* __restrict__ extrab,
       const int* __restrict__ gidx, const int* __restrict__ gidx2, int ldex,
       float* __restrict__ aggout) {
    extern __shared__ bf16 smem[];
    bf16* Asm = smem;
    bf16* Bsm = smem + NSTAGE * A_STAGE_H;

    uint32_t aU = (uint32_t)__cvta_generic_to_shared(Asm);
    uint32_t bU = (uint32_t)__cvta_generic_to_shared(Bsm);

    int tid  = threadIdx.x;
    int lane = tid & 31;
    int warp = tid >> 5;
    int wm = warp & 1;
    int wn = warp >> 1;
    int g   = lane >> 2;
    int tig = lane & 3;
    int m0 = blockIdx.y * TBM;
    int n0 = blockIdx.x * TBN;

    float acc[4][4][4] = {};

    auto issue_load = [&](int s, int k0) {
        #pragma unroll
        for (int i = 0; i < 4; i++) {
            int id = tid + i * 256;
            int ar = id >> 3, ak = (id & 7) << 3;
            uint32_t da = aU + (s * A_STAGE_H + ar * ASTRH + ak) * 2;
            cp_async16(da, A + (size_t)(m0 + ar) * K + k0 + ak, true);
            int br = id >> 4, bn = (id & 15) << 3;
            int gn = n0 + bn;
            uint32_t db = bU + (s * B_STAGE_H + br * BSTRH + bn) * 2;
            cp_async16(db, B + (size_t)(k0 + br) * N + gn, gn + 8 <= N);
        }
    };

    int niter = K / TBK;   // >= 1
    issue_load(0, 0);
    cp_commit();
    if (niter > 1) { issue_load(1, TBK); cp_commit(); }

    for (int it = 0; it < niter; it++) {
        if (it >= niter - 2) cp_wait0(); else cp_wait1();
        __syncthreads();
        if (it + 2 < niter) {
            issue_load((it + 2) % NSTAGE, (it + 2) * TBK);
            cp_commit();
        }
        int s = it % NSTAGE;
        uint32_t aB = aU + s * A_STAGE_H * 2;
        uint32_t bB = bU + s * B_STAGE_H * 2;
        #pragma unroll
        for (int ks = 0; ks < TBK; ks += 16) {
            uint32_t af[4][4], bfr[4][2];
            #pragma unroll
            for (int mt = 0; mt < 4; mt++) {
                int row = wm * 64 + mt * 16 + (lane & 15);
                uint32_t ad = aB + (row * ASTRH + ks + ((lane >> 4) << 3)) * 2;
                ldsm_x4(af[mt][0], af[mt][1], af[mt][2], af[mt][3], ad);
            }
            #pragma unroll
            for (int bp = 0; bp < 2; bp++) {
                int krow = ks + (lane & 15);
                int ncol = wn * 32 + bp * 16 + ((lane >> 4) << 3);
                uint32_t bd = bB + (krow * BSTRH + ncol) * 2;
                ldsm_x4_t(bfr[2*bp][0], bfr[2*bp][1], bfr[2*bp+1][0], bfr[2*bp+1][1], bd);
            }
            #pragma unroll
            for (int mt = 0; mt < 4; mt++)
                #pragma unroll
                for (int nt = 0; nt < 4; nt++)
                    mma_bf16(acc[mt][nt], af[mt], bfr[nt]);
        }
    }

    bf16* Cb = (bf16*)Cv;

    #pragma unroll
    for (int mt = 0; mt < 4; mt++) {
        #pragma unroll
        for (int half = 0; half < 2; half++) {
            int rib = wm * 64 + mt * 16 + half * 8 + g;
            int r = m0 + rib;
            int ebase = 0, abase = 0;
            if (EPI == 2 || EPI == 4) ebase = r * ldex;
            if (EPI == 3) { ebase = gidx[r] * ldex; abase = gidx2[r] * ldex; }

            #pragma unroll
            for (int nt = 0; nt < 4; nt++) {
                int n = n0 + wn * 32 + nt * 8 + 2 * tig;
                float c0 = acc[mt][nt][half * 2 + 0];
                float c1 = acc[mt][nt][half * 2 + 1];
                if (EPI == 1) { c0 += extraf[n]; c1 += extraf[n + 1]; }
                else if (EPI == 2) {
                    c0 = fmaxf(c0 + extraf[ebase + n],     0.0f);
                    c1 = fmaxf(c1 + extraf[ebase + n + 1], 0.0f);
                } else if (EPI == 3) {
                    c0 = fmaxf(c0 + __bfloat162float(extrab[ebase + n]),     0.0f);
                    c1 = fmaxf(c1 + __bfloat162float(extrab[ebase + n + 1]), 0.0f);
                    atomicAdd(&aggout[abase + n],     c0);
                    atomicAdd(&aggout[abase + n + 1], c1);
                    continue;
                } else if (EPI == 4) {
                    c0 += __bfloat162float(extrab[ebase + n]);
                    c1 += __bfloat162float(extrab[ebase + n + 1]);
                } else if (EPI == 5) {
                    float x = c0;
                    c0 = 0.5f * x * (1.0f + tanhf(0.7978845608028654f * (x + 0.044715f * x * x * x)));
                    x = c1;
                    c1 = 0.5f * x * (1.0f + tanhf(0.7978845608028654f * (x + 0.044715f * x * x * x)));
                }
                if (n + 1 < N) {
                    __nv_bfloat162 p;
                    p.x = __float2bfloat16_rn(c0);
                    p.y = __float2bfloat16_rn(c1);
                    *(__nv_bfloat162*)&Cb[(size_t)r * N + n] = p;
                }
            }
        }
    }
}

// ================= fused persistent LM head, M=64 rows/CTA (R12 proven) =================
#define LMSTR    144
#define LM_A_B   (64 * LMSTR)
#define LM_BSTG  (128 * LMSTR)
#define LM_B_OFF LM_A_B
#define LM_NTILE 79
#define LM_X2_OFF  LM_A_B
#define LM_W2_OFF  (LM_A_B + 64 * 528)
#define LM_STAT_OFF (LM_W2_OFF + 256 * 144)
#define LM_SMEM_TOT (LM_STAT_OFF + 64 * 4 * 8 + 64 * 8)

__global__ void __launch_bounds__(256, 2)
lm_fused(float* __restrict__ probs, const float* __restrict__ lc2b) {
    extern __shared__ char smc[];
    uint32_t aU = (uint32_t)__cvta_generic_to_shared(smc);
    uint32_t bU = aU + LM_B_OFF;
    float2* spart = (float2*)(smc + LM_STAT_OFF);
    float2* sstat = spart + 64 * 4;

    int tid = threadIdx.x;
    int lane = tid & 31, warp = tid >> 5;
    int wm = warp & 1, wn = warp >> 1;
    int g = lane >> 2, tig = lane & 3;
    int m0 = blockIdx.x * 64;

    // ---- preamble: y[64,64] = x2[64,256] @ lc2w + b -> A region ----
    {
        uint32_t xU = aU + LM_X2_OFF;
        uint32_t wU = aU + LM_W2_OFF;
        const char* X2b = (const char*)g_x2;
        #pragma unroll
        for (int i = 0; i < 8; i++) {
            int id = tid + i * 256;
            int row = id >> 5, c = (id & 31) << 4;
            cp_async16(xU + row * 528 + c, X2b + (size_t)(m0 + row) * 512 + c, true);
        }
        const char* W2b = (const char*)g_lc2w;
        #pragma unroll
        for (int i = 0; i < 8; i++) {
            int id = tid + i * 256;
            int row = id >> 3, c = (id & 7) << 4;
            cp_async16(wU + row * 144 + c, W2b + (size_t)row * 128 + c, true);
        }
        cp_commit(); cp_wait0();
        __syncthreads();

        int pw_r = warp & 3;
        int pw_c = warp >> 2;
        float yacc[4][4] = {};
        #pragma unroll
        for (int ks = 0; ks < 16; ks++) {
            uint32_t axf[4];
            uint32_t ad = xU + (pw_r * 16 + (lane & 15)) * 528
                        + (ks * 16 + ((lane >> 4) << 3)) * 2;
            ldsm_x4(axf[0], axf[1], axf[2], axf[3], ad);
            uint32_t bw[4][2];
            #pragma unroll
            for (int p = 0; p < 2; p++) {
                uint32_t bd = wU + (ks * 16 + (lane & 15)) * 144
                            + (pw_c * 32 + p * 16 + ((lane >> 4) << 3)) * 2;
                ldsm_x4_t(bw[2*p][0], bw[2*p][1], bw[2*p+1][0], bw[2*p+1][1], bd);
            }
            #pragma unroll
            for (int nt = 0; nt < 4; nt++)
                mma_bf16(yacc[nt], axf, bw[nt]);
        }
        __syncthreads();

        #pragma unroll
        for (int half = 0; half < 2; half++) {
            int rib = pw_r * 16 + half * 8 + g;
            #pragma unroll
            for (int nt = 0; nt < 4; nt++) {
                int col = pw_c * 32 + nt * 8 + 2 * tig;
                float v0 = yacc[nt][half * 2 + 0] + lc2b[col];
                float v1 = yacc[nt][half * 2 + 1] + lc2b[col + 1];
                __nv_bfloat162 p;
                p.x = __float2bfloat16_rn(v0);
                p.y = __float2bfloat16_rn(v1);
                *(__nv_bfloat162*)(smc + rib * LMSTR + col * 2) = p;
            }
        }
        __syncthreads();
    }

    auto issue_B = [&](int stage, int t) {
        const char* Bb = (const char*)g_embf;
        #pragma unroll
        for (int i = 0; i < 4; i++) {
            int id = tid + i * 256;
            int row = id >> 3, c = (id & 7) << 4;
            int v = t * 128 + row;
            cp_async16(bU + stage * LM_BSTG + row * LMSTR + c,
                       Bb + (size_t)v * 128 + c, v < VOCAB);
        }
        cp_commit();
    };

    issue_B(0, 0);
    issue_B(1, 1);

    uint32_t af[2][4][4];
    #pragma unroll
    for (int mt = 0; mt < 2; mt++)
        #pragma unroll
        for (int ks = 0; ks < 4; ks++) {
            uint32_t ad = aU + (wm * 32 + mt * 16 + (lane & 15)) * LMSTR
                        + ks * 32 + ((lane >> 4) << 4);
            ldsm_x4(af[mt][ks][0], af[mt][ks][1], af[mt][ks][2], af[mt][ks][3], ad);
        }

    float rm[4], rs[4];
    #pragma unroll
    for (int s = 0; s < 4; s++) { rm[s] = -1e30f; rs[s] = 0.0f; }

    int brow = (lane & 7) + ((lane >> 4) << 3);
    int bcol16 = ((lane >> 3) & 1) << 4;

    // ======== PASS 1: stats ========
    for (int t = 0; t < LM_NTILE; t++) {
        if (t == LM_NTILE - 1) cp_wait0(); else cp_wait1();
        __syncthreads();
        if (t + 2 < LM_NTILE) issue_B((t + 2) % 3, t + 2);

        uint32_t bB = bU + (t % 3) * LM_BSTG;
        float acc[2][4][4] = {};
        #pragma unroll
        for (int ks = 0; ks < 4; ks++) {
            uint32_t bfr[4][2];
            #pragma unroll
            for (int p = 0; p < 2; p++) {
                uint32_t bd = bB + (wn * 32 + p * 16 + brow) * LMSTR + ks * 32 + bcol16;
                ldsm_x4(bfr[2*p][0], bfr[2*p][1], bfr[2*p+1][0], bfr[2*p+1][1], bd);
            }
            #pragma unroll
            for (int mt = 0; mt < 2; mt++)
                #pragma unroll
                for (int nt = 0; nt < 4; nt++)
                    mma_bf16(acc[mt][nt], af[mt][ks], bfr[nt]);
        }

        int nb0 = t * 128 + wn * 32 + 2 * tig;
        #pragma unroll
        for (int mt = 0; mt < 2; mt++)
            #pragma unroll
            for (int half = 0; half < 2; half++) {
                int slot = mt * 2 + half;
                float v[8];
                float bm = -1e30f;
                #pragma unroll
                for (int nt = 0; nt < 4; nt++)
                    #pragma unroll
                    for (int j = 0; j < 2; j++) {
                        int n = nb0 + nt * 8 + j;
                        float x = (n < VOCAB) ? acc[mt][nt][half * 2 + j] : -1e30f;
                        v[nt * 2 + j] = x;
                        bm = fmaxf(bm, x);
                    }
                float nm = fmaxf(rm[slot], bm);
                float add = 0.0f;
                #pragma unroll
                for (int j = 0; j < 8; j++) add += __expf(v[j] - nm);
                rs[slot] = rs[slot] * __expf(rm[slot] - nm) + add;
                rm[slot] = nm;
            }
    }

    // ---- reduce stats ----
    #pragma unroll
    for (int slot = 0; slot < 4; slot++) {
        float m = rm[slot], s = rs[slot];
        #pragma unroll
        for (int off = 1; off <= 2; off <<= 1) {
            float om = __shfl_xor_sync(0xffffffffu, m, off);
            float os = __shfl_xor_sync(0xffffffffu, s, off);
            float nm = fmaxf(m, om);
            s = s * __expf(m - nm) + os * __expf(om - nm);
            m = nm;
        }
        int mt = slot >> 1, half = slot & 1;
        int rib = wm * 32 + mt * 16 + half * 8 + g;
        if (tig == 0) spart[rib * 4 + wn] = make_float2(m, s);
    }
    __syncthreads();
    if (tid < 64) {
        float m = -1e30f, s = 0.0f;
        #pragma unroll
        for (int w = 0; w < 4; w++) {
            float2 p = spart[tid * 4 + w];
            float nm = fmaxf(m, p.x);
            s = s * __expf(m - nm) + p.y * __expf(p.x - nm);
            m = nm;
        }
        sstat[tid] = make_float2(m, 1.0f / s);
    }
    __syncthreads();

    float stm[4], sti[4];
    #pragma unroll
    for (int slot = 0; slot < 4; slot++) {
        int mt = slot >> 1, half = slot & 1;
        int rib = wm * 32 + mt * 16 + half * 8 + g;
        float2 st = sstat[rib];
        stm[slot] = st.x; sti[slot] = st.y;
    }

    // ======== PASS 2: recompute + write probs ========
    issue_B(0, 0);
    issue_B(1, 1);
    for (int t = 0; t < LM_NTILE; t++) {
        if (t == LM_NTILE - 1) cp_wait0(); else cp_wait1();
        __syncthreads();
        if (t + 2 < LM_NTILE) issue_B((t + 2) % 3, t + 2);

        uint32_t bB = bU + (t % 3) * LM_BSTG;
        float acc[2][4][4] = {};
        #pragma unroll
        for (int ks = 0; ks < 4; ks++) {
            uint32_t bfr[4][2];
            #pragma unroll
            for (int p = 0; p < 2; p++) {
                uint32_t bd = bB + (wn * 32 + p * 16 + brow) * LMSTR + ks * 32 + bcol16;
                ldsm_x4(bfr[2*p][0], bfr[2*p][1], bfr[2*p+1][0], bfr[2*p+1][1], bd);
            }
            #pragma unroll
            for (int mt = 0; mt < 2; mt++)
                #pragma unroll
                for (int nt = 0; nt < 4; nt++)
                    mma_bf16(acc[mt][nt], af[mt][ks], bfr[nt]);
        }

        int nb0 = t * 128 + wn * 32 + 2 * tig;
        #pragma unroll
        for (int mt = 0; mt < 2; mt++)
            #pragma unroll
            for (int half = 0; half < 2; half++) {
                int slot = mt * 2 + half;
                int rib = wm * 32 + mt * 16 + half * 8 + g;
                size_t rowoff = (size_t)(m0 + rib) * VOCAB;
                float m = stm[slot], inv = sti[slot];
                #pragma unroll
                for (int nt = 0; nt < 4; nt++) {
                    int n = nb0 + nt * 8;
                    if (n < VOCAB) {
                        float p0 = __expf(acc[mt][nt][half * 2 + 0] - m) * inv;
                        float p1 = __expf(acc[mt][nt][half * 2 + 1] - m) * inv;
                        __stcs((float2*)&probs[rowoff + n], make_float2(p0, p1));
                    }
                }
            }
    }
}

// ---------------- attention ----------------
__global__ void __launch_bounds__(256) attention_kernel() {
    __shared__ float qs[8][DG], ks[8][DG], vs[8][DG];
    int b = blockIdx.x;
    int tid = threadIdx.x;
    for (int i = tid; i < 8 * DG; i += 256) {
        int s = i >> 8, c = i & 255;
        size_t off = (size_t)(b * 8 + s) * 768 + c;
        qs[s][c] = __bfloat162float(g_qkv[off]);
        ks[s][c] = __bfloat162float(g_qkv[off + 256]);
        vs[s][c] = __bfloat162float(g_qkv[off + 512]);
    }
    __syncthreads();

    int h  = tid >> 6;
    int qx = (tid >> 3) & 7;
    int kx = tid & 7;
    float att = 0.0f;
    #pragma unroll
    for (int d = 0; d < HD; d++)
        att += qs[qx][h * HD + d] * ks[kx][h * HD + d];
    att *= 0.125f;

    float mx = att;
    mx = fmaxf(mx, __shfl_xor_sync(0xffffffffu, mx, 4));
    mx = fmaxf(mx, __shfl_xor_sync(0xffffffffu, mx, 2));
    mx = fmaxf(mx, __shfl_xor_sync(0xffffffffu, mx, 1));
    float ex = expf(att - mx);
    float sm = ex;
    sm += __shfl_xor_sync(0xffffffffu, sm, 4);
    sm += __shfl_xor_sync(0xffffffffu, sm, 2);
    sm += __shfl_xor_sync(0xffffffffu, sm, 1);
    float a = ex / sm;

    int lane = tid & 31;
    int base = lane & ~7;
    float a_all[8];
    #pragma unroll
    for (int kk = 0; kk < 8; kk++)
        a_all[kk] = __shfl_sync(0xffffffffu, a, base + kk);

    #pragma unroll
    for (int t2 = 0; t2 < 8; t2++) {
        int d = kx * 8 + t2;
        float o = 0.0f;
        #pragma unroll
        for (int kk = 0; kk < 8; kk++)
            o += a_all[kk] * vs[kk][h * HD + d];
        g_ao[(size_t)(b * 8 + qx) * DG + h * HD + d] = __float2bfloat16_rn(o);
    }
}

// ---------------- host launcher ----------------
template<int EPI>
static void launch_one(const bf16* A, const bf16* B, void* C, int M, int N, int K,
                       const float* extraf, const bf16* extrab,
                       const int* gidx, const int* gidx2, int ldex, float* aggout) {
    static bool attr_done = false;
    if (!attr_done) {
        cudaFuncSetAttribute(tmma_k<EPI>, cudaFuncAttributeMaxDynamicSharedMemorySize,
                             GEMM_SMEM_BYTES);
        attr_done = true;
    }
    dim3 grid((N + TBN - 1) / TBN, M / TBM), blk(256);
    tmma_k<EPI><<<grid, blk, GEMM_SMEM_BYTES>>>(A, B, C, M, N, K, extraf, extrab,
                                                gidx, gidx2, ldex, aggout);
}

static void launch_gemm(int epi, const bf16* A, const bf16* B, void* C,
                        int M, int N, int K,
                        const float* extraf = nullptr, const bf16* extrab = nullptr,
                        const int* gidx = nullptr, const int* gidx2 = nullptr,
                        int ldex = 0, float* aggout = nullptr) {
    switch (epi) {
        case 0: launch_one<0>(A, B, C, M, N, K, extraf, extrab, gidx, gidx2, ldex, aggout); break;
        case 1: launch_one<1>(A, B, C, M, N, K, extraf, extrab, gidx, gidx2, ldex, aggout); break;
        case 2: launch_one<2>(A, B, C, M, N, K, extraf, extrab, gidx, gidx2, ldex, aggout); break;
        case 3: launch_one<3>(A, B, C, M, N, K, extraf, extrab, gidx, gidx2, ldex, aggout); break;
        case 4: launch_one<4>(A, B, C, M, N, K, extraf, extrab, gidx, gidx2, ldex, aggout); break;
        case 5: launch_one<5>(A, B, C, M, N, K, extraf, extrab, gidx, gidx2, ldex, aggout); break;
    }
}

template <typename T>
static T* sym_addr(const void* sym) {
    void* p = nullptr;
    cudaGetSymbolAddress(&p, sym);
    return (T*)p;
}

extern "C" void kernel_launch(void* const* d_in, const int* in_sizes, int n_in,
                              void* d_out, int out_size) {
    const int*   node_tokens = (const int*)d_in[0];
    const int*   edge_tokens = (const int*)d_in[1];
    const int*   edge_index  = (const int*)d_in[2];
    const void*  mask_rows   = d_in[3];
    const float* emb    = (const float*)d_in[4];
    const float* W_msg  = (const float*)d_in[5];
    const float* W_node = (const float*)d_in[6];
    const float* lc1_w  = (const float*)d_in[7];
    const float* lc1_b  = (const float*)d_in[8];
    const float* lc2_w  = (const float*)d_in[9];
    const float* lc2_b  = (const float*)d_in[10];
    const float* Wq  = (const float*)d_in[11];
    const float* Wk  = (const float*)d_in[12];
    const float* Wv  = (const float*)d_in[13];
    const float* Wo  = (const float*)d_in[14];
    const float* Wf1 = (const float*)d_in[15];
    const float* Wf2 = (const float*)d_in[16];

    float* out = (float*)d_out;
    bool concat = (out_size != ROWS * VOCAB);
    float* labels_out = concat ? out : nullptr;
    float* probs      = concat ? out + ROWS : out;

    const int* src = edge_index;
    const int* dst = edge_index + N_EDGES;

    bf16* px   = sym_addr<bf16>(g_x);
    bf16* pe   = sym_addr<bf16>(g_e);
    float* pagg= sym_addr<float>(g_agg);
    bf16* ph   = sym_addr<bf16>(g_h);
    bf16* peh  = sym_addr<bf16>(g_eh);
    bf16* pzg  = sym_addr<bf16>(g_zg);
    bf16* pqkv = sym_addr<bf16>(g_qkv);
    bf16* pao  = sym_addr<bf16>(g_ao);
    bf16* px1  = sym_addr<bf16>(g_x1);
    bf16* pffn = sym_addr<bf16>(g_ffn);
    bf16* px2  = sym_addr<bf16>(g_x2);
    bf16* pwmsg = sym_addr<bf16>(g_wmsg);
    bf16* pwnode= sym_addr<bf16>(g_wnode);
    bf16* plc1w = sym_addr<bf16>(g_lc1w);
    bf16* pwo   = sym_addr<bf16>(g_wo);
    bf16* pwf1  = sym_addr<bf16>(g_wf1);
    bf16* pwf2  = sym_addr<bf16>(g_wf2);
    bf16* pwqkv = sym_addr<bf16>(g_wqkv);

    // 1. mask dtype detect + labels/masked tokens
    detect_mask_kernel<<<1, 512>>>((const int*)mask_rows);
    mask_kernel<<<(N_EDGES * L_TOK + 255) / 256, 256>>>(edge_tokens, mask_rows, labels_out);

    // 2. merged prep + embeddings (+ zero agg, needed before fused-scatter msg GEMM)
    prep_all_kernel<<<(PREP_TOTAL + 255) / 256, 256>>>(W_msg, W_node, lc1_w, lc2_w,
                                                       Wo, Wf1, Wf2, emb, Wq, Wk, Wv);
    zero_kernel<<<(N_NODES * FD / 4 + 255) / 256, 256>>>((float4*)pagg, N_NODES * FD / 4);
    embed_all_kernel<<<(N16 + E16 + 255) / 256, 256>>>(node_tokens);

    // 3. GNN: msg GEMM with fused relu + scatter-add into g_agg (no g_msg roundtrip)
    launch_gemm(3, pe, pwmsg, nullptr, N_EDGES, FD, FD, nullptr, px, src, dst, FD, pagg);
    launch_gemm(2, px, pwnode, ph, N_NODES, FD, FD, pagg, nullptr, nullptr, nullptr, FD);
    edge_gather_kernel<<<(N_EDGES * FD / 8 + 255) / 256, 256>>>(src, dst);

    // 4. lc1
    launch_gemm(1, peh, plc1w, pzg, ROWS, DG, D_GNN, lc1_b);

    // 5. transformer
    launch_gemm(0, pzg, pwqkv, pqkv, ROWS, 3 * DG, DG);
    attention_kernel<<<N_EDGES, 256>>>();
    launch_gemm(4, pao, pwo, px1, ROWS, DG, DG, nullptr, pzg, nullptr, nullptr, DG);
    launch_gemm(5, px1, pwf1, pffn, ROWS, 4 * DG, DG);
    launch_gemm(4, pffn, pwf2, px2, ROWS, DG, 4 * DG, nullptr, px1, nullptr, nullptr, DG);

    // 6. fused LM head
    {
        static bool lm_attr = false;
        if (!lm_attr) {
            cudaFuncSetAttribute(lm_fused, cudaFuncAttributeMaxDynamicSharedMemorySize,
                                 LM_SMEM_TOT);
            lm_attr = true;
        }
        lm_fused<<<ROWS / 64, 256, LM_SMEM_TOT>>>(probs, lc2_b);
    }
}

// round 14
// speedup vs baseline: 1.1049x; 1.0049x over previous
#include <cuda_runtime.h>
#include <cuda_bf16.h>
#include <math.h>
#include <stdint.h>

// ---------------- problem constants ----------------
#define VOCAB   10000
#define D_GNN   64
#define L_TOK   8
#define DG      256
#define NH      4
#define HD      64
#define N_NODES 8192
#define N_EDGES 2048
#define FD      512
#define ROWS    16384

typedef __nv_bfloat16 bf16;

// ---------------- scratch (static device memory) ----------------
__device__ bf16  g_x   [N_NODES * FD];
__device__ bf16  g_e   [N_EDGES * FD];
__device__ float g_agg [N_NODES * FD];
__device__ bf16  g_h   [N_NODES * FD];
__device__ bf16  g_zg  [ROWS * DG];
__device__ bf16  g_qkv [ROWS * 3 * DG];
__device__ bf16  g_ao  [ROWS * DG];
__device__ bf16  g_x1  [ROWS * DG];
__device__ bf16  g_ffn [ROWS * 4 * DG];
__device__ bf16  g_x2  [ROWS * DG];
__device__ bf16  g_wmsg [FD * FD];
__device__ bf16  g_wnode[FD * FD];
__device__ bf16  g_lc1w [D_GNN * DG];
__device__ bf16  g_lc2w [DG * D_GNN];
__device__ bf16  g_wo   [DG * DG];
__device__ bf16  g_wf1  [DG * 4 * DG];
__device__ bf16  g_wf2  [4 * DG * DG];
__device__ bf16  g_wqkv [DG * 3 * DG];
__device__ bf16  g_embf [VOCAB * D_GNN];
__device__ int   g_mask_mode;

// ---------------- mask dtype detection ----------------
__global__ void detect_mask_kernel(const int* __restrict__ mr) {
    __shared__ int notint, notflt;
    if (threadIdx.x == 0) { notint = 0; notflt = 0; }
    __syncthreads();
    int w = mr[threadIdx.x];
    if (w != 0 && w != 1)          atomicExch(&notint, 1);
    if (w != 0 && w != 0x3F800000) atomicExch(&notflt, 1);
    __syncthreads();
    if (threadIdx.x == 0)
        g_mask_mode = notint ? (notflt ? 2 : 1) : 0;
}

// ---------------- merged prep ----------------
#define SZ_WMSG  (FD*FD)
#define SZ_WNODE (FD*FD)
#define SZ_LC1   (D_GNN*DG)
#define SZ_LC2   (DG*D_GNN)
#define SZ_WO    (DG*DG)
#define SZ_WF1   (DG*4*DG)
#define SZ_WF2   (4*DG*DG)
#define CW_TOTAL (SZ_WMSG+SZ_WNODE+SZ_LC1+SZ_LC2+SZ_WO+SZ_WF1+SZ_WF2)
#define PREP_TOTAL (CW_TOTAL + VOCAB*D_GNN + DG*DG)

__global__ void prep_all_kernel(const float* Wmsg, const float* Wnode,
                                const float* lc1w, const float* lc2w,
                                const float* Wo, const float* Wf1, const float* Wf2,
                                const float* emb, const float* Wq, const float* Wk,
                                const float* Wv) {
    int i = blockIdx.x * blockDim.x + threadIdx.x;
    if (i >= PREP_TOTAL) return;
    int j = i;
    if (j < SZ_WMSG)  { g_wmsg[j]  = __float2bfloat16_rn(Wmsg[j]);  return; } j -= SZ_WMSG;
    if (j < SZ_WNODE) { g_wnode[j] = __float2bfloat16_rn(Wnode[j]); return; } j -= SZ_WNODE;
    if (j < SZ_LC1)   { g_lc1w[j]  = __float2bfloat16_rn(lc1w[j]);  return; } j -= SZ_LC1;
    if (j < SZ_LC2)   { g_lc2w[j]  = __float2bfloat16_rn(lc2w[j]);  return; } j -= SZ_LC2;
    if (j < SZ_WO)    { g_wo[j]    = __float2bfloat16_rn(Wo[j]);    return; } j -= SZ_WO;
    if (j < SZ_WF1)   { g_wf1[j]   = __float2bfloat16_rn(Wf1[j]);   return; } j -= SZ_WF1;
    if (j < SZ_WF2)   { g_wf2[j]   = __float2bfloat16_rn(Wf2[j]);   return; } j -= SZ_WF2;
    if (j < VOCAB*D_GNN) { g_embf[j] = __float2bfloat16_rn(emb[j]); return; } j -= VOCAB*D_GNN;
    int k = j >> 8, n = j & 255;
    g_wqkv[k * 768 + n]       = __float2bfloat16_rn(Wq[j]);
    g_wqkv[k * 768 + 256 + n] = __float2bfloat16_rn(Wk[j]);
    g_wqkv[k * 768 + 512 + n] = __float2bfloat16_rn(Wv[j]);
}

// merged: node embed + edge embed with inline masking + labels
#define N16 (N_NODES * FD / 8)
#define E16 (N_EDGES * FD / 8)
__global__ void embed_all_kernel(const int* __restrict__ ntok, const int* __restrict__ etok,
                                 const void* __restrict__ maskraw, float* labels_out) {
    int i = blockIdx.x * blockDim.x + threadIdx.x;
    if (i >= N16 + E16) return;
    const uint4* tab = (const uint4*)g_embf;
    if (i < N16) {
        ((uint4*)g_x)[i] = tab[ntok[i >> 3] * 8 + (i & 7)];
    } else {
        int j = i - N16;
        int ti = j >> 3;            // token row 0..16383
        int e  = ti >> 3;           // edge
        int t = etok[ti];
        bool mr;
        int mode = g_mask_mode;
        if (mode == 0)      mr = ((const int*)maskraw)[e] != 0;
        else if (mode == 1) mr = ((const float*)maskraw)[e] != 0.0f;
        else                mr = ((const unsigned char*)maskraw)[e] != 0;
        bool msk = mr && (t >= 4);
        int tok = msk ? 4 : t;
        ((uint4*)g_e)[j] = tab[tok * 8 + (j & 7)];
        if ((j & 7) == 0 && labels_out)
            labels_out[ti] = msk ? (float)t : -100.0f;
    }
}

// ================= common helpers =================
__device__ __forceinline__ void cp_async16(uint32_t dst, const void* src, bool pred) {
    int sz = pred ? 16 : 0;
    asm volatile("cp.async.cg.shared.global [%0], [%1], 16, %2;\n"
                 :: "r"(dst), "l"(src), "r"(sz));
}
__device__ __forceinline__ void cp_commit() { asm volatile("cp.async.commit_group;\n"); }
__device__ __forceinline__ void cp_wait0()  { asm volatile("cp.async.wait_group 0;\n"); }
__device__ __forceinline__ void cp_wait1()  { asm volatile("cp.async.wait_group 1;\n"); }

__device__ __forceinline__ void mma_bf16(float c[4], const uint32_t a[4], const uint32_t b[2]) {
    asm volatile(
        "mma.sync.aligned.m16n8k16.row.col.f32.bf16.bf16.f32 "
        "{%0,%1,%2,%3}, {%4,%5,%6,%7}, {%8,%9}, {%0,%1,%2,%3};"
        : "+f"(c[0]), "+f"(c[1]), "+f"(c[2]), "+f"(c[3])
        : "r"(a[0]), "r"(a[1]), "r"(a[2]), "r"(a[3]), "r"(b[0]), "r"(b[1]));
}

__device__ __forceinline__ void ldsm_x4(uint32_t& r0, uint32_t& r1, uint32_t& r2, uint32_t& r3,
                                        uint32_t addr) {
    asm volatile("ldmatrix.sync.aligned.m8n8.x4.shared.b16 {%0,%1,%2,%3}, [%4];"
                 : "=r"(r0), "=r"(r1), "=r"(r2), "=r"(r3) : "r"(addr));
}
__device__ __forceinline__ void ldsm_x4_t(uint32_t& r0, uint32_t& r1, uint32_t& r2, uint32_t& r3,
                                          uint32_t addr) {
    asm volatile("ldmatrix.sync.aligned.m8n8.x4.trans.shared.b16 {%0,%1,%2,%3}, [%4];"
                 : "=r"(r0), "=r"(r1), "=r"(r2), "=r"(r3) : "r"(addr));
}

__device__ __forceinline__ uint4 add_pack8(uint4 ra, uint4 rb) {
    const __nv_bfloat162* ha = (const __nv_bfloat162*)&ra;
    const __nv_bfloat162* hb = (const __nv_bfloat162*)&rb;
    uint4 out;
    __nv_bfloat162* ho = (__nv_bfloat162*)&out;
    #pragma unroll
    for (int j = 0; j < 4; j++) {
        ho[j].x = __float2bfloat16_rn(__bfloat162float(ha[j].x) + __bfloat162float(hb[j].x));
        ho[j].y = __float2bfloat16_rn(__bfloat162float(ha[j].y) + __bfloat162float(hb[j].y));
    }
    return out;
}

// ================= mma.sync bf16 GEMM (mid-network), TBK=64 =================
// EPI: 0 plain | 1 +biasf[n] | 2 relu(+extraf[m*ld+n]) |
//      3 relu(c + extrab[gidx[m]*ld+n]) -> atomicAdd(aggout[gidx2[m]*ld+n])  [no C write]
//      4 +extrab[m*ld+n] | 5 gelu
// GA=1: A row r gathered as g_h[gidx[r>>3]] + g_h[gidx2[r>>3]] slice (r&7)*64 (K must be 64)

#define TBM 128
#define TBN 128
#define TBK 64
#define ASTRH 72
#define BSTRH 136
#define NSTAGE 3
#define A_STAGE_H (TBM * ASTRH)
#define B_STAGE_H (TBK * BSTRH)
#define GEMM_SMEM_BYTES (NSTAGE * (A_STAGE_H + B_STAGE_H) * 2)

template<int EPI, int GA>
__global__ void __launch_bounds__(256)
tmma_k(const bf16* __restrict__ A, const bf16* __restrict__ B, void* __restrict__ Cv,
       int M, int N, int K,
       const float* __restrict__ extraf, const bf16* __restrict__ extrab,
       const int* __restrict__ gidx, const int* __restrict__ gidx2, int ldex,
       float* __restrict__ aggout) {
    extern __shared__ bf16 smem[];
    bf16* Asm = smem;
    bf16* Bsm = smem + NSTAGE * A_STAGE_H;

    uint32_t aU = (uint32_t)__cvta_generic_to_shared(Asm);
    uint32_t bU = (uint32_t)__cvta_generic_to_shared(Bsm);

    int tid  = threadIdx.x;
    int lane = tid & 31;
    int warp = tid >> 5;
    int wm = warp & 1;
    int wn = warp >> 1;
    int g   = lane >> 2;
    int tig = lane & 3;
    int m0 = blockIdx.y * TBM;
    int n0 = blockIdx.x * TBN;

    float acc[4][4][4] = {};

    auto issue_load = [&](int s, int k0) {
        #pragma unroll
        for (int i = 0; i < 4; i++) {
            int id = tid + i * 256;
            int ar = id >> 3, ak = (id & 7) << 3;
            if (GA) {
                int r = m0 + ar;
                int e = r >> 3, l = r & 7;
                const bf16* hs = g_h + (size_t)gidx[e]  * FD + l * 64 + ak;
                const bf16* hd = g_h + (size_t)gidx2[e] * FD + l * 64 + ak;
                uint4 v = add_pack8(*(const uint4*)hs, *(const uint4*)hd);
                *(uint4*)&Asm[s * A_STAGE_H + ar * ASTRH + ak] = v;
            } else {
                uint32_t da = aU + (s * A_STAGE_H + ar * ASTRH + ak) * 2;
                cp_async16(da, A + (size_t)(m0 + ar) * K + k0 + ak, true);
            }
            int br = id >> 4, bn = (id & 15) << 3;
            int gn = n0 + bn;
            uint32_t db = bU + (s * B_STAGE_H + br * BSTRH + bn) * 2;
            cp_async16(db, B + (size_t)(k0 + br) * N + gn, gn + 8 <= N);
        }
    };

    int niter = K / TBK;
    issue_load(0, 0);
    cp_commit();
    if (niter > 1) { issue_load(1, TBK); cp_commit(); }

    for (int it = 0; it < niter; it++) {
        if (it >= niter - 2) cp_wait0(); else cp_wait1();
        __syncthreads();
        if (it + 2 < niter) {
            issue_load((it + 2) % NSTAGE, (it + 2) * TBK);
            cp_commit();
        }
        int s = it % NSTAGE;
        uint32_t aB = aU + s * A_STAGE_H * 2;
        uint32_t bB = bU + s * B_STAGE_H * 2;
        #pragma unroll
        for (int ks = 0; ks < TBK; ks += 16) {
            uint32_t af[4][4], bfr[4][2];
            #pragma unroll
            for (int mt = 0; mt < 4; mt++) {
                int row = wm * 64 + mt * 16 + (lane & 15);
                uint32_t ad = aB + (row * ASTRH + ks + ((lane >> 4) << 3)) * 2;
                ldsm_x4(af[mt][0], af[mt][1], af[mt][2], af[mt][3], ad);
            }
            #pragma unroll
            for (int bp = 0; bp < 2; bp++) {
                int krow = ks + (lane & 15);
                int ncol = wn * 32 + bp * 16 + ((lane >> 4) << 3);
                uint32_t bd = bB + (krow * BSTRH + ncol) * 2;
                ldsm_x4_t(bfr[2*bp][0], bfr[2*bp][1], bfr[2*bp+1][0], bfr[2*bp+1][1], bd);
            }
            #pragma unroll
            for (int mt = 0; mt < 4; mt++)
                #pragma unroll
                for (int nt = 0; nt < 4; nt++)
                    mma_bf16(acc[mt][nt], af[mt], bfr[nt]);
        }
    }

    bf16* Cb = (bf16*)Cv;

    #pragma unroll
    for (int mt = 0; mt < 4; mt++) {
        #pragma unroll
        for (int half = 0; half < 2; half++) {
            int rib = wm * 64 + mt * 16 + half * 8 + g;
            int r = m0 + rib;
            int ebase = 0, abase = 0;
            if (EPI == 2 || EPI == 4) ebase = r * ldex;
            if (EPI == 3) { ebase = gidx[r] * ldex; abase = gidx2[r] * ldex; }

            #pragma unroll
            for (int nt = 0; nt < 4; nt++) {
                int n = n0 + wn * 32 + nt * 8 + 2 * tig;
                float c0 = acc[mt][nt][half * 2 + 0];
                float c1 = acc[mt][nt][half * 2 + 1];
                if (EPI == 1) { c0 += extraf[n]; c1 += extraf[n + 1]; }
                else if (EPI == 2) {
                    c0 = fmaxf(c0 + extraf[ebase + n],     0.0f);
                    c1 = fmaxf(c1 + extraf[ebase + n + 1], 0.0f);
                } else if (EPI == 3) {
                    c0 = fmaxf(c0 + __bfloat162float(extrab[ebase + n]),     0.0f);
                    c1 = fmaxf(c1 + __bfloat162float(extrab[ebase + n + 1]), 0.0f);
                    atomicAdd(&aggout[abase + n],     c0);
                    atomicAdd(&aggout[abase + n + 1], c1);
                    continue;
                } else if (EPI == 4) {
                    c0 += __bfloat162float(extrab[ebase + n]);
                    c1 += __bfloat162float(extrab[ebase + n + 1]);
                } else if (EPI == 5) {
                    float x = c0;
                    c0 = 0.5f * x * (1.0f + tanhf(0.7978845608028654f * (x + 0.044715f * x * x * x)));
                    x = c1;
                    c1 = 0.5f * x * (1.0f + tanhf(0.7978845608028654f * (x + 0.044715f * x * x * x)));
                }
                if (n + 1 < N) {
                    __nv_bfloat162 p;
                    p.x = __float2bfloat16_rn(c0);
                    p.y = __float2bfloat16_rn(c1);
                    *(__nv_bfloat162*)&Cb[(size_t)r * N + n] = p;
                }
            }
        }
    }
}

// ================= fused persistent LM head, M=64 rows/CTA (R12/13 proven) =================
#define LMSTR    144
#define LM_A_B   (64 * LMSTR)
#define LM_BSTG  (128 * LMSTR)
#define LM_B_OFF LM_A_B
#define LM_NTILE 79
#define LM_X2_OFF  LM_A_B
#define LM_W2_OFF  (LM_A_B + 64 * 528)
#define LM_STAT_OFF (LM_W2_OFF + 256 * 144)
#define LM_SMEM_TOT (LM_STAT_OFF + 64 * 4 * 8 + 64 * 8)

__global__ void __launch_bounds__(256, 2)
lm_fused(float* __restrict__ probs, const float* __restrict__ lc2b) {
    extern __shared__ char smc[];
    uint32_t aU = (uint32_t)__cvta_generic_to_shared(smc);
    uint32_t bU = aU + LM_B_OFF;
    float2* spart = (float2*)(smc + LM_STAT_OFF);
    float2* sstat = spart + 64 * 4;

    int tid = threadIdx.x;
    int lane = tid & 31, warp = tid >> 5;
    int wm = warp & 1, wn = warp >> 1;
    int g = lane >> 2, tig = lane & 3;
    int m0 = blockIdx.x * 64;

    // ---- preamble: y[64,64] = x2[64,256] @ lc2w + b -> A region ----
    {
        uint32_t xU = aU + LM_X2_OFF;
        uint32_t wU = aU + LM_W2_OFF;
        const char* X2b = (const char*)g_x2;
        #pragma unroll
        for (int i = 0; i < 8; i++) {
            int id = tid + i * 256;
            int row = id >> 5, c = (id & 31) << 4;
            cp_async16(xU + row * 528 + c, X2b + (size_t)(m0 + row) * 512 + c, true);
        }
        const char* W2b = (const char*)g_lc2w;
        #pragma unroll
        for (int i = 0; i < 8; i++) {
            int id = tid + i * 256;
            int row = id >> 3, c = (id & 7) << 4;
            cp_async16(wU + row * 144 + c, W2b + (size_t)row * 128 + c, true);
        }
        cp_commit(); cp_wait0();
        __syncthreads();

        int pw_r = warp & 3;
        int pw_c = warp >> 2;
        float yacc[4][4] = {};
        #pragma unroll
        for (int ks = 0; ks < 16; ks++) {
            uint32_t axf[4];
            uint32_t ad = xU + (pw_r * 16 + (lane & 15)) * 528
                        + (ks * 16 + ((lane >> 4) << 3)) * 2;
            ldsm_x4(axf[0], axf[1], axf[2], axf[3], ad);
            uint32_t bw[4][2];
            #pragma unroll
            for (int p = 0; p < 2; p++) {
                uint32_t bd = wU + (ks * 16 + (lane & 15)) * 144
                            + (pw_c * 32 + p * 16 + ((lane >> 4) << 3)) * 2;
                ldsm_x4_t(bw[2*p][0], bw[2*p][1], bw[2*p+1][0], bw[2*p+1][1], bd);
            }
            #pragma unroll
            for (int nt = 0; nt < 4; nt++)
                mma_bf16(yacc[nt], axf, bw[nt]);
        }
        __syncthreads();

        #pragma unroll
        for (int half = 0; half < 2; half++) {
            int rib = pw_r * 16 + half * 8 + g;
            #pragma unroll
            for (int nt = 0; nt < 4; nt++) {
                int col = pw_c * 32 + nt * 8 + 2 * tig;
                float v0 = yacc[nt][half * 2 + 0] + lc2b[col];
                float v1 = yacc[nt][half * 2 + 1] + lc2b[col + 1];
                __nv_bfloat162 p;
                p.x = __float2bfloat16_rn(v0);
                p.y = __float2bfloat16_rn(v1);
                *(__nv_bfloat162*)(smc + rib * LMSTR + col * 2) = p;
            }
        }
        __syncthreads();
    }

    auto issue_B = [&](int stage, int t) {
        const char* Bb = (const char*)g_embf;
        #pragma unroll
        for (int i = 0; i < 4; i++) {
            int id = tid + i * 256;
            int row = id >> 3, c = (id & 7) << 4;
            int v = t * 128 + row;
            cp_async16(bU + stage * LM_BSTG + row * LMSTR + c,
                       Bb + (size_t)v * 128 + c, v < VOCAB);
        }
        cp_commit();
    };

    issue_B(0, 0);
    issue_B(1, 1);

    uint32_t af[2][4][4];
    #pragma unroll
    for (int mt = 0; mt < 2; mt++)
        #pragma unroll
        for (int ks = 0; ks < 4; ks++) {
            uint32_t ad = aU + (wm * 32 + mt * 16 + (lane & 15)) * LMSTR
                        + ks * 32 + ((lane >> 4) << 4);
            ldsm_x4(af[mt][ks][0], af[mt][ks][1], af[mt][ks][2], af[mt][ks][3], ad);
        }

    float rm[4], rs[4];
    #pragma unroll
    for (int s = 0; s < 4; s++) { rm[s] = -1e30f; rs[s] = 0.0f; }

    int brow = (lane & 7) + ((lane >> 4) << 3);
    int bcol16 = ((lane >> 3) & 1) << 4;

    // ======== PASS 1: stats ========
    for (int t = 0; t < LM_NTILE; t++) {
        if (t == LM_NTILE - 1) cp_wait0(); else cp_wait1();
        __syncthreads();
        if (t + 2 < LM_NTILE) issue_B((t + 2) % 3, t + 2);

        uint32_t bB = bU + (t % 3) * LM_BSTG;
        float acc[2][4][4] = {};
        #pragma unroll
        for (int ks = 0; ks < 4; ks++) {
            uint32_t bfr[4][2];
            #pragma unroll
            for (int p = 0; p < 2; p++) {
                uint32_t bd = bB + (wn * 32 + p * 16 + brow) * LMSTR + ks * 32 + bcol16;
                ldsm_x4(bfr[2*p][0], bfr[2*p][1], bfr[2*p+1][0], bfr[2*p+1][1], bd);
            }
            #pragma unroll
            for (int mt = 0; mt < 2; mt++)
                #pragma unroll
                for (int nt = 0; nt < 4; nt++)
                    mma_bf16(acc[mt][nt], af[mt][ks], bfr[nt]);
        }

        int nb0 = t * 128 + wn * 32 + 2 * tig;
        #pragma unroll
        for (int mt = 0; mt < 2; mt++)
            #pragma unroll
            for (int half = 0; half < 2; half++) {
                int slot = mt * 2 + half;
                float v[8];
                float bm = -1e30f;
                #pragma unroll
                for (int nt = 0; nt < 4; nt++)
                    #pragma unroll
                    for (int j = 0; j < 2; j++) {
                        int n = nb0 + nt * 8 + j;
                        float x = (n < VOCAB) ? acc[mt][nt][half * 2 + j] : -1e30f;
                        v[nt * 2 + j] = x;
                        bm = fmaxf(bm, x);
                    }
                float nm = fmaxf(rm[slot], bm);
                float add = 0.0f;
                #pragma unroll
                for (int j = 0; j < 8; j++) add += __expf(v[j] - nm);
                rs[slot] = rs[slot] * __expf(rm[slot] - nm) + add;
                rm[slot] = nm;
            }
    }

    // ---- reduce stats ----
    #pragma unroll
    for (int slot = 0; slot < 4; slot++) {
        float m = rm[slot], s = rs[slot];
        #pragma unroll
        for (int off = 1; off <= 2; off <<= 1) {
            float om = __shfl_xor_sync(0xffffffffu, m, off);
            float os = __shfl_xor_sync(0xffffffffu, s, off);
            float nm = fmaxf(m, om);
            s = s * __expf(m - nm) + os * __expf(om - nm);
            m = nm;
        }
        int mt = slot >> 1, half = slot & 1;
        int rib = wm * 32 + mt * 16 + half * 8 + g;
        if (tig == 0) spart[rib * 4 + wn] = make_float2(m, s);
    }
    __syncthreads();
    if (tid < 64) {
        float m = -1e30f, s = 0.0f;
        #pragma unroll
        for (int w = 0; w < 4; w++) {
            float2 p = spart[tid * 4 + w];
            float nm = fmaxf(m, p.x);
            s = s * __expf(m - nm) + p.y * __expf(p.x - nm);
            m = nm;
        }
        sstat[tid] = make_float2(m, 1.0f / s);
    }
    __syncthreads();

    float stm[4], sti[4];
    #pragma unroll
    for (int slot = 0; slot < 4; slot++) {
        int mt = slot >> 1, half = slot & 1;
        int rib = wm * 32 + mt * 16 + half * 8 + g;
        float2 st = sstat[rib];
        stm[slot] = st.x; sti[slot] = st.y;
    }

    // ======== PASS 2: recompute + write probs ========
    issue_B(0, 0);
    issue_B(1, 1);
    for (int t = 0; t < LM_NTILE; t++) {
        if (t == LM_NTILE - 1) cp_wait0(); else cp_wait1();
        __syncthreads();
        if (t + 2 < LM_NTILE) issue_B((t + 2) % 3, t + 2);

        uint32_t bB = bU + (t % 3) * LM_BSTG;
        float acc[2][4][4] = {};
        #pragma unroll
        for (int ks = 0; ks < 4; ks++) {
            uint32_t bfr[4][2];
            #pragma unroll
            for (int p = 0; p < 2; p++) {
                uint32_t bd = bB + (wn * 32 + p * 16 + brow) * LMSTR + ks * 32 + bcol16;
                ldsm_x4(bfr[2*p][0], bfr[2*p][1], bfr[2*p+1][0], bfr[2*p+1][1], bd);
            }
            #pragma unroll
            for (int mt = 0; mt < 2; mt++)
                #pragma unroll
                for (int nt = 0; nt < 4; nt++)
                    mma_bf16(acc[mt][nt], af[mt][ks], bfr[nt]);
        }

        int nb0 = t * 128 + wn * 32 + 2 * tig;
        #pragma unroll
        for (int mt = 0; mt < 2; mt++)
            #pragma unroll
            for (int half = 0; half < 2; half++) {
                int slot = mt * 2 + half;
                int rib = wm * 32 + mt * 16 + half * 8 + g;
                size_t rowoff = (size_t)(m0 + rib) * VOCAB;
                float m = stm[slot], inv = sti[slot];
                #pragma unroll
                for (int nt = 0; nt < 4; nt++) {
                    int n = nb0 + nt * 8;
                    if (n < VOCAB) {
                        float p0 = __expf(acc[mt][nt][half * 2 + 0] - m) * inv;
                        float p1 = __expf(acc[mt][nt][half * 2 + 1] - m) * inv;
                        __stcs((float2*)&probs[rowoff + n], make_float2(p0, p1));
                    }
                }
            }
    }
}

// ---------------- attention ----------------
__global__ void __launch_bounds__(256) attention_kernel() {
    __shared__ float qs[8][DG], ks[8][DG], vs[8][DG];
    int b = blockIdx.x;
    int tid = threadIdx.x;
    for (int i = tid; i < 8 * DG; i += 256) {
        int s = i >> 8, c = i & 255;
        size_t off = (size_t)(b * 8 + s) * 768 + c;
        qs[s][c] = __bfloat162float(g_qkv[off]);
        ks[s][c] = __bfloat162float(g_qkv[off + 256]);
        vs[s][c] = __bfloat162float(g_qkv[off + 512]);
    }
    __syncthreads();

    int h  = tid >> 6;
    int qx = (tid >> 3) & 7;
    int kx = tid & 7;
    float att = 0.0f;
    #pragma unroll
    for (int d = 0; d < HD; d++)
        att += qs[qx][h * HD + d] * ks[kx][h * HD + d];
    att *= 0.125f;

    float mx = att;
    mx = fmaxf(mx, __shfl_xor_sync(0xffffffffu, mx, 4));
    mx = fmaxf(mx, __shfl_xor_sync(0xffffffffu, mx, 2));
    mx = fmaxf(mx, __shfl_xor_sync(0xffffffffu, mx, 1));
    float ex = expf(att - mx);
    float sm = ex;
    sm += __shfl_xor_sync(0xffffffffu, sm, 4);
    sm += __shfl_xor_sync(0xffffffffu, sm, 2);
    sm += __shfl_xor_sync(0xffffffffu, sm, 1);
    float a = ex / sm;

    int lane = tid & 31;
    int base = lane & ~7;
    float a_all[8];
    #pragma unroll
    for (int kk = 0; kk < 8; kk++)
        a_all[kk] = __shfl_sync(0xffffffffu, a, base + kk);

    #pragma unroll
    for (int t2 = 0; t2 < 8; t2++) {
        int d = kx * 8 + t2;
        float o = 0.0f;
        #pragma unroll
        for (int kk = 0; kk < 8; kk++)
            o += a_all[kk] * vs[kk][h * HD + d];
        g_ao[(size_t)(b * 8 + qx) * DG + h * HD + d] = __float2bfloat16_rn(o);
    }
}

// ---------------- host launcher ----------------
template<int EPI, int GA>
static void launch_one(const bf16* A, const bf16* B, void* C, int M, int N, int K,
                       const float* extraf, const bf16* extrab,
                       const int* gidx, const int* gidx2, int ldex, float* aggout) {
    static bool attr_done = false;
    if (!attr_done) {
        cudaFuncSetAttribute((tmma_k<EPI, GA>), cudaFuncAttributeMaxDynamicSharedMemorySize,
                             GEMM_SMEM_BYTES);
        attr_done = true;
    }
    dim3 grid((N + TBN - 1) / TBN, M / TBM), blk(256);
    tmma_k<EPI, GA><<<grid, blk, GEMM_SMEM_BYTES>>>(A, B, C, M, N, K, extraf, extrab,
                                                    gidx, gidx2, ldex, aggout);
}

template <typename T>
static T* sym_addr(const void* sym) {
    void* p = nullptr;
    cudaGetSymbolAddress(&p, sym);
    return (T*)p;
}

extern "C" void kernel_launch(void* const* d_in, const int* in_sizes, int n_in,
                              void* d_out, int out_size) {
    const int*   node_tokens = (const int*)d_in[0];
    const int*   edge_tokens = (const int*)d_in[1];
    const int*   edge_index  = (const int*)d_in[2];
    const void*  mask_rows   = d_in[3];
    const float* emb    = (const float*)d_in[4];
    const float* W_msg  = (const float*)d_in[5];
    const float* W_node = (const float*)d_in[6];
    const float* lc1_w  = (const float*)d_in[7];
    const float* lc1_b  = (const float*)d_in[8];
    const float* lc2_w  = (const float*)d_in[9];
    const float* lc2_b  = (const float*)d_in[10];
    const float* Wq  = (const float*)d_in[11];
    const float* Wk  = (const float*)d_in[12];
    const float* Wv  = (const float*)d_in[13];
    const float* Wo  = (const float*)d_in[14];
    const float* Wf1 = (const float*)d_in[15];
    const float* Wf2 = (const float*)d_in[16];

    float* out = (float*)d_out;
    bool concat = (out_size != ROWS * VOCAB);
    float* labels_out = concat ? out : nullptr;
    float* probs      = concat ? out + ROWS : out;

    const int* src = edge_index;
    const int* dst = edge_index + N_EDGES;

    bf16* px   = sym_addr<bf16>(g_x);
    bf16* pe   = sym_addr<bf16>(g_e);
    float* pagg= sym_addr<float>(g_agg);
    bf16* ph   = sym_addr<bf16>(g_h);
    bf16* pzg  = sym_addr<bf16>(g_zg);
    bf16* pqkv = sym_addr<bf16>(g_qkv);
    bf16* pao  = sym_addr<bf16>(g_ao);
    bf16* px1  = sym_addr<bf16>(g_x1);
    bf16* pffn = sym_addr<bf16>(g_ffn);
    bf16* px2  = sym_addr<bf16>(g_x2);
    bf16* pwmsg = sym_addr<bf16>(g_wmsg);
    bf16* pwnode= sym_addr<bf16>(g_wnode);
    bf16* plc1w = sym_addr<bf16>(g_lc1w);
    bf16* pwo   = sym_addr<bf16>(g_wo);
    bf16* pwf1  = sym_addr<bf16>(g_wf1);
    bf16* pwf2  = sym_addr<bf16>(g_wf2);
    bf16* pwqkv = sym_addr<bf16>(g_wqkv);

    // 1. mask dtype detect + merged prep + agg clear
    detect_mask_kernel<<<1, 512>>>((const int*)mask_rows);
    prep_all_kernel<<<(PREP_TOTAL + 255) / 256, 256>>>(W_msg, W_node, lc1_w, lc2_w,
                                                       Wo, Wf1, Wf2, emb, Wq, Wk, Wv);
    cudaMemsetAsync(pagg, 0, (size_t)N_NODES * FD * sizeof(float));

    // 2. merged embeddings (node + masked edge + labels)
    embed_all_kernel<<<(N16 + E16 + 255) / 256, 256>>>(node_tokens, edge_tokens,
                                                       mask_rows, labels_out);

    // 3. GNN: msg GEMM (fused relu + scatter-add), node GEMM
    launch_one<3,0>(pe, pwmsg, nullptr, N_EDGES, FD, FD, nullptr, px, src, dst, FD, pagg);
    launch_one<2,0>(px, pwnode, ph, N_NODES, FD, FD, pagg, nullptr, nullptr, nullptr, FD, nullptr);

    // 4. lc1 with fused edge gather (A = h[src]+h[dst])
    launch_one<1,1>(nullptr, plc1w, pzg, ROWS, DG, D_GNN, lc1_b, nullptr, src, dst, 0, nullptr);

    // 5. transformer
    launch_one<0,0>(pzg, pwqkv, pqkv, ROWS, 3 * DG, DG, nullptr, nullptr, nullptr, nullptr, 0, nullptr);
    attention_kernel<<<N_EDGES, 256>>>();
    launch_one<4,0>(pao, pwo, px1, ROWS, DG, DG, nullptr, pzg, nullptr, nullptr, DG, nullptr);
    launch_one<5,0>(px1, pwf1, pffn, ROWS, 4 * DG, DG, nullptr, nullptr, nullptr, nullptr, 0, nullptr);
    launch_one<4,0>(pffn, pwf2, px2, ROWS, DG, 4 * DG, nullptr, px1, nullptr, nullptr, DG, nullptr);

    // 6. fused LM head
    {
        static bool lm_attr = false;
        if (!lm_attr) {
            cudaFuncSetAttribute(lm_fused, cudaFuncAttributeMaxDynamicSharedMemorySize,
                                 LM_SMEM_TOT);
            lm_attr = true;
        }
        lm_fused<<<ROWS / 64, 256, LM_SMEM_TOT>>>(probs, lc2_b);
    }
}

// round 15
// speedup vs baseline: 1.1140x; 1.0082x over previous
#include <cuda_runtime.h>
#include <cuda_bf16.h>
#include <math.h>
#include <stdint.h>

// ---------------- problem constants ----------------
#define VOCAB   10000
#define D_GNN   64
#define L_TOK   8
#define DG      256
#define NH      4
#define HD      64
#define N_NODES 8192
#define N_EDGES 2048
#define FD      512
#define ROWS    16384

typedef __nv_bfloat16 bf16;

// ---------------- scratch (static device memory) ----------------
__device__ bf16  g_x   [N_NODES * FD];
__device__ bf16  g_e   [N_EDGES * FD];
__device__ float g_agg [N_NODES * FD];
__device__ bf16  g_h   [N_NODES * FD];
__device__ bf16  g_zg  [ROWS * DG];
__device__ bf16  g_qkv [ROWS * 3 * DG];
__device__ bf16  g_ao  [ROWS * DG];
__device__ bf16  g_x1  [ROWS * DG];
__device__ bf16  g_ffn [ROWS * 4 * DG];
__device__ bf16  g_x2  [ROWS * DG];
__device__ bf16  g_wmsg [FD * FD];
__device__ bf16  g_wnode[FD * FD];
__device__ bf16  g_lc1w [D_GNN * DG];
__device__ bf16  g_lc2w [DG * D_GNN];
__device__ bf16  g_wo   [DG * DG];
__device__ bf16  g_wf1  [DG * 4 * DG];
__device__ bf16  g_wf2  [4 * DG * DG];
__device__ bf16  g_wqkv [DG * 3 * DG];
__device__ bf16  g_embf [VOCAB * D_GNN];
__device__ int   g_mask_mode;

// ---------------- mask dtype detection ----------------
__global__ void detect_mask_kernel(const int* __restrict__ mr) {
    __shared__ int notint, notflt;
    if (threadIdx.x == 0) { notint = 0; notflt = 0; }
    __syncthreads();
    int w = mr[threadIdx.x];
    if (w != 0 && w != 1)          atomicExch(&notint, 1);
    if (w != 0 && w != 0x3F800000) atomicExch(&notflt, 1);
    __syncthreads();
    if (threadIdx.x == 0)
        g_mask_mode = notint ? (notflt ? 2 : 1) : 0;
}

// ---------------- merged prep ----------------
#define SZ_WMSG  (FD*FD)
#define SZ_WNODE (FD*FD)
#define SZ_LC1   (D_GNN*DG)
#define SZ_LC2   (DG*D_GNN)
#define SZ_WO    (DG*DG)
#define SZ_WF1   (DG*4*DG)
#define SZ_WF2   (4*DG*DG)
#define CW_TOTAL (SZ_WMSG+SZ_WNODE+SZ_LC1+SZ_LC2+SZ_WO+SZ_WF1+SZ_WF2)
#define PREP_TOTAL (CW_TOTAL + VOCAB*D_GNN + DG*DG)

__global__ void prep_all_kernel(const float* Wmsg, const float* Wnode,
                                const float* lc1w, const float* lc2w,
                                const float* Wo, const float* Wf1, const float* Wf2,
                                const float* emb, const float* Wq, const float* Wk,
                                const float* Wv) {
    int i = blockIdx.x * blockDim.x + threadIdx.x;
    if (i >= PREP_TOTAL) return;
    int j = i;
    if (j < SZ_WMSG)  { g_wmsg[j]  = __float2bfloat16_rn(Wmsg[j]);  return; } j -= SZ_WMSG;
    if (j < SZ_WNODE) { g_wnode[j] = __float2bfloat16_rn(Wnode[j]); return; } j -= SZ_WNODE;
    if (j < SZ_LC1)   { g_lc1w[j]  = __float2bfloat16_rn(lc1w[j]);  return; } j -= SZ_LC1;
    if (j < SZ_LC2)   { g_lc2w[j]  = __float2bfloat16_rn(lc2w[j]);  return; } j -= SZ_LC2;
    if (j < SZ_WO)    { g_wo[j]    = __float2bfloat16_rn(Wo[j]);    return; } j -= SZ_WO;
    if (j < SZ_WF1)   { g_wf1[j]   = __float2bfloat16_rn(Wf1[j]);   return; } j -= SZ_WF1;
    if (j < SZ_WF2)   { g_wf2[j]   = __float2bfloat16_rn(Wf2[j]);   return; } j -= SZ_WF2;
    if (j < VOCAB*D_GNN) { g_embf[j] = __float2bfloat16_rn(emb[j]); return; } j -= VOCAB*D_GNN;
    int k = j >> 8, n = j & 255;
    g_wqkv[k * 768 + n]       = __float2bfloat16_rn(Wq[j]);
    g_wqkv[k * 768 + 256 + n] = __float2bfloat16_rn(Wk[j]);
    g_wqkv[k * 768 + 512 + n] = __float2bfloat16_rn(Wv[j]);
}

// merged: node embed + edge embed with inline masking + labels
#define N16 (N_NODES * FD / 8)
#define E16 (N_EDGES * FD / 8)
__global__ void embed_all_kernel(const int* __restrict__ ntok, const int* __restrict__ etok,
                                 const void* __restrict__ maskraw, float* labels_out) {
    int i = blockIdx.x * blockDim.x + threadIdx.x;
    if (i >= N16 + E16) return;
    const uint4* tab = (const uint4*)g_embf;
    if (i < N16) {
        ((uint4*)g_x)[i] = tab[ntok[i >> 3] * 8 + (i & 7)];
    } else {
        int j = i - N16;
        int ti = j >> 3;
        int e  = ti >> 3;
        int t = etok[ti];
        bool mr;
        int mode = g_mask_mode;
        if (mode == 0)      mr = ((const int*)maskraw)[e] != 0;
        else if (mode == 1) mr = ((const float*)maskraw)[e] != 0.0f;
        else                mr = ((const unsigned char*)maskraw)[e] != 0;
        bool msk = mr && (t >= 4);
        int tok = msk ? 4 : t;
        ((uint4*)g_e)[j] = tab[tok * 8 + (j & 7)];
        if ((j & 7) == 0 && labels_out)
            labels_out[ti] = msk ? (float)t : -100.0f;
    }
}

// ================= common helpers =================
__device__ __forceinline__ void cp_async16(uint32_t dst, const void* src, bool pred) {
    int sz = pred ? 16 : 0;
    asm volatile("cp.async.cg.shared.global [%0], [%1], 16, %2;\n"
                 :: "r"(dst), "l"(src), "r"(sz));
}
__device__ __forceinline__ void cp_commit() { asm volatile("cp.async.commit_group;\n"); }
__device__ __forceinline__ void cp_wait0()  { asm volatile("cp.async.wait_group 0;\n"); }
__device__ __forceinline__ void cp_wait1()  { asm volatile("cp.async.wait_group 1;\n"); }

__device__ __forceinline__ void mma_bf16(float c[4], const uint32_t a[4], const uint32_t b[2]) {
    asm volatile(
        "mma.sync.aligned.m16n8k16.row.col.f32.bf16.bf16.f32 "
        "{%0,%1,%2,%3}, {%4,%5,%6,%7}, {%8,%9}, {%0,%1,%2,%3};"
        : "+f"(c[0]), "+f"(c[1]), "+f"(c[2]), "+f"(c[3])
        : "r"(a[0]), "r"(a[1]), "r"(a[2]), "r"(a[3]), "r"(b[0]), "r"(b[1]));
}

__device__ __forceinline__ void ldsm_x4(uint32_t& r0, uint32_t& r1, uint32_t& r2, uint32_t& r3,
                                        uint32_t addr) {
    asm volatile("ldmatrix.sync.aligned.m8n8.x4.shared.b16 {%0,%1,%2,%3}, [%4];"
                 : "=r"(r0), "=r"(r1), "=r"(r2), "=r"(r3) : "r"(addr));
}
__device__ __forceinline__ void ldsm_x4_t(uint32_t& r0, uint32_t& r1, uint32_t& r2, uint32_t& r3,
                                          uint32_t addr) {
    asm volatile("ldmatrix.sync.aligned.m8n8.x4.trans.shared.b16 {%0,%1,%2,%3}, [%4];"
                 : "=r"(r0), "=r"(r1), "=r"(r2), "=r"(r3) : "r"(addr));
}

__device__ __forceinline__ uint4 add_pack8(uint4 ra, uint4 rb) {
    const __nv_bfloat162* ha = (const __nv_bfloat162*)&ra;
    const __nv_bfloat162* hb = (const __nv_bfloat162*)&rb;
    uint4 out;
    __nv_bfloat162* ho = (__nv_bfloat162*)&out;
    #pragma unroll
    for (int j = 0; j < 4; j++) {
        ho[j].x = __float2bfloat16_rn(__bfloat162float(ha[j].x) + __bfloat162float(hb[j].x));
        ho[j].y = __float2bfloat16_rn(__bfloat162float(ha[j].y) + __bfloat162float(hb[j].y));
    }
    return out;
}

// ================= mma.sync bf16 GEMM (mid-network), TBK=64, M-tile = NMT*32 =================
// EPI: 0 plain | 1 +biasf[n] | 2 relu(+extraf[m*ld+n]) |
//      3 relu(c + extrab[gidx[m]*ld+n]) -> atomicAdd(aggout[gidx2[m]*ld+n])  [no C write]
//      4 +extrab[m*ld+n] | 5 gelu
// GA=1: A row r = g_h[gidx[r>>3]] + g_h[gidx2[r>>3]] slice (r&7)*64 (K must be 64)

#define TBN 128
#define TBK 64
#define ASTRH 72
#define BSTRH 136
#define NSTAGE 3
#define A_STAGE_H (128 * ASTRH)
#define B_STAGE_H (TBK * BSTRH)
#define GEMM_SMEM_BYTES (NSTAGE * (A_STAGE_H + B_STAGE_H) * 2)

template<int EPI, int GA, int NMT>
__global__ void __launch_bounds__(256)
tmma_k(const bf16* __restrict__ A, const bf16* __restrict__ B, void* __restrict__ Cv,
       int M, int N, int K,
       const float* __restrict__ extraf, const bf16* __restrict__ extrab,
       const int* __restrict__ gidx, const int* __restrict__ gidx2, int ldex,
       float* __restrict__ aggout) {
    extern __shared__ bf16 smem[];
    bf16* Asm = smem;
    bf16* Bsm = smem + NSTAGE * A_STAGE_H;

    uint32_t aU = (uint32_t)__cvta_generic_to_shared(Asm);
    uint32_t bU = (uint32_t)__cvta_generic_to_shared(Bsm);

    const int TBM_L = NMT * 32;

    int tid  = threadIdx.x;
    int lane = tid & 31;
    int warp = tid >> 5;
    int wm = warp & 1;
    int wn = warp >> 1;
    int g   = lane >> 2;
    int tig = lane & 3;
    int m0 = blockIdx.y * TBM_L;
    int n0 = blockIdx.x * TBN;

    float acc[NMT][4][4] = {};

    auto issue_load = [&](int s, int k0) {
        #pragma unroll
        for (int i = 0; i < NMT; i++) {                 // A: TBM_L rows x 8 chunks
            int id = tid + i * 256;
            int ar = id >> 3, ak = (id & 7) << 3;
            if (GA) {
                int r = m0 + ar;
                int e = r >> 3, l = r & 7;
                const bf16* hs = g_h + (size_t)gidx[e]  * FD + l * 64 + ak;
                const bf16* hd = g_h + (size_t)gidx2[e] * FD + l * 64 + ak;
                uint4 v = add_pack8(*(const uint4*)hs, *(const uint4*)hd);
                *(uint4*)&Asm[s * A_STAGE_H + ar * ASTRH + ak] = v;
            } else {
                uint32_t da = aU + (s * A_STAGE_H + ar * ASTRH + ak) * 2;
                cp_async16(da, A + (size_t)(m0 + ar) * K + k0 + ak, true);
            }
        }
        #pragma unroll
        for (int i = 0; i < 4; i++) {                   // B: 64 rows x 16 chunks
            int id = tid + i * 256;
            int br = id >> 4, bn = (id & 15) << 3;
            int gn = n0 + bn;
            uint32_t db = bU + (s * B_STAGE_H + br * BSTRH + bn) * 2;
            cp_async16(db, B + (size_t)(k0 + br) * N + gn, gn + 8 <= N);
        }
    };

    int niter = K / TBK;
    issue_load(0, 0);
    cp_commit();
    if (niter > 1) { issue_load(1, TBK); cp_commit(); }

    for (int it = 0; it < niter; it++) {
        if (it >= niter - 2) cp_wait0(); else cp_wait1();
        __syncthreads();
        if (it + 2 < niter) {
            issue_load((it + 2) % NSTAGE, (it + 2) * TBK);
            cp_commit();
        }
        int s = it % NSTAGE;
        uint32_t aB = aU + s * A_STAGE_H * 2;
        uint32_t bB = bU + s * B_STAGE_H * 2;
        #pragma unroll
        for (int ks = 0; ks < TBK; ks += 16) {
            uint32_t af[NMT][4], bfr[4][2];
            #pragma unroll
            for (int mt = 0; mt < NMT; mt++) {
                int row = wm * (NMT * 16) + mt * 16 + (lane & 15);
                uint32_t ad = aB + (row * ASTRH + ks + ((lane >> 4) << 3)) * 2;
                ldsm_x4(af[mt][0], af[mt][1], af[mt][2], af[mt][3], ad);
            }
            #pragma unroll
            for (int bp = 0; bp < 2; bp++) {
                int krow = ks + (lane & 15);
                int ncol = wn * 32 + bp * 16 + ((lane >> 4) << 3);
                uint32_t bd = bB + (krow * BSTRH + ncol) * 2;
                ldsm_x4_t(bfr[2*bp][0], bfr[2*bp][1], bfr[2*bp+1][0], bfr[2*bp+1][1], bd);
            }
            #pragma unroll
            for (int mt = 0; mt < NMT; mt++)
                #pragma unroll
                for (int nt = 0; nt < 4; nt++)
                    mma_bf16(acc[mt][nt], af[mt], bfr[nt]);
        }
    }

    bf16* Cb = (bf16*)Cv;

    #pragma unroll
    for (int mt = 0; mt < NMT; mt++) {
        #pragma unroll
        for (int half = 0; half < 2; half++) {
            int rib = wm * (NMT * 16) + mt * 16 + half * 8 + g;
            int r = m0 + rib;
            int ebase = 0, abase = 0;
            if (EPI == 2 || EPI == 4) ebase = r * ldex;
            if (EPI == 3) { ebase = gidx[r] * ldex; abase = gidx2[r] * ldex; }

            #pragma unroll
            for (int nt = 0; nt < 4; nt++) {
                int n = n0 + wn * 32 + nt * 8 + 2 * tig;
                float c0 = acc[mt][nt][half * 2 + 0];
                float c1 = acc[mt][nt][half * 2 + 1];
                if (EPI == 1) { c0 += extraf[n]; c1 += extraf[n + 1]; }
                else if (EPI == 2) {
                    c0 = fmaxf(c0 + extraf[ebase + n],     0.0f);
                    c1 = fmaxf(c1 + extraf[ebase + n + 1], 0.0f);
                } else if (EPI == 3) {
                    c0 = fmaxf(c0 + __bfloat162float(extrab[ebase + n]),     0.0f);
                    c1 = fmaxf(c1 + __bfloat162float(extrab[ebase + n + 1]), 0.0f);
                    atomicAdd(&aggout[abase + n],     c0);
                    atomicAdd(&aggout[abase + n + 1], c1);
                    continue;
                } else if (EPI == 4) {
                    c0 += __bfloat162float(extrab[ebase + n]);
                    c1 += __bfloat162float(extrab[ebase + n + 1]);
                } else if (EPI == 5) {
                    float x = c0;
                    c0 = 0.5f * x * (1.0f + tanhf(0.7978845608028654f * (x + 0.044715f * x * x * x)));
                    x = c1;
                    c1 = 0.5f * x * (1.0f + tanhf(0.7978845608028654f * (x + 0.044715f * x * x * x)));
                }
                if (n + 1 < N) {
                    __nv_bfloat162 p;
                    p.x = __float2bfloat16_rn(c0);
                    p.y = __float2bfloat16_rn(c1);
                    *(__nv_bfloat162*)&Cb[(size_t)r * N + n] = p;
                }
            }
        }
    }
}

// ================= fused persistent LM head, M=64 rows/CTA =================
#define LMSTR    144
#define LM_A_B   (64 * LMSTR)
#define LM_BSTG  (128 * LMSTR)
#define LM_B_OFF LM_A_B
#define LM_NTILE 79
#define LM_X2_OFF  LM_A_B
#define LM_W2_OFF  (LM_A_B + 64 * 528)
#define LM_STAT_OFF (LM_W2_OFF + 256 * 144)
#define LM_SMEM_TOT (LM_STAT_OFF + 64 * 4 * 8 + 64 * 8)

__global__ void __launch_bounds__(256, 2)
lm_fused(float* __restrict__ probs, const float* __restrict__ lc2b) {
    extern __shared__ char smc[];
    uint32_t aU = (uint32_t)__cvta_generic_to_shared(smc);
    uint32_t bU = aU + LM_B_OFF;
    float2* spart = (float2*)(smc + LM_STAT_OFF);
    float2* sstat = spart + 64 * 4;

    int tid = threadIdx.x;
    int lane = tid & 31, warp = tid >> 5;
    int wm = warp & 1, wn = warp >> 1;
    int g = lane >> 2, tig = lane & 3;
    int m0 = blockIdx.x * 64;

    // ---- preamble: y[64,64] = x2[64,256] @ lc2w + b -> A region ----
    {
        uint32_t xU = aU + LM_X2_OFF;
        uint32_t wU = aU + LM_W2_OFF;
        const char* X2b = (const char*)g_x2;
        #pragma unroll
        for (int i = 0; i < 8; i++) {
            int id = tid + i * 256;
            int row = id >> 5, c = (id & 31) << 4;
            cp_async16(xU + row * 528 + c, X2b + (size_t)(m0 + row) * 512 + c, true);
        }
        const char* W2b = (const char*)g_lc2w;
        #pragma unroll
        for (int i = 0; i < 8; i++) {
            int id = tid + i * 256;
            int row = id >> 3, c = (id & 7) << 4;
            cp_async16(wU + row * 144 + c, W2b + (size_t)row * 128 + c, true);
        }
        cp_commit(); cp_wait0();
        __syncthreads();

        int pw_r = warp & 3;
        int pw_c = warp >> 2;
        float yacc[4][4] = {};
        #pragma unroll
        for (int ks = 0; ks < 16; ks++) {
            uint32_t axf[4];
            uint32_t ad = xU + (pw_r * 16 + (lane & 15)) * 528
                        + (ks * 16 + ((lane >> 4) << 3)) * 2;
            ldsm_x4(axf[0], axf[1], axf[2], axf[3], ad);
            uint32_t bw[4][2];
            #pragma unroll
            for (int p = 0; p < 2; p++) {
                uint32_t bd = wU + (ks * 16 + (lane & 15)) * 144
                            + (pw_c * 32 + p * 16 + ((lane >> 4) << 3)) * 2;
                ldsm_x4_t(bw[2*p][0], bw[2*p][1], bw[2*p+1][0], bw[2*p+1][1], bd);
            }
            #pragma unroll
            for (int nt = 0; nt < 4; nt++)
                mma_bf16(yacc[nt], axf, bw[nt]);
        }
        __syncthreads();

        #pragma unroll
        for (int half = 0; half < 2; half++) {
            int rib = pw_r * 16 + half * 8 + g;
            #pragma unroll
            for (int nt = 0; nt < 4; nt++) {
                int col = pw_c * 32 + nt * 8 + 2 * tig;
                float v0 = yacc[nt][half * 2 + 0] + lc2b[col];
                float v1 = yacc[nt][half * 2 + 1] + lc2b[col + 1];
                __nv_bfloat162 p;
                p.x = __float2bfloat16_rn(v0);
                p.y = __float2bfloat16_rn(v1);
                *(__nv_bfloat162*)(smc + rib * LMSTR + col * 2) = p;
            }
        }
        __syncthreads();
    }

    auto issue_B = [&](int stage, int t) {
        const char* Bb = (const char*)g_embf;
        #pragma unroll
        for (int i = 0; i < 4; i++) {
            int id = tid + i * 256;
            int row = id >> 3, c = (id & 7) << 4;
            int v = t * 128 + row;
            cp_async16(bU + stage * LM_BSTG + row * LMSTR + c,
                       Bb + (size_t)v * 128 + c, v < VOCAB);
        }
        cp_commit();
    };

    issue_B(0, 0);
    issue_B(1, 1);

    uint32_t af[2][4][4];
    #pragma unroll
    for (int mt = 0; mt < 2; mt++)
        #pragma unroll
        for (int ks = 0; ks < 4; ks++) {
            uint32_t ad = aU + (wm * 32 + mt * 16 + (lane & 15)) * LMSTR
                        + ks * 32 + ((lane >> 4) << 4);
            ldsm_x4(af[mt][ks][0], af[mt][ks][1], af[mt][ks][2], af[mt][ks][3], ad);
        }

    float rm[4], rs[4];
    #pragma unroll
    for (int s = 0; s < 4; s++) { rm[s] = -1e30f; rs[s] = 0.0f; }

    int brow = (lane & 7) + ((lane >> 4) << 3);
    int bcol16 = ((lane >> 3) & 1) << 4;

    // ======== PASS 1: stats ========
    for (int t = 0; t < LM_NTILE; t++) {
        if (t == LM_NTILE - 1) cp_wait0(); else cp_wait1();
        __syncthreads();
        if (t + 2 < LM_NTILE) issue_B((t + 2) % 3, t + 2);

        uint32_t bB = bU + (t % 3) * LM_BSTG;
        float acc[2][4][4] = {};
        #pragma unroll
        for (int ks = 0; ks < 4; ks++) {
            uint32_t bfr[4][2];
            #pragma unroll
            for (int p = 0; p < 2; p++) {
                uint32_t bd = bB + (wn * 32 + p * 16 + brow) * LMSTR + ks * 32 + bcol16;
                ldsm_x4(bfr[2*p][0], bfr[2*p][1], bfr[2*p+1][0], bfr[2*p+1][1], bd);
            }
            #pragma unroll
            for (int mt = 0; mt < 2; mt++)
                #pragma unroll
                for (int nt = 0; nt < 4; nt++)
                    mma_bf16(acc[mt][nt], af[mt][ks], bfr[nt]);
        }

        int nb0 = t * 128 + wn * 32 + 2 * tig;
        #pragma unroll
        for (int mt = 0; mt < 2; mt++)
            #pragma unroll
            for (int half = 0; half < 2; half++) {
                int slot = mt * 2 + half;
                float v[8];
                float bm = -1e30f;
                #pragma unroll
                for (int nt = 0; nt < 4; nt++)
                    #pragma unroll
                    for (int j = 0; j < 2; j++) {
                        int n = nb0 + nt * 8 + j;
                        float x = (n < VOCAB) ? acc[mt][nt][half * 2 + j] : -1e30f;
                        v[nt * 2 + j] = x;
                        bm = fmaxf(bm, x);
                    }
                float nm = fmaxf(rm[slot], bm);
                float add = 0.0f;
                #pragma unroll
                for (int j = 0; j < 8; j++) add += __expf(v[j] - nm);
                rs[slot] = rs[slot] * __expf(rm[slot] - nm) + add;
                rm[slot] = nm;
            }
    }

    // ---- reduce stats ----
    #pragma unroll
    for (int slot = 0; slot < 4; slot++) {
        float m = rm[slot], s = rs[slot];
        #pragma unroll
        for (int off = 1; off <= 2; off <<= 1) {
            float om = __shfl_xor_sync(0xffffffffu, m, off);
            float os = __shfl_xor_sync(0xffffffffu, s, off);
            float nm = fmaxf(m, om);
            s = s * __expf(m - nm) + os * __expf(om - nm);
            m = nm;
        }
        int mt = slot >> 1, half = slot & 1;
        int rib = wm * 32 + mt * 16 + half * 8 + g;
        if (tig == 0) spart[rib * 4 + wn] = make_float2(m, s);
    }
    __syncthreads();
    if (tid < 64) {
        float m = -1e30f, s = 0.0f;
        #pragma unroll
        for (int w = 0; w < 4; w++) {
            float2 p = spart[tid * 4 + w];
            float nm = fmaxf(m, p.x);
            s = s * __expf(m - nm) + p.y * __expf(p.x - nm);
            m = nm;
        }
        sstat[tid] = make_float2(m, 1.0f / s);
    }
    __syncthreads();

    float stm[4], sti[4];
    #pragma unroll
    for (int slot = 0; slot < 4; slot++) {
        int mt = slot >> 1, half = slot & 1;
        int rib = wm * 32 + mt * 16 + half * 8 + g;
        float2 st = sstat[rib];
        stm[slot] = st.x; sti[slot] = st.y;
    }

    // ======== PASS 2: recompute + write probs ========
    issue_B(0, 0);
    issue_B(1, 1);
    for (int t = 0; t < LM_NTILE; t++) {
        if (t == LM_NTILE - 1) cp_wait0(); else cp_wait1();
        __syncthreads();
        if (t + 2 < LM_NTILE) issue_B((t + 2) % 3, t + 2);

        uint32_t bB = bU + (t % 3) * LM_BSTG;
        float acc[2][4][4] = {};
        #pragma unroll
        for (int ks = 0; ks < 4; ks++) {
            uint32_t bfr[4][2];
            #pragma unroll
            for (int p = 0; p < 2; p++) {
                uint32_t bd = bB + (wn * 32 + p * 16 + brow) * LMSTR + ks * 32 + bcol16;
                ldsm_x4(bfr[2*p][0], bfr[2*p][1], bfr[2*p+1][0], bfr[2*p+1][1], bd);
            }
            #pragma unroll
            for (int mt = 0; mt < 2; mt++)
                #pragma unroll
                for (int nt = 0; nt < 4; nt++)
                    mma_bf16(acc[mt][nt], af[mt][ks], bfr[nt]);
        }

        int nb0 = t * 128 + wn * 32 + 2 * tig;
        #pragma unroll
        for (int mt = 0; mt < 2; mt++)
            #pragma unroll
            for (int half = 0; half < 2; half++) {
                int slot = mt * 2 + half;
                int rib = wm * 32 + mt * 16 + half * 8 + g;
                size_t rowoff = (size_t)(m0 + rib) * VOCAB;
                float m = stm[slot], inv = sti[slot];
                #pragma unroll
                for (int nt = 0; nt < 4; nt++) {
                    int n = nb0 + nt * 8;
                    if (n < VOCAB) {
                        float p0 = __expf(acc[mt][nt][half * 2 + 0] - m) * inv;
                        float p1 = __expf(acc[mt][nt][half * 2 + 1] - m) * inv;
                        __stcs((float2*)&probs[rowoff + n], make_float2(p0, p1));
                    }
                }
            }
    }
}

// ---------------- attention ----------------
__global__ void __launch_bounds__(256) attention_kernel() {
    __shared__ float qs[8][DG], ks[8][DG], vs[8][DG];
    int b = blockIdx.x;
    int tid = threadIdx.x;
    for (int i = tid; i < 8 * DG; i += 256) {
        int s = i >> 8, c = i & 255;
        size_t off = (size_t)(b * 8 + s) * 768 + c;
        qs[s][c] = __bfloat162float(g_qkv[off]);
        ks[s][c] = __bfloat162float(g_qkv[off + 256]);
        vs[s][c] = __bfloat162float(g_qkv[off + 512]);
    }
    __syncthreads();

    int h  = tid >> 6;
    int qx = (tid >> 3) & 7;
    int kx = tid & 7;
    float att = 0.0f;
    #pragma unroll
    for (int d = 0; d < HD; d++)
        att += qs[qx][h * HD + d] * ks[kx][h * HD + d];
    att *= 0.125f;

    float mx = att;
    mx = fmaxf(mx, __shfl_xor_sync(0xffffffffu, mx, 4));
    mx = fmaxf(mx, __shfl_xor_sync(0xffffffffu, mx, 2));
    mx = fmaxf(mx, __shfl_xor_sync(0xffffffffu, mx, 1));
    float ex = expf(att - mx);
    float sm = ex;
    sm += __shfl_xor_sync(0xffffffffu, sm, 4);
    sm += __shfl_xor_sync(0xffffffffu, sm, 2);
    sm += __shfl_xor_sync(0xffffffffu, sm, 1);
    float a = ex / sm;

    int lane = tid & 31;
    int base = lane & ~7;
    float a_all[8];
    #pragma unroll
    for (int kk = 0; kk < 8; kk++)
        a_all[kk] = __shfl_sync(0xffffffffu, a, base + kk);

    #pragma unroll
    for (int t2 = 0; t2 < 8; t2++) {
        int d = kx * 8 + t2;
        float o = 0.0f;
        #pragma unroll
        for (int kk = 0; kk < 8; kk++)
            o += a_all[kk] * vs[kk][h * HD + d];
        g_ao[(size_t)(b * 8 + qx) * DG + h * HD + d] = __float2bfloat16_rn(o);
    }
}

// ---------------- host launcher ----------------
template<int EPI, int GA, int NMT>
static void launch_one(const bf16* A, const bf16* B, void* C, int M, int N, int K,
                       const float* extraf, const bf16* extrab,
                       const int* gidx, const int* gidx2, int ldex, float* aggout) {
    static bool attr_done = false;
    if (!attr_done) {
        cudaFuncSetAttribute((tmma_k<EPI, GA, NMT>), cudaFuncAttributeMaxDynamicSharedMemorySize,
                             GEMM_SMEM_BYTES);
        attr_done = true;
    }
    dim3 grid((N + TBN - 1) / TBN, M / (NMT * 32)), blk(256);
    tmma_k<EPI, GA, NMT><<<grid, blk, GEMM_SMEM_BYTES>>>(A, B, C, M, N, K, extraf, extrab,
                                                         gidx, gidx2, ldex, aggout);
}

template <typename T>
static T* sym_addr(const void* sym) {
    void* p = nullptr;
    cudaGetSymbolAddress(&p, sym);
    return (T*)p;
}

extern "C" void kernel_launch(void* const* d_in, const int* in_sizes, int n_in,
                              void* d_out, int out_size) {
    const int*   node_tokens = (const int*)d_in[0];
    const int*   edge_tokens = (const int*)d_in[1];
    const int*   edge_index  = (const int*)d_in[2];
    const void*  mask_rows   = d_in[3];
    const float* emb    = (const float*)d_in[4];
    const float* W_msg  = (const float*)d_in[5];
    const float* W_node = (const float*)d_in[6];
    const float* lc1_w  = (const float*)d_in[7];
    const float* lc1_b  = (const float*)d_in[8];
    const float* lc2_w  = (const float*)d_in[9];
    const float* lc2_b  = (const float*)d_in[10];
    const float* Wq  = (const float*)d_in[11];
    const float* Wk  = (const float*)d_in[12];
    const float* Wv  = (const float*)d_in[13];
    const float* Wo  = (const float*)d_in[14];
    const float* Wf1 = (const float*)d_in[15];
    const float* Wf2 = (const float*)d_in[16];

    float* out = (float*)d_out;
    bool concat = (out_size != ROWS * VOCAB);
    float* labels_out = concat ? out : nullptr;
    float* probs      = concat ? out + ROWS : out;

    const int* src = edge_index;
    const int* dst = edge_index + N_EDGES;

    bf16* px   = sym_addr<bf16>(g_x);
    bf16* pe   = sym_addr<bf16>(g_e);
    float* pagg= sym_addr<float>(g_agg);
    bf16* ph   = sym_addr<bf16>(g_h);
    bf16* pzg  = sym_addr<bf16>(g_zg);
    bf16* pqkv = sym_addr<bf16>(g_qkv);
    bf16* pao  = sym_addr<bf16>(g_ao);
    bf16* px1  = sym_addr<bf16>(g_x1);
    bf16* pffn = sym_addr<bf16>(g_ffn);
    bf16* px2  = sym_addr<bf16>(g_x2);
    bf16* pwmsg = sym_addr<bf16>(g_wmsg);
    bf16* pwnode= sym_addr<bf16>(g_wnode);
    bf16* plc1w = sym_addr<bf16>(g_lc1w);
    bf16* pwo   = sym_addr<bf16>(g_wo);
    bf16* pwf1  = sym_addr<bf16>(g_wf1);
    bf16* pwf2  = sym_addr<bf16>(g_wf2);
    bf16* pwqkv = sym_addr<bf16>(g_wqkv);

    // 1. mask dtype detect + merged prep + agg clear
    detect_mask_kernel<<<1, 512>>>((const int*)mask_rows);
    prep_all_kernel<<<(PREP_TOTAL + 255) / 256, 256>>>(W_msg, W_node, lc1_w, lc2_w,
                                                       Wo, Wf1, Wf2, emb, Wq, Wk, Wv);
    cudaMemsetAsync(pagg, 0, (size_t)N_NODES * FD * sizeof(float));

    // 2. merged embeddings
    embed_all_kernel<<<(N16 + E16 + 255) / 256, 256>>>(node_tokens, edge_tokens,
                                                       mask_rows, labels_out);

    // 3. GNN: msg GEMM uses 32-row tiles (256 CTAs, fills chip); node GEMM 128-row
    launch_one<3,0,1>(pe, pwmsg, nullptr, N_EDGES, FD, FD, nullptr, px, src, dst, FD, pagg);
    launch_one<2,0,4>(px, pwnode, ph, N_NODES, FD, FD, pagg, nullptr, nullptr, nullptr, FD, nullptr);

    // 4. lc1 with fused edge gather
    launch_one<1,1,4>(nullptr, plc1w, pzg, ROWS, DG, D_GNN, lc1_b, nullptr, src, dst, 0, nullptr);

    // 5. transformer
    launch_one<0,0,4>(pzg, pwqkv, pqkv, ROWS, 3 * DG, DG, nullptr, nullptr, nullptr, nullptr, 0, nullptr);
    attention_kernel<<<N_EDGES, 256>>>();
    launch_one<4,0,4>(pao, pwo, px1, ROWS, DG, DG, nullptr, pzg, nullptr, nullptr, DG, nullptr);
    launch_one<5,0,4>(px1, pwf1, pffn, ROWS, 4 * DG, DG, nullptr, nullptr, nullptr, nullptr, 0, nullptr);
    launch_one<4,0,4>(pffn, pwf2, px2, ROWS, DG, 4 * DG, nullptr, px1, nullptr, nullptr, DG, nullptr);

    // 6. fused LM head
    {
        static bool lm_attr = false;
        if (!lm_attr) {
            cudaFuncSetAttribute(lm_fused, cudaFuncAttributeMaxDynamicSharedMemorySize,
                                 LM_SMEM_TOT);
            lm_attr = true;
        }
        lm_fused<<<ROWS / 64, 256, LM_SMEM_TOT>>>(probs, lc2_b);
    }
}

// round 16
// speedup vs baseline: 1.1163x; 1.0020x over previous
#include <cuda_runtime.h>
#include <cuda_bf16.h>
#include <math.h>
#include <stdint.h>

// ---------------- problem constants ----------------
#define VOCAB   10000
#define D_GNN   64
#define L_TOK   8
#define DG      256
#define NH      4
#define HD      64
#define N_NODES 8192
#define N_EDGES 2048
#define FD      512
#define ROWS    16384

typedef __nv_bfloat16 bf16;

// ---------------- scratch (static device memory) ----------------
__device__ bf16  g_x   [N_NODES * FD];
__device__ bf16  g_e   [N_EDGES * FD];
__device__ float g_agg [N_NODES * FD];
__device__ bf16  g_h   [N_NODES * FD];
__device__ bf16  g_zg  [ROWS * DG];
__device__ bf16  g_qkv [ROWS * 3 * DG];
__device__ bf16  g_ao  [ROWS * DG];
__device__ bf16  g_x1  [ROWS * DG];
__device__ bf16  g_ffn [ROWS * 4 * DG];
__device__ bf16  g_x2  [ROWS * DG];
__device__ bf16  g_wmsg [FD * FD];
__device__ bf16  g_wnode[FD * FD];
__device__ bf16  g_lc1w [D_GNN * DG];
__device__ bf16  g_lc2w [DG * D_GNN];
__device__ bf16  g_wo   [DG * DG];
__device__ bf16  g_wf1  [DG * 4 * DG];
__device__ bf16  g_wf2  [4 * DG * DG];
__device__ bf16  g_wqkv [DG * 3 * DG];
__device__ bf16  g_embf [VOCAB * D_GNN];
__device__ int   g_mask_mode;

// ---------------- mask dtype detection ----------------
__global__ void detect_mask_kernel(const int* __restrict__ mr) {
    __shared__ int notint, notflt;
    if (threadIdx.x == 0) { notint = 0; notflt = 0; }
    __syncthreads();
    int w = mr[threadIdx.x];
    if (w != 0 && w != 1)          atomicExch(&notint, 1);
    if (w != 0 && w != 0x3F800000) atomicExch(&notflt, 1);
    __syncthreads();
    if (threadIdx.x == 0)
        g_mask_mode = notint ? (notflt ? 2 : 1) : 0;
}

// ---------------- merged prep ----------------
#define SZ_WMSG  (FD*FD)
#define SZ_WNODE (FD*FD)
#define SZ_LC1   (D_GNN*DG)
#define SZ_LC2   (DG*D_GNN)
#define SZ_WO    (DG*DG)
#define SZ_WF1   (DG*4*DG)
#define SZ_WF2   (4*DG*DG)
#define CW_TOTAL (SZ_WMSG+SZ_WNODE+SZ_LC1+SZ_LC2+SZ_WO+SZ_WF1+SZ_WF2)
#define PREP_TOTAL (CW_TOTAL + VOCAB*D_GNN + DG*DG)

__global__ void prep_all_kernel(const float* Wmsg, const float* Wnode,
                                const float* lc1w, const float* lc2w,
                                const float* Wo, const float* Wf1, const float* Wf2,
                                const float* emb, const float* Wq, const float* Wk,
                                const float* Wv) {
    int i = blockIdx.x * blockDim.x + threadIdx.x;
    if (i >= PREP_TOTAL) return;
    int j = i;
    if (j < SZ_WMSG)  { g_wmsg[j]  = __float2bfloat16_rn(Wmsg[j]);  return; } j -= SZ_WMSG;
    if (j < SZ_WNODE) { g_wnode[j] = __float2bfloat16_rn(Wnode[j]); return; } j -= SZ_WNODE;
    if (j < SZ_LC1)   { g_lc1w[j]  = __float2bfloat16_rn(lc1w[j]);  return; } j -= SZ_LC1;
    if (j < SZ_LC2)   { g_lc2w[j]  = __float2bfloat16_rn(lc2w[j]);  return; } j -= SZ_LC2;
    if (j < SZ_WO)    { g_wo[j]    = __float2bfloat16_rn(Wo[j]);    return; } j -= SZ_WO;
    if (j < SZ_WF1)   { g_wf1[j]   = __float2bfloat16_rn(Wf1[j]);   return; } j -= SZ_WF1;
    if (j < SZ_WF2)   { g_wf2[j]   = __float2bfloat16_rn(Wf2[j]);   return; } j -= SZ_WF2;
    if (j < VOCAB*D_GNN) { g_embf[j] = __float2bfloat16_rn(emb[j]); return; } j -= VOCAB*D_GNN;
    int k = j >> 8, n = j & 255;
    g_wqkv[k * 768 + n]       = __float2bfloat16_rn(Wq[j]);
    g_wqkv[k * 768 + 256 + n] = __float2bfloat16_rn(Wk[j]);
    g_wqkv[k * 768 + 512 + n] = __float2bfloat16_rn(Wv[j]);
}

// merged: node embed + edge embed with inline masking + labels
#define N16 (N_NODES * FD / 8)
#define E16 (N_EDGES * FD / 8)
__global__ void embed_all_kernel(const int* __restrict__ ntok, const int* __restrict__ etok,
                                 const void* __restrict__ maskraw, float* labels_out) {
    int i = blockIdx.x * blockDim.x + threadIdx.x;
    if (i >= N16 + E16) return;
    const uint4* tab = (const uint4*)g_embf;
    if (i < N16) {
        ((uint4*)g_x)[i] = tab[ntok[i >> 3] * 8 + (i & 7)];
    } else {
        int j = i - N16;
        int ti = j >> 3;
        int e  = ti >> 3;
        int t = etok[ti];
        bool mr;
        int mode = g_mask_mode;
        if (mode == 0)      mr = ((const int*)maskraw)[e] != 0;
        else if (mode == 1) mr = ((const float*)maskraw)[e] != 0.0f;
        else                mr = ((const unsigned char*)maskraw)[e] != 0;
        bool msk = mr && (t >= 4);
        int tok = msk ? 4 : t;
        ((uint4*)g_e)[j] = tab[tok * 8 + (j & 7)];
        if ((j & 7) == 0 && labels_out)
            labels_out[ti] = msk ? (float)t : -100.0f;
    }
}

// ================= common helpers =================
__device__ __forceinline__ void cp_async16(uint32_t dst, const void* src, bool pred) {
    int sz = pred ? 16 : 0;
    asm volatile("cp.async.cg.shared.global [%0], [%1], 16, %2;\n"
                 :: "r"(dst), "l"(src), "r"(sz));
}
__device__ __forceinline__ void cp_commit() { asm volatile("cp.async.commit_group;\n"); }
__device__ __forceinline__ void cp_wait0()  { asm volatile("cp.async.wait_group 0;\n"); }
__device__ __forceinline__ void cp_wait1()  { asm volatile("cp.async.wait_group 1;\n"); }

__device__ __forceinline__ void mma_bf16(float c[4], const uint32_t a[4], const uint32_t b[2]) {
    asm volatile(
        "mma.sync.aligned.m16n8k16.row.col.f32.bf16.bf16.f32 "
        "{%0,%1,%2,%3}, {%4,%5,%6,%7}, {%8,%9}, {%0,%1,%2,%3};"
        : "+f"(c[0]), "+f"(c[1]), "+f"(c[2]), "+f"(c[3])
        : "r"(a[0]), "r"(a[1]), "r"(a[2]), "r"(a[3]), "r"(b[0]), "r"(b[1]));
}

__device__ __forceinline__ void ldsm_x4(uint32_t& r0, uint32_t& r1, uint32_t& r2, uint32_t& r3,
                                        uint32_t addr) {
    asm volatile("ldmatrix.sync.aligned.m8n8.x4.shared.b16 {%0,%1,%2,%3}, [%4];"
                 : "=r"(r0), "=r"(r1), "=r"(r2), "=r"(r3) : "r"(addr));
}
__device__ __forceinline__ void ldsm_x4_t(uint32_t& r0, uint32_t& r1, uint32_t& r2, uint32_t& r3,
                                          uint32_t addr) {
    asm volatile("ldmatrix.sync.aligned.m8n8.x4.trans.shared.b16 {%0,%1,%2,%3}, [%4];"
                 : "=r"(r0), "=r"(r1), "=r"(r2), "=r"(r3) : "r"(addr));
}

__device__ __forceinline__ uint4 add_pack8(uint4 ra, uint4 rb) {
    const __nv_bfloat162* ha = (const __nv_bfloat162*)&ra;
    const __nv_bfloat162* hb = (const __nv_bfloat162*)&rb;
    uint4 out;
    __nv_bfloat162* ho = (__nv_bfloat162*)&out;
    #pragma unroll
    for (int j = 0; j < 4; j++) {
        ho[j].x = __float2bfloat16_rn(__bfloat162float(ha[j].x) + __bfloat162float(hb[j].x));
        ho[j].y = __float2bfloat16_rn(__bfloat162float(ha[j].y) + __bfloat162float(hb[j].y));
    }
    return out;
}

// ================= mma.sync bf16 GEMM, TBK=64, M-tile = NMT*32, NMT-scaled smem =================
// EPI: 0 plain | 1 +biasf[n] | 2 relu(+extraf[m*ld+n]) |
//      3 relu(c + extrab[gidx[m]*ld+n]) -> atomicAdd(aggout[gidx2[m]*ld+n])  [no C write]
//      4 +extrab[m*ld+n] | 5 gelu
// GA=1: A row r = g_h[gidx[r>>3]] + g_h[gidx2[r>>3]] slice (r&7)*64 (K must be 64)

#define TBN 128
#define TBK 64
#define ASTRH 72
#define BSTRH 136
#define NSTAGE 3
#define B_STAGE_H (TBK * BSTRH)
#define A_STAGE_OF(NMT) ((NMT) * 32 * ASTRH)
#define GEMM_SMEM_OF(NMT) (NSTAGE * (A_STAGE_OF(NMT) + B_STAGE_H) * 2)

template<int EPI, int GA, int NMT>
__global__ void __launch_bounds__(256)
tmma_k(const bf16* __restrict__ A, const bf16* __restrict__ B, void* __restrict__ Cv,
       int M, int N, int K,
       const float* __restrict__ extraf, const bf16* __restrict__ extrab,
       const int* __restrict__ gidx, const int* __restrict__ gidx2, int ldex,
       float* __restrict__ aggout) {
    extern __shared__ bf16 smem[];
    const int A_STAGE = A_STAGE_OF(NMT);
    bf16* Asm = smem;
    bf16* Bsm = smem + NSTAGE * A_STAGE;

    uint32_t aU = (uint32_t)__cvta_generic_to_shared(Asm);
    uint32_t bU = (uint32_t)__cvta_generic_to_shared(Bsm);

    const int TBM_L = NMT * 32;

    int tid  = threadIdx.x;
    int lane = tid & 31;
    int warp = tid >> 5;
    int wm = warp & 1;
    int wn = warp >> 1;
    int g   = lane >> 2;
    int tig = lane & 3;
    int m0 = blockIdx.y * TBM_L;
    int n0 = blockIdx.x * TBN;

    float acc[NMT][4][4] = {};

    auto issue_load = [&](int s, int k0) {
        #pragma unroll
        for (int i = 0; i < NMT; i++) {
            int id = tid + i * 256;
            int ar = id >> 3, ak = (id & 7) << 3;
            if (GA) {
                int r = m0 + ar;
                int e = r >> 3, l = r & 7;
                const bf16* hs = g_h + (size_t)gidx[e]  * FD + l * 64 + ak;
                const bf16* hd = g_h + (size_t)gidx2[e] * FD + l * 64 + ak;
                uint4 v = add_pack8(*(const uint4*)hs, *(const uint4*)hd);
                *(uint4*)&Asm[s * A_STAGE + ar * ASTRH + ak] = v;
            } else {
                uint32_t da = aU + (s * A_STAGE + ar * ASTRH + ak) * 2;
                cp_async16(da, A + (size_t)(m0 + ar) * K + k0 + ak, true);
            }
        }
        #pragma unroll
        for (int i = 0; i < 4; i++) {
            int id = tid + i * 256;
            int br = id >> 4, bn = (id & 15) << 3;
            int gn = n0 + bn;
            uint32_t db = bU + (s * B_STAGE_H + br * BSTRH + bn) * 2;
            cp_async16(db, B + (size_t)(k0 + br) * N + gn, gn + 8 <= N);
        }
    };

    int niter = K / TBK;
    issue_load(0, 0);
    cp_commit();
    if (niter > 1) { issue_load(1, TBK); cp_commit(); }

    for (int it = 0; it < niter; it++) {
        if (it >= niter - 2) cp_wait0(); else cp_wait1();
        __syncthreads();
        if (it + 2 < niter) {
            issue_load((it + 2) % NSTAGE, (it + 2) * TBK);
            cp_commit();
        }
        int s = it % NSTAGE;
        uint32_t aB = aU + s * A_STAGE * 2;
        uint32_t bB = bU + s * B_STAGE_H * 2;
        #pragma unroll
        for (int ks = 0; ks < TBK; ks += 16) {
            uint32_t af[NMT][4], bfr[4][2];
            #pragma unroll
            for (int mt = 0; mt < NMT; mt++) {
                int row = wm * (NMT * 16) + mt * 16 + (lane & 15);
                uint32_t ad = aB + (row * ASTRH + ks + ((lane >> 4) << 3)) * 2;
                ldsm_x4(af[mt][0], af[mt][1], af[mt][2], af[mt][3], ad);
            }
            #pragma unroll
            for (int bp = 0; bp < 2; bp++) {
                int krow = ks + (lane & 15);
                int ncol = wn * 32 + bp * 16 + ((lane >> 4) << 3);
                uint32_t bd = bB + (krow * BSTRH + ncol) * 2;
                ldsm_x4_t(bfr[2*bp][0], bfr[2*bp][1], bfr[2*bp+1][0], bfr[2*bp+1][1], bd);
            }
            #pragma unroll
            for (int mt = 0; mt < NMT; mt++)
                #pragma unroll
                for (int nt = 0; nt < 4; nt++)
                    mma_bf16(acc[mt][nt], af[mt], bfr[nt]);
        }
    }

    bf16* Cb = (bf16*)Cv;

    #pragma unroll
    for (int mt = 0; mt < NMT; mt++) {
        #pragma unroll
        for (int half = 0; half < 2; half++) {
            int rib = wm * (NMT * 16) + mt * 16 + half * 8 + g;
            int r = m0 + rib;
            int ebase = 0, abase = 0;
            if (EPI == 2 || EPI == 4) ebase = r * ldex;
            if (EPI == 3) { ebase = gidx[r] * ldex; abase = gidx2[r] * ldex; }

            #pragma unroll
            for (int nt = 0; nt < 4; nt++) {
                int n = n0 + wn * 32 + nt * 8 + 2 * tig;
                float c0 = acc[mt][nt][half * 2 + 0];
                float c1 = acc[mt][nt][half * 2 + 1];
                if (EPI == 1) { c0 += extraf[n]; c1 += extraf[n + 1]; }
                else if (EPI == 2) {
                    c0 = fmaxf(c0 + extraf[ebase + n],     0.0f);
                    c1 = fmaxf(c1 + extraf[ebase + n + 1], 0.0f);
                } else if (EPI == 3) {
                    c0 = fmaxf(c0 + __bfloat162float(extrab[ebase + n]),     0.0f);
                    c1 = fmaxf(c1 + __bfloat162float(extrab[ebase + n + 1]), 0.0f);
                    atomicAdd(&aggout[abase + n],     c0);
                    atomicAdd(&aggout[abase + n + 1], c1);
                    continue;
                } else if (EPI == 4) {
                    c0 += __bfloat162float(extrab[ebase + n]);
                    c1 += __bfloat162float(extrab[ebase + n + 1]);
                } else if (EPI == 5) {
                    float x = c0;
                    c0 = 0.5f * x * (1.0f + tanhf(0.7978845608028654f * (x + 0.044715f * x * x * x)));
                    x = c1;
                    c1 = 0.5f * x * (1.0f + tanhf(0.7978845608028654f * (x + 0.044715f * x * x * x)));
                }
                if (n + 1 < N) {
                    __nv_bfloat162 p;
                    p.x = __float2bfloat16_rn(c0);
                    p.y = __float2bfloat16_rn(c1);
                    *(__nv_bfloat162*)&Cb[(size_t)r * N + n] = p;
                }
            }
        }
    }
}

// ================= fused persistent LM head, M=64 rows/CTA =================
#define LMSTR    144
#define LM_A_B   (64 * LMSTR)
#define LM_BSTG  (128 * LMSTR)
#define LM_B_OFF LM_A_B
#define LM_NTILE 79
#define LM_X2_OFF  LM_A_B
#define LM_W2_OFF  (LM_A_B + 64 * 528)
#define LM_STAT_OFF (LM_W2_OFF + 256 * 144)
#define LM_SMEM_TOT (LM_STAT_OFF + 64 * 4 * 8 + 64 * 8)

__global__ void __launch_bounds__(256, 2)
lm_fused(float* __restrict__ probs, const float* __restrict__ lc2b) {
    extern __shared__ char smc[];
    uint32_t aU = (uint32_t)__cvta_generic_to_shared(smc);
    uint32_t bU = aU + LM_B_OFF;
    float2* spart = (float2*)(smc + LM_STAT_OFF);
    float2* sstat = spart + 64 * 4;

    int tid = threadIdx.x;
    int lane = tid & 31, warp = tid >> 5;
    int wm = warp & 1, wn = warp >> 1;
    int g = lane >> 2, tig = lane & 3;
    int m0 = blockIdx.x * 64;

    // ---- preamble: y[64,64] = x2[64,256] @ lc2w + b -> A region ----
    {
        uint32_t xU = aU + LM_X2_OFF;
        uint32_t wU = aU + LM_W2_OFF;
        const char* X2b = (const char*)g_x2;
        #pragma unroll
        for (int i = 0; i < 8; i++) {
            int id = tid + i * 256;
            int row = id >> 5, c = (id & 31) << 4;
            cp_async16(xU + row * 528 + c, X2b + (size_t)(m0 + row) * 512 + c, true);
        }
        const char* W2b = (const char*)g_lc2w;
        #pragma unroll
        for (int i = 0; i < 8; i++) {
            int id = tid + i * 256;
            int row = id >> 3, c = (id & 7) << 4;
            cp_async16(wU + row * 144 + c, W2b + (size_t)row * 128 + c, true);
        }
        cp_commit(); cp_wait0();
        __syncthreads();

        int pw_r = warp & 3;
        int pw_c = warp >> 2;
        float yacc[4][4] = {};
        #pragma unroll
        for (int ks = 0; ks < 16; ks++) {
            uint32_t axf[4];
            uint32_t ad = xU + (pw_r * 16 + (lane & 15)) * 528
                        + (ks * 16 + ((lane >> 4) << 3)) * 2;
            ldsm_x4(axf[0], axf[1], axf[2], axf[3], ad);
            uint32_t bw[4][2];
            #pragma unroll
            for (int p = 0; p < 2; p++) {
                uint32_t bd = wU + (ks * 16 + (lane & 15)) * 144
                            + (pw_c * 32 + p * 16 + ((lane >> 4) << 3)) * 2;
                ldsm_x4_t(bw[2*p][0], bw[2*p][1], bw[2*p+1][0], bw[2*p+1][1], bd);
            }
            #pragma unroll
            for (int nt = 0; nt < 4; nt++)
                mma_bf16(yacc[nt], axf, bw[nt]);
        }
        __syncthreads();

        #pragma unroll
        for (int half = 0; half < 2; half++) {
            int rib = pw_r * 16 + half * 8 + g;
            #pragma unroll
            for (int nt = 0; nt < 4; nt++) {
                int col = pw_c * 32 + nt * 8 + 2 * tig;
                float v0 = yacc[nt][half * 2 + 0] + lc2b[col];
                float v1 = yacc[nt][half * 2 + 1] + lc2b[col + 1];
                __nv_bfloat162 p;
                p.x = __float2bfloat16_rn(v0);
                p.y = __float2bfloat16_rn(v1);
                *(__nv_bfloat162*)(smc + rib * LMSTR + col * 2) = p;
            }
        }
        __syncthreads();
    }

    auto issue_B = [&](int stage, int t) {
        const char* Bb = (const char*)g_embf;
        #pragma unroll
        for (int i = 0; i < 4; i++) {
            int id = tid + i * 256;
            int row = id >> 3, c = (id & 7) << 4;
            int v = t * 128 + row;
            cp_async16(bU + stage * LM_BSTG + row * LMSTR + c,
                       Bb + (size_t)v * 128 + c, v < VOCAB);
        }
        cp_commit();
    };

    issue_B(0, 0);
    issue_B(1, 1);

    uint32_t af[2][4][4];
    #pragma unroll
    for (int mt = 0; mt < 2; mt++)
        #pragma unroll
        for (int ks = 0; ks < 4; ks++) {
            uint32_t ad = aU + (wm * 32 + mt * 16 + (lane & 15)) * LMSTR
                        + ks * 32 + ((lane >> 4) << 4);
            ldsm_x4(af[mt][ks][0], af[mt][ks][1], af[mt][ks][2], af[mt][ks][3], ad);
        }

    float rm[4], rs[4];
    #pragma unroll
    for (int s = 0; s < 4; s++) { rm[s] = -1e30f; rs[s] = 0.0f; }

    int brow = (lane & 7) + ((lane >> 4) << 3);
    int bcol16 = ((lane >> 3) & 1) << 4;

    // ======== PASS 1: stats ========
    for (int t = 0; t < LM_NTILE; t++) {
        if (t == LM_NTILE - 1) cp_wait0(); else cp_wait1();
        __syncthreads();
        if (t + 2 < LM_NTILE) issue_B((t + 2) % 3, t + 2);

        uint32_t bB = bU + (t % 3) * LM_BSTG;
        float acc[2][4][4] = {};
        #pragma unroll
        for (int ks = 0; ks < 4; ks++) {
            uint32_t bfr[4][2];
            #pragma unroll
            for (int p = 0; p < 2; p++) {
                uint32_t bd = bB + (wn * 32 + p * 16 + brow) * LMSTR + ks * 32 + bcol16;
                ldsm_x4(bfr[2*p][0], bfr[2*p][1], bfr[2*p+1][0], bfr[2*p+1][1], bd);
            }
            #pragma unroll
            for (int mt = 0; mt < 2; mt++)
                #pragma unroll
                for (int nt = 0; nt < 4; nt++)
                    mma_bf16(acc[mt][nt], af[mt][ks], bfr[nt]);
        }

        int nb0 = t * 128 + wn * 32 + 2 * tig;
        #pragma unroll
        for (int mt = 0; mt < 2; mt++)
            #pragma unroll
            for (int half = 0; half < 2; half++) {
                int slot = mt * 2 + half;
                float v[8];
                float bm = -1e30f;
                #pragma unroll
                for (int nt = 0; nt < 4; nt++)
                    #pragma unroll
                    for (int j = 0; j < 2; j++) {
                        int n = nb0 + nt * 8 + j;
                        float x = (n < VOCAB) ? acc[mt][nt][half * 2 + j] : -1e30f;
                        v[nt * 2 + j] = x;
                        bm = fmaxf(bm, x);
                    }
                float nm = fmaxf(rm[slot], bm);
                float add = 0.0f;
                #pragma unroll
                for (int j = 0; j < 8; j++) add += __expf(v[j] - nm);
                rs[slot] = rs[slot] * __expf(rm[slot] - nm) + add;
                rm[slot] = nm;
            }
    }

    // ---- reduce stats ----
    #pragma unroll
    for (int slot = 0; slot < 4; slot++) {
        float m = rm[slot], s = rs[slot];
        #pragma unroll
        for (int off = 1; off <= 2; off <<= 1) {
            float om = __shfl_xor_sync(0xffffffffu, m, off);
            float os = __shfl_xor_sync(0xffffffffu, s, off);
            float nm = fmaxf(m, om);
            s = s * __expf(m - nm) + os * __expf(om - nm);
            m = nm;
        }
        int mt = slot >> 1, half = slot & 1;
        int rib = wm * 32 + mt * 16 + half * 8 + g;
        if (tig == 0) spart[rib * 4 + wn] = make_float2(m, s);
    }
    __syncthreads();
    if (tid < 64) {
        float m = -1e30f, s = 0.0f;
        #pragma unroll
        for (int w = 0; w < 4; w++) {
            float2 p = spart[tid * 4 + w];
            float nm = fmaxf(m, p.x);
            s = s * __expf(m - nm) + p.y * __expf(p.x - nm);
            m = nm;
        }
        sstat[tid] = make_float2(m, 1.0f / s);
    }
    __syncthreads();

    float stm[4], sti[4];
    #pragma unroll
    for (int slot = 0; slot < 4; slot++) {
        int mt = slot >> 1, half = slot & 1;
        int rib = wm * 32 + mt * 16 + half * 8 + g;
        float2 st = sstat[rib];
        stm[slot] = st.x; sti[slot] = st.y;
    }

    // ======== PASS 2: recompute + write probs ========
    issue_B(0, 0);
    issue_B(1, 1);
    for (int t = 0; t < LM_NTILE; t++) {
        if (t == LM_NTILE - 1) cp_wait0(); else cp_wait1();
        __syncthreads();
        if (t + 2 < LM_NTILE) issue_B((t + 2) % 3, t + 2);

        uint32_t bB = bU + (t % 3) * LM_BSTG;
        float acc[2][4][4] = {};
        #pragma unroll
        for (int ks = 0; ks < 4; ks++) {
            uint32_t bfr[4][2];
            #pragma unroll
            for (int p = 0; p < 2; p++) {
                uint32_t bd = bB + (wn * 32 + p * 16 + brow) * LMSTR + ks * 32 + bcol16;
                ldsm_x4(bfr[2*p][0], bfr[2*p][1], bfr[2*p+1][0], bfr[2*p+1][1], bd);
            }
            #pragma unroll
            for (int mt = 0; mt < 2; mt++)
                #pragma unroll
                for (int nt = 0; nt < 4; nt++)
                    mma_bf16(acc[mt][nt], af[mt][ks], bfr[nt]);
        }

        int nb0 = t * 128 + wn * 32 + 2 * tig;
        #pragma unroll
        for (int mt = 0; mt < 2; mt++)
            #pragma unroll
            for (int half = 0; half < 2; half++) {
                int slot = mt * 2 + half;
                int rib = wm * 32 + mt * 16 + half * 8 + g;
                size_t rowoff = (size_t)(m0 + rib) * VOCAB;
                float m = stm[slot], inv = sti[slot];
                #pragma unroll
                for (int nt = 0; nt < 4; nt++) {
                    int n = nb0 + nt * 8;
                    if (n < VOCAB) {
                        float p0 = __expf(acc[mt][nt][half * 2 + 0] - m) * inv;
                        float p1 = __expf(acc[mt][nt][half * 2 + 1] - m) * inv;
                        __stcs((float2*)&probs[rowoff + n], make_float2(p0, p1));
                    }
                }
            }
    }
}

// ---------------- attention ----------------
__global__ void __launch_bounds__(256) attention_kernel() {
    __shared__ float qs[8][DG], ks[8][DG], vs[8][DG];
    int b = blockIdx.x;
    int tid = threadIdx.x;
    for (int i = tid; i < 8 * DG; i += 256) {
        int s = i >> 8, c = i & 255;
        size_t off = (size_t)(b * 8 + s) * 768 + c;
        qs[s][c] = __bfloat162float(g_qkv[off]);
        ks[s][c] = __bfloat162float(g_qkv[off + 256]);
        vs[s][c] = __bfloat162float(g_qkv[off + 512]);
    }
    __syncthreads();

    int h  = tid >> 6;
    int qx = (tid >> 3) & 7;
    int kx = tid & 7;
    float att = 0.0f;
    #pragma unroll
    for (int d = 0; d < HD; d++)
        att += qs[qx][h * HD + d] * ks[kx][h * HD + d];
    att *= 0.125f;

    float mx = att;
    mx = fmaxf(mx, __shfl_xor_sync(0xffffffffu, mx, 4));
    mx = fmaxf(mx, __shfl_xor_sync(0xffffffffu, mx, 2));
    mx = fmaxf(mx, __shfl_xor_sync(0xffffffffu, mx, 1));
    float ex = expf(att - mx);
    float sm = ex;
    sm += __shfl_xor_sync(0xffffffffu, sm, 4);
    sm += __shfl_xor_sync(0xffffffffu, sm, 2);
    sm += __shfl_xor_sync(0xffffffffu, sm, 1);
    float a = ex / sm;

    int lane = tid & 31;
    int base = lane & ~7;
    float a_all[8];
    #pragma unroll
    for (int kk = 0; kk < 8; kk++)
        a_all[kk] = __shfl_sync(0xffffffffu, a, base + kk);

    #pragma unroll
    for (int t2 = 0; t2 < 8; t2++) {
        int d = kx * 8 + t2;
        float o = 0.0f;
        #pragma unroll
        for (int kk = 0; kk < 8; kk++)
            o += a_all[kk] * vs[kk][h * HD + d];
        g_ao[(size_t)(b * 8 + qx) * DG + h * HD + d] = __float2bfloat16_rn(o);
    }
}

// ---------------- host launcher ----------------
template<int EPI, int GA, int NMT>
static void launch_one(const bf16* A, const bf16* B, void* C, int M, int N, int K,
                       const float* extraf, const bf16* extrab,
                       const int* gidx, const int* gidx2, int ldex, float* aggout) {
    static bool attr_done = false;
    if (!attr_done) {
        cudaFuncSetAttribute((tmma_k<EPI, GA, NMT>), cudaFuncAttributeMaxDynamicSharedMemorySize,
                             GEMM_SMEM_OF(NMT));
        attr_done = true;
    }
    dim3 grid((N + TBN - 1) / TBN, M / (NMT * 32)), blk(256);
    tmma_k<EPI, GA, NMT><<<grid, blk, GEMM_SMEM_OF(NMT)>>>(A, B, C, M, N, K, extraf, extrab,
                                                           gidx, gidx2, ldex, aggout);
}

template <typename T>
static T* sym_addr(const void* sym) {
    void* p = nullptr;
    cudaGetSymbolAddress(&p, sym);
    return (T*)p;
}

extern "C" void kernel_launch(void* const* d_in, const int* in_sizes, int n_in,
                              void* d_out, int out_size) {
    const int*   node_tokens = (const int*)d_in[0];
    const int*   edge_tokens = (const int*)d_in[1];
    const int*   edge_index  = (const int*)d_in[2];
    const void*  mask_rows   = d_in[3];
    const float* emb    = (const float*)d_in[4];
    const float* W_msg  = (const float*)d_in[5];
    const float* W_node = (const float*)d_in[6];
    const float* lc1_w  = (const float*)d_in[7];
    const float* lc1_b  = (const float*)d_in[8];
    const float* lc2_w  = (const float*)d_in[9];
    const float* lc2_b  = (const float*)d_in[10];
    const float* Wq  = (const float*)d_in[11];
    const float* Wk  = (const float*)d_in[12];
    const float* Wv  = (const float*)d_in[13];
    const float* Wo  = (const float*)d_in[14];
    const float* Wf1 = (const float*)d_in[15];
    const float* Wf2 = (const float*)d_in[16];

    float* out = (float*)d_out;
    bool concat = (out_size != ROWS * VOCAB);
    float* labels_out = concat ? out : nullptr;
    float* probs      = concat ? out + ROWS : out;

    const int* src = edge_index;
    const int* dst = edge_index + N_EDGES;

    bf16* px   = sym_addr<bf16>(g_x);
    bf16* pe   = sym_addr<bf16>(g_e);
    float* pagg= sym_addr<float>(g_agg);
    bf16* ph   = sym_addr<bf16>(g_h);
    bf16* pzg  = sym_addr<bf16>(g_zg);
    bf16* pqkv = sym_addr<bf16>(g_qkv);
    bf16* pao  = sym_addr<bf16>(g_ao);
    bf16* px1  = sym_addr<bf16>(g_x1);
    bf16* pffn = sym_addr<bf16>(g_ffn);
    bf16* px2  = sym_addr<bf16>(g_x2);
    bf16* pwmsg = sym_addr<bf16>(g_wmsg);
    bf16* pwnode= sym_addr<bf16>(g_wnode);
    bf16* plc1w = sym_addr<bf16>(g_lc1w);
    bf16* pwo   = sym_addr<bf16>(g_wo);
    bf16* pwf1  = sym_addr<bf16>(g_wf1);
    bf16* pwf2  = sym_addr<bf16>(g_wf2);
    bf16* pwqkv = sym_addr<bf16>(g_wqkv);

    // 1. mask dtype detect + merged prep + agg clear
    detect_mask_kernel<<<1, 512>>>((const int*)mask_rows);
    prep_all_kernel<<<(PREP_TOTAL + 255) / 256, 256>>>(W_msg, W_node, lc1_w, lc2_w,
                                                       Wo, Wf1, Wf2, emb, Wq, Wk, Wv);
    cudaMemsetAsync(pagg, 0, (size_t)N_NODES * FD * sizeof(float));

    // 2. merged embeddings
    embed_all_kernel<<<(N16 + E16 + 255) / 256, 256>>>(node_tokens, edge_tokens,
                                                       mask_rows, labels_out);

    // 3. GNN: msg GEMM 32-row tiles with right-sized smem (3 CTAs/SM); node GEMM 128-row
    launch_one<3,0,1>(pe, pwmsg, nullptr, N_EDGES, FD, FD, nullptr, px, src, dst, FD, pagg);
    launch_one<2,0,4>(px, pwnode, ph, N_NODES, FD, FD, pagg, nullptr, nullptr, nullptr, FD, nullptr);

    // 4. lc1 with fused edge gather
    launch_one<1,1,4>(nullptr, plc1w, pzg, ROWS, DG, D_GNN, lc1_b, nullptr, src, dst, 0, nullptr);

    // 5. transformer
    launch_one<0,0,4>(pzg, pwqkv, pqkv, ROWS, 3 * DG, DG, nullptr, nullptr, nullptr, nullptr, 0, nullptr);
    attention_kernel<<<N_EDGES, 256>>>();
    launch_one<4,0,4>(pao, pwo, px1, ROWS, DG, DG, nullptr, pzg, nullptr, nullptr, DG, nullptr);
    launch_one<5,0,4>(px1, pwf1, pffn, ROWS, 4 * DG, DG, nullptr, nullptr, nullptr, nullptr, 0, nullptr);
    launch_one<4,0,4>(pffn, pwf2, px2, ROWS, DG, 4 * DG, nullptr, px1, nullptr, nullptr, DG, nullptr);

    // 6. fused LM head
    {
        static bool lm_attr = false;
        if (!lm_attr) {
            cudaFuncSetAttribute(lm_fused, cudaFuncAttributeMaxDynamicSharedMemorySize,
                                 LM_SMEM_TOT);
            lm_attr = true;
        }
        lm_fused<<<ROWS / 64, 256, LM_SMEM_TOT>>>(probs, lc2_b);
    }
}

// round 17
// speedup vs baseline: 1.1375x; 1.0190x over previous
#include <cuda_runtime.h>
#include <cuda_bf16.h>
#include <math.h>
#include <stdint.h>

// ---------------- problem constants ----------------
#define VOCAB   10000
#define D_GNN   64
#define L_TOK   8
#define DG      256
#define NH      4
#define HD      64
#define N_NODES 8192
#define N_EDGES 2048
#define FD      512
#define ROWS    16384
#define LOG2E   1.4426950408889634f

typedef __nv_bfloat16 bf16;

// ---------------- scratch (static device memory) ----------------
__device__ bf16  g_x   [N_NODES * FD];
__device__ bf16  g_e   [N_EDGES * FD];
__device__ float g_agg [N_NODES * FD];
__device__ bf16  g_h   [N_NODES * FD];
__device__ bf16  g_zg  [ROWS * DG];
__device__ bf16  g_qkv [ROWS * 3 * DG];
__device__ bf16  g_ao  [ROWS * DG];
__device__ bf16  g_x1  [ROWS * DG];
__device__ bf16  g_ffn [ROWS * 4 * DG];
__device__ bf16  g_x2  [ROWS * DG];
__device__ bf16  g_wmsg [FD * FD];
__device__ bf16  g_wnode[FD * FD];
__device__ bf16  g_lc1w [D_GNN * DG];
__device__ bf16  g_lc2w [DG * D_GNN];
__device__ bf16  g_wo   [DG * DG];
__device__ bf16  g_wf1  [DG * 4 * DG];
__device__ bf16  g_wf2  [4 * DG * DG];
__device__ bf16  g_wqkv [DG * 3 * DG];
__device__ bf16  g_embf [VOCAB * D_GNN];
__device__ int   g_mask_mode;

// ---------------- mask dtype detection ----------------
__global__ void detect_mask_kernel(const int* __restrict__ mr) {
    __shared__ int notint, notflt;
    if (threadIdx.x == 0) { notint = 0; notflt = 0; }
    __syncthreads();
    int w = mr[threadIdx.x];
    if (w != 0 && w != 1)          atomicExch(&notint, 1);
    if (w != 0 && w != 0x3F800000) atomicExch(&notflt, 1);
    __syncthreads();
    if (threadIdx.x == 0)
        g_mask_mode = notint ? (notflt ? 2 : 1) : 0;
}

// ---------------- merged prep ----------------
#define SZ_WMSG  (FD*FD)
#define SZ_WNODE (FD*FD)
#define SZ_LC1   (D_GNN*DG)
#define SZ_LC2   (DG*D_GNN)
#define SZ_WO    (DG*DG)
#define SZ_WF1   (DG*4*DG)
#define SZ_WF2   (4*DG*DG)
#define CW_TOTAL (SZ_WMSG+SZ_WNODE+SZ_LC1+SZ_LC2+SZ_WO+SZ_WF1+SZ_WF2)
#define PREP_TOTAL (CW_TOTAL + VOCAB*D_GNN + DG*DG)

__global__ void prep_all_kernel(const float* Wmsg, const float* Wnode,
                                const float* lc1w, const float* lc2w,
                                const float* Wo, const float* Wf1, const float* Wf2,
                                const float* emb, const float* Wq, const float* Wk,
                                const float* Wv) {
    int i = blockIdx.x * blockDim.x + threadIdx.x;
    if (i >= PREP_TOTAL) return;
    int j = i;
    if (j < SZ_WMSG)  { g_wmsg[j]  = __float2bfloat16_rn(Wmsg[j]);  return; } j -= SZ_WMSG;
    if (j < SZ_WNODE) { g_wnode[j] = __float2bfloat16_rn(Wnode[j]); return; } j -= SZ_WNODE;
    if (j < SZ_LC1)   { g_lc1w[j]  = __float2bfloat16_rn(lc1w[j]);  return; } j -= SZ_LC1;
    if (j < SZ_LC2)   { g_lc2w[j]  = __float2bfloat16_rn(lc2w[j]);  return; } j -= SZ_LC2;
    if (j < SZ_WO)    { g_wo[j]    = __float2bfloat16_rn(Wo[j]);    return; } j -= SZ_WO;
    if (j < SZ_WF1)   { g_wf1[j]   = __float2bfloat16_rn(Wf1[j]);   return; } j -= SZ_WF1;
    if (j < SZ_WF2)   { g_wf2[j]   = __float2bfloat16_rn(Wf2[j]);   return; } j -= SZ_WF2;
    if (j < VOCAB*D_GNN) { g_embf[j] = __float2bfloat16_rn(emb[j]); return; } j -= VOCAB*D_GNN;
    int k = j >> 8, n = j & 255;
    g_wqkv[k * 768 + n]       = __float2bfloat16_rn(Wq[j]);
    g_wqkv[k * 768 + 256 + n] = __float2bfloat16_rn(Wk[j]);
    g_wqkv[k * 768 + 512 + n] = __float2bfloat16_rn(Wv[j]);
}

// merged: node embed + edge embed with inline masking + labels
#define N16 (N_NODES * FD / 8)
#define E16 (N_EDGES * FD / 8)
__global__ void embed_all_kernel(const int* __restrict__ ntok, const int* __restrict__ etok,
                                 const void* __restrict__ maskraw, float* labels_out) {
    int i = blockIdx.x * blockDim.x + threadIdx.x;
    if (i >= N16 + E16) return;
    const uint4* tab = (const uint4*)g_embf;
    if (i < N16) {
        ((uint4*)g_x)[i] = tab[ntok[i >> 3] * 8 + (i & 7)];
    } else {
        int j = i - N16;
        int ti = j >> 3;
        int e  = ti >> 3;
        int t = etok[ti];
        bool mr;
        int mode = g_mask_mode;
        if (mode == 0)      mr = ((const int*)maskraw)[e] != 0;
        else if (mode == 1) mr = ((const float*)maskraw)[e] != 0.0f;
        else                mr = ((const unsigned char*)maskraw)[e] != 0;
        bool msk = mr && (t >= 4);
        int tok = msk ? 4 : t;
        ((uint4*)g_e)[j] = tab[tok * 8 + (j & 7)];
        if ((j & 7) == 0 && labels_out)
            labels_out[ti] = msk ? (float)t : -100.0f;
    }
}

// ================= common helpers =================
__device__ __forceinline__ void cp_async16(uint32_t dst, const void* src, bool pred) {
    int sz = pred ? 16 : 0;
    asm volatile("cp.async.cg.shared.global [%0], [%1], 16, %2;\n"
                 :: "r"(dst), "l"(src), "r"(sz));
}
__device__ __forceinline__ void cp_commit() { asm volatile("cp.async.commit_group;\n"); }
__device__ __forceinline__ void cp_wait0()  { asm volatile("cp.async.wait_group 0;\n"); }
__device__ __forceinline__ void cp_wait1()  { asm volatile("cp.async.wait_group 1;\n"); }

__device__ __forceinline__ void mma_bf16(float c[4], const uint32_t a[4], const uint32_t b[2]) {
    asm volatile(
        "mma.sync.aligned.m16n8k16.row.col.f32.bf16.bf16.f32 "
        "{%0,%1,%2,%3}, {%4,%5,%6,%7}, {%8,%9}, {%0,%1,%2,%3};"
        : "+f"(c[0]), "+f"(c[1]), "+f"(c[2]), "+f"(c[3])
        : "r"(a[0]), "r"(a[1]), "r"(a[2]), "r"(a[3]), "r"(b[0]), "r"(b[1]));
}

__device__ __forceinline__ void ldsm_x4(uint32_t& r0, uint32_t& r1, uint32_t& r2, uint32_t& r3,
                                        uint32_t addr) {
    asm volatile("ldmatrix.sync.aligned.m8n8.x4.shared.b16 {%0,%1,%2,%3}, [%4];"
                 : "=r"(r0), "=r"(r1), "=r"(r2), "=r"(r3) : "r"(addr));
}
__device__ __forceinline__ void ldsm_x4_t(uint32_t& r0, uint32_t& r1, uint32_t& r2, uint32_t& r3,
                                          uint32_t addr) {
    asm volatile("ldmatrix.sync.aligned.m8n8.x4.trans.shared.b16 {%0,%1,%2,%3}, [%4];"
                 : "=r"(r0), "=r"(r1), "=r"(r2), "=r"(r3) : "r"(addr));
}

__device__ __forceinline__ uint4 add_pack8(uint4 ra, uint4 rb) {
    const __nv_bfloat162* ha = (const __nv_bfloat162*)&ra;
    const __nv_bfloat162* hb = (const __nv_bfloat162*)&rb;
    uint4 out;
    __nv_bfloat162* ho = (__nv_bfloat162*)&out;
    #pragma unroll
    for (int j = 0; j < 4; j++) {
        ho[j].x = __float2bfloat16_rn(__bfloat162float(ha[j].x) + __bfloat162float(hb[j].x));
        ho[j].y = __float2bfloat16_rn(__bfloat162float(ha[j].y) + __bfloat162float(hb[j].y));
    }
    return out;
}

// ================= mma.sync bf16 GEMM, TBK=64, M-tile = NMT*32 =================
// EPI: 0 plain | 1 +biasf[n] | 2 relu(+extraf[m*ld+n]) |
//      3 relu(c + extrab[gidx[m]*ld+n]) -> atomicAdd(aggout[gidx2[m]*ld+n])  [no C write]
//      4 +extrab[m*ld+n] | 5 gelu
// GA=1: A row r = g_h[gidx[r>>3]] + g_h[gidx2[r>>3]] slice (r&7)*64 (K must be 64)

#define TBN 128
#define TBK 64
#define ASTRH 72
#define BSTRH 136
#define NSTAGE 3
#define B_STAGE_H (TBK * BSTRH)
#define A_STAGE_OF(NMT) ((NMT) * 32 * ASTRH)
#define GEMM_SMEM_OF(NMT) (NSTAGE * (A_STAGE_OF(NMT) + B_STAGE_H) * 2)

template<int EPI, int GA, int NMT>
__global__ void __launch_bounds__(256)
tmma_k(const bf16* __restrict__ A, const bf16* __restrict__ B, void* __restrict__ Cv,
       int M, int N, int K,
       const float* __restrict__ extraf, const bf16* __restrict__ extrab,
       const int* __restrict__ gidx, const int* __restrict__ gidx2, int ldex,
       float* __restrict__ aggout) {
    extern __shared__ bf16 smem[];
    const int A_STAGE = A_STAGE_OF(NMT);
    bf16* Asm = smem;
    bf16* Bsm = smem + NSTAGE * A_STAGE;

    uint32_t aU = (uint32_t)__cvta_generic_to_shared(Asm);
    uint32_t bU = (uint32_t)__cvta_generic_to_shared(Bsm);

    const int TBM_L = NMT * 32;

    int tid  = threadIdx.x;
    int lane = tid & 31;
    int warp = tid >> 5;
    int wm = warp & 1;
    int wn = warp >> 1;
    int g   = lane >> 2;
    int tig = lane & 3;
    int m0 = blockIdx.y * TBM_L;
    int n0 = blockIdx.x * TBN;

    float acc[NMT][4][4] = {};

    auto issue_load = [&](int s, int k0) {
        #pragma unroll
        for (int i = 0; i < NMT; i++) {
            int id = tid + i * 256;
            int ar = id >> 3, ak = (id & 7) << 3;
            if (GA) {
                int r = m0 + ar;
                int e = r >> 3, l = r & 7;
                const bf16* hs = g_h + (size_t)gidx[e]  * FD + l * 64 + ak;
                const bf16* hd = g_h + (size_t)gidx2[e] * FD + l * 64 + ak;
                uint4 v = add_pack8(*(const uint4*)hs, *(const uint4*)hd);
                *(uint4*)&Asm[s * A_STAGE + ar * ASTRH + ak] = v;
            } else {
                uint32_t da = aU + (s * A_STAGE + ar * ASTRH + ak) * 2;
                cp_async16(da, A + (size_t)(m0 + ar) * K + k0 + ak, true);
            }
        }
        #pragma unroll
        for (int i = 0; i < 4; i++) {
            int id = tid + i * 256;
            int br = id >> 4, bn = (id & 15) << 3;
            int gn = n0 + bn;
            uint32_t db = bU + (s * B_STAGE_H + br * BSTRH + bn) * 2;
            cp_async16(db, B + (size_t)(k0 + br) * N + gn, gn + 8 <= N);
        }
    };

    int niter = K / TBK;
    issue_load(0, 0);
    cp_commit();
    if (niter > 1) { issue_load(1, TBK); cp_commit(); }

    for (int it = 0; it < niter; it++) {
        if (it >= niter - 2) cp_wait0(); else cp_wait1();
        __syncthreads();
        if (it + 2 < niter) {
            issue_load((it + 2) % NSTAGE, (it + 2) * TBK);
            cp_commit();
        }
        int s = it % NSTAGE;
        uint32_t aB = aU + s * A_STAGE * 2;
        uint32_t bB = bU + s * B_STAGE_H * 2;
        #pragma unroll
        for (int ks = 0; ks < TBK; ks += 16) {
            uint32_t af[NMT][4], bfr[4][2];
            #pragma unroll
            for (int mt = 0; mt < NMT; mt++) {
                int row = wm * (NMT * 16) + mt * 16 + (lane & 15);
                uint32_t ad = aB + (row * ASTRH + ks + ((lane >> 4) << 3)) * 2;
                ldsm_x4(af[mt][0], af[mt][1], af[mt][2], af[mt][3], ad);
            }
            #pragma unroll
            for (int bp = 0; bp < 2; bp++) {
                int krow = ks + (lane & 15);
                int ncol = wn * 32 + bp * 16 + ((lane >> 4) << 3);
                uint32_t bd = bB + (krow * BSTRH + ncol) * 2;
                ldsm_x4_t(bfr[2*bp][0], bfr[2*bp][1], bfr[2*bp+1][0], bfr[2*bp+1][1], bd);
            }
            #pragma unroll
            for (int mt = 0; mt < NMT; mt++)
                #pragma unroll
                for (int nt = 0; nt < 4; nt++)
                    mma_bf16(acc[mt][nt], af[mt], bfr[nt]);
        }
    }

    bf16* Cb = (bf16*)Cv;

    #pragma unroll
    for (int mt = 0; mt < NMT; mt++) {
        #pragma unroll
        for (int half = 0; half < 2; half++) {
            int rib = wm * (NMT * 16) + mt * 16 + half * 8 + g;
            int r = m0 + rib;
            int ebase = 0, abase = 0;
            if (EPI == 2 || EPI == 4) ebase = r * ldex;
            if (EPI == 3) { ebase = gidx[r] * ldex; abase = gidx2[r] * ldex; }

            #pragma unroll
            for (int nt = 0; nt < 4; nt++) {
                int n = n0 + wn * 32 + nt * 8 + 2 * tig;
                float c0 = acc[mt][nt][half * 2 + 0];
                float c1 = acc[mt][nt][half * 2 + 1];
                if (EPI == 1) { c0 += extraf[n]; c1 += extraf[n + 1]; }
                else if (EPI == 2) {
                    c0 = fmaxf(c0 + extraf[ebase + n],     0.0f);
                    c1 = fmaxf(c1 + extraf[ebase + n + 1], 0.0f);
                } else if (EPI == 3) {
                    c0 = fmaxf(c0 + __bfloat162float(extrab[ebase + n]),     0.0f);
                    c1 = fmaxf(c1 + __bfloat162float(extrab[ebase + n + 1]), 0.0f);
                    atomicAdd(&aggout[abase + n],     c0);
                    atomicAdd(&aggout[abase + n + 1], c1);
                    continue;
                } else if (EPI == 4) {
                    c0 += __bfloat162float(extrab[ebase + n]);
                    c1 += __bfloat162float(extrab[ebase + n + 1]);
                } else if (EPI == 5) {
                    float x = c0;
                    c0 = 0.5f * x * (1.0f + tanhf(0.7978845608028654f * (x + 0.044715f * x * x * x)));
                    x = c1;
                    c1 = 0.5f * x * (1.0f + tanhf(0.7978845608028654f * (x + 0.044715f * x * x * x)));
                }
                if (n + 1 < N) {
                    __nv_bfloat162 p;
                    p.x = __float2bfloat16_rn(c0);
                    p.y = __float2bfloat16_rn(c1);
                    *(__nv_bfloat162*)&Cb[(size_t)r * N + n] = p;
                }
            }
        }
    }
}

// ================= fused persistent LM head, M=64 rows/CTA, base-2 logit domain =================
#define LMSTR    144
#define LM_A_B   (64 * LMSTR)
#define LM_BSTG  (128 * LMSTR)
#define LM_B_OFF LM_A_B
#define LM_NTILE 79
#define LM_X2_OFF  LM_A_B
#define LM_W2_OFF  (LM_A_B + 64 * 528)
#define LM_STAT_OFF (LM_W2_OFF + 256 * 144)
#define LM_SMEM_TOT (LM_STAT_OFF + 64 * 4 * 8 + 64 * 8)

__global__ void __launch_bounds__(256, 2)
lm_fused(float* __restrict__ probs, const float* __restrict__ lc2b) {
    extern __shared__ char smc[];
    uint32_t aU = (uint32_t)__cvta_generic_to_shared(smc);
    uint32_t bU = aU + LM_B_OFF;
    float2* spart = (float2*)(smc + LM_STAT_OFF);
    float2* sstat = spart + 64 * 4;

    int tid = threadIdx.x;
    int lane = tid & 31, warp = tid >> 5;
    int wm = warp & 1, wn = warp >> 1;
    int g = lane >> 2, tig = lane & 3;
    int m0 = blockIdx.x * 64;

    // ---- preamble: y[64,64] = (x2[64,256] @ lc2w + b) * log2(e) -> A region ----
    // logits come out of the MMA pre-scaled: l' = l * log2e. exp2(l'-m') == exp(l-m).
    {
        uint32_t xU = aU + LM_X2_OFF;
        uint32_t wU = aU + LM_W2_OFF;
        const char* X2b = (const char*)g_x2;
        #pragma unroll
        for (int i = 0; i < 8; i++) {
            int id = tid + i * 256;
            int row = id >> 5, c = (id & 31) << 4;
            cp_async16(xU + row * 528 + c, X2b + (size_t)(m0 + row) * 512 + c, true);
        }
        const char* W2b = (const char*)g_lc2w;
        #pragma unroll
        for (int i = 0; i < 8; i++) {
            int id = tid + i * 256;
            int row = id >> 3, c = (id & 7) << 4;
            cp_async16(wU + row * 144 + c, W2b + (size_t)row * 128 + c, true);
        }
        cp_commit(); cp_wait0();
        __syncthreads();

        int pw_r = warp & 3;
        int pw_c = warp >> 2;
        float yacc[4][4] = {};
        #pragma unroll
        for (int ks = 0; ks < 16; ks++) {
            uint32_t axf[4];
            uint32_t ad = xU + (pw_r * 16 + (lane & 15)) * 528
                        + (ks * 16 + ((lane >> 4) << 3)) * 2;
            ldsm_x4(axf[0], axf[1], axf[2], axf[3], ad);
            uint32_t bw[4][2];
            #pragma unroll
            for (int p = 0; p < 2; p++) {
                uint32_t bd = wU + (ks * 16 + (lane & 15)) * 144
                            + (pw_c * 32 + p * 16 + ((lane >> 4) << 3)) * 2;
                ldsm_x4_t(bw[2*p][0], bw[2*p][1], bw[2*p+1][0], bw[2*p+1][1], bd);
            }
            #pragma unroll
            for (int nt = 0; nt < 4; nt++)
                mma_bf16(yacc[nt], axf, bw[nt]);
        }
        __syncthreads();

        #pragma unroll
        for (int half = 0; half < 2; half++) {
            int rib = pw_r * 16 + half * 8 + g;
            #pragma unroll
            for (int nt = 0; nt < 4; nt++) {
                int col = pw_c * 32 + nt * 8 + 2 * tig;
                float v0 = (yacc[nt][half * 2 + 0] + lc2b[col])     * LOG2E;
                float v1 = (yacc[nt][half * 2 + 1] + lc2b[col + 1]) * LOG2E;
                __nv_bfloat162 p;
                p.x = __float2bfloat16_rn(v0);
                p.y = __float2bfloat16_rn(v1);
                *(__nv_bfloat162*)(smc + rib * LMSTR + col * 2) = p;
            }
        }
        __syncthreads();
    }

    auto issue_B = [&](int stage, int t) {
        const char* Bb = (const char*)g_embf;
        #pragma unroll
        for (int i = 0; i < 4; i++) {
            int id = tid + i * 256;
            int row = id >> 3, c = (id & 7) << 4;
            int v = t * 128 + row;
            cp_async16(bU + stage * LM_BSTG + row * LMSTR + c,
                       Bb + (size_t)v * 128 + c, v < VOCAB);
        }
        cp_commit();
    };

    issue_B(0, 0);
    issue_B(1, 1);

    uint32_t af[2][4][4];
    #pragma unroll
    for (int mt = 0; mt < 2; mt++)
        #pragma unroll
        for (int ks = 0; ks < 4; ks++) {
            uint32_t ad = aU + (wm * 32 + mt * 16 + (lane & 15)) * LMSTR
                        + ks * 32 + ((lane >> 4) << 4);
            ldsm_x4(af[mt][ks][0], af[mt][ks][1], af[mt][ks][2], af[mt][ks][3], ad);
        }

    float rm[4], rs[4];
    #pragma unroll
    for (int s = 0; s < 4; s++) { rm[s] = -1e30f; rs[s] = 0.0f; }

    int brow = (lane & 7) + ((lane >> 4) << 3);
    int bcol16 = ((lane >> 3) & 1) << 4;

    // ======== PASS 1: stats (base-2 domain, exp2f = pure MUFU) ========
    for (int t = 0; t < LM_NTILE; t++) {
        if (t == LM_NTILE - 1) cp_wait0(); else cp_wait1();
        __syncthreads();
        if (t + 2 < LM_NTILE) issue_B((t + 2) % 3, t + 2);

        uint32_t bB = bU + (t % 3) * LM_BSTG;
        float acc[2][4][4] = {};
        #pragma unroll
        for (int ks = 0; ks < 4; ks++) {
            uint32_t bfr[4][2];
            #pragma unroll
            for (int p = 0; p < 2; p++) {
                uint32_t bd = bB + (wn * 32 + p * 16 + brow) * LMSTR + ks * 32 + bcol16;
                ldsm_x4(bfr[2*p][0], bfr[2*p][1], bfr[2*p+1][0], bfr[2*p+1][1], bd);
            }
            #pragma unroll
            for (int mt = 0; mt < 2; mt++)
                #pragma unroll
                for (int nt = 0; nt < 4; nt++)
                    mma_bf16(acc[mt][nt], af[mt][ks], bfr[nt]);
        }

        int nb0 = t * 128 + wn * 32 + 2 * tig;
        #pragma unroll
        for (int mt = 0; mt < 2; mt++)
            #pragma unroll
            for (int half = 0; half < 2; half++) {
                int slot = mt * 2 + half;
                float v[8];
                float bm = -1e30f;
                #pragma unroll
                for (int nt = 0; nt < 4; nt++)
                    #pragma unroll
                    for (int j = 0; j < 2; j++) {
                        int n = nb0 + nt * 8 + j;
                        float x = (n < VOCAB) ? acc[mt][nt][half * 2 + j] : -1e30f;
                        v[nt * 2 + j] = x;
                        bm = fmaxf(bm, x);
                    }
                float nm = fmaxf(rm[slot], bm);
                float add = 0.0f;
                #pragma unroll
                for (int j = 0; j < 8; j++) add += exp2f(v[j] - nm);
                rs[slot] = rs[slot] * exp2f(rm[slot] - nm) + add;
                rm[slot] = nm;
            }
    }

    // ---- reduce stats ----
    #pragma unroll
    for (int slot = 0; slot < 4; slot++) {
        float m = rm[slot], s = rs[slot];
        #pragma unroll
        for (int off = 1; off <= 2; off <<= 1) {
            float om = __shfl_xor_sync(0xffffffffu, m, off);
            float os = __shfl_xor_sync(0xffffffffu, s, off);
            float nm = fmaxf(m, om);
            s = s * exp2f(m - nm) + os * exp2f(om - nm);
            m = nm;
        }
        int mt = slot >> 1, half = slot & 1;
        int rib = wm * 32 + mt * 16 + half * 8 + g;
        if (tig == 0) spart[rib * 4 + wn] = make_float2(m, s);
    }
    __syncthreads();
    if (tid < 64) {
        float m = -1e30f, s = 0.0f;
        #pragma unroll
        for (int w = 0; w < 4; w++) {
            float2 p = spart[tid * 4 + w];
            float nm = fmaxf(m, p.x);
            s = s * exp2f(m - nm) + p.y * exp2f(p.x - nm);
            m = nm;
        }
        sstat[tid] = make_float2(m, 1.0f / s);
    }
    __syncthreads();

    float stm[4], sti[4];
    #pragma unroll
    for (int slot = 0; slot < 4; slot++) {
        int mt = slot >> 1, half = slot & 1;
        int rib = wm * 32 + mt * 16 + half * 8 + g;
        float2 st = sstat[rib];
        stm[slot] = st.x; sti[slot] = st.y;
    }

    // ======== PASS 2: recompute + write probs ========
    issue_B(0, 0);
    issue_B(1, 1);
    for (int t = 0; t < LM_NTILE; t++) {
        if (t == LM_NTILE - 1) cp_wait0(); else cp_wait1();
        __syncthreads();
        if (t + 2 < LM_NTILE) issue_B((t + 2) % 3, t + 2);

        uint32_t bB = bU + (t % 3) * LM_BSTG;
        float acc[2][4][4] = {};
        #pragma unroll
        for (int ks = 0; ks < 4; ks++) {
            uint32_t bfr[4][2];
            #pragma unroll
            for (int p = 0; p < 2; p++) {
                uint32_t bd = bB + (wn * 32 + p * 16 + brow) * LMSTR + ks * 32 + bcol16;
                ldsm_x4(bfr[2*p][0], bfr[2*p][1], bfr[2*p+1][0], bfr[2*p+1][1], bd);
            }
            #pragma unroll
            for (int mt = 0; mt < 2; mt++)
                #pragma unroll
                for (int nt = 0; nt < 4; nt++)
                    mma_bf16(acc[mt][nt], af[mt][ks], bfr[nt]);
        }

        int nb0 = t * 128 + wn * 32 + 2 * tig;
        #pragma unroll
        for (int mt = 0; mt < 2; mt++)
            #pragma unroll
            for (int half = 0; half < 2; half++) {
                int slot = mt * 2 + half;
                int rib = wm * 32 + mt * 16 + half * 8 + g;
                size_t rowoff = (size_t)(m0 + rib) * VOCAB;
                float m = stm[slot], inv = sti[slot];
                #pragma unroll
                for (int nt = 0; nt < 4; nt++) {
                    int n = nb0 + nt * 8;
                    if (n < VOCAB) {
                        float p0 = exp2f(acc[mt][nt][half * 2 + 0] - m) * inv;
                        float p1 = exp2f(acc[mt][nt][half * 2 + 1] - m) * inv;
                        __stcs((float2*)&probs[rowoff + n], make_float2(p0, p1));
                    }
                }
            }
    }
}

// ---------------- attention ----------------
__global__ void __launch_bounds__(256) attention_kernel() {
    __shared__ float qs[8][DG], ks[8][DG], vs[8][DG];
    int b = blockIdx.x;
    int tid = threadIdx.x;
    for (int i = tid; i < 8 * DG; i += 256) {
        int s = i >> 8, c = i & 255;
        size_t off = (size_t)(b * 8 + s) * 768 + c;
        qs[s][c] = __bfloat162float(g_qkv[off]);
        ks[s][c] = __bfloat162float(g_qkv[off + 256]);
        vs[s][c] = __bfloat162float(g_qkv[off + 512]);
    }
    __syncthreads();

    int h  = tid >> 6;
    int qx = (tid >> 3) & 7;
    int kx = tid & 7;
    float att = 0.0f;
    #pragma unroll
    for (int d = 0; d < HD; d++)
        att += qs[qx][h * HD + d] * ks[kx][h * HD + d];
    att *= 0.125f;

    float mx = att;
    mx = fmaxf(mx, __shfl_xor_sync(0xffffffffu, mx, 4));
    mx = fmaxf(mx, __shfl_xor_sync(0xffffffffu, mx, 2));
    mx = fmaxf(mx, __shfl_xor_sync(0xffffffffu, mx, 1));
    float ex = expf(att - mx);
    float sm = ex;
    sm += __shfl_xor_sync(0xffffffffu, sm, 4);
    sm += __shfl_xor_sync(0xffffffffu, sm, 2);
    sm += __shfl_xor_sync(0xffffffffu, sm, 1);
    float a = ex / sm;

    int lane = tid & 31;
    int base = lane & ~7;
    float a_all[8];
    #pragma unroll
    for (int kk = 0; kk < 8; kk++)
        a_all[kk] = __shfl_sync(0xffffffffu, a, base + kk);

    #pragma unroll
    for (int t2 = 0; t2 < 8; t2++) {
        int d = kx * 8 + t2;
        float o = 0.0f;
        #pragma unroll
        for (int kk = 0; kk < 8; kk++)
            o += a_all[kk] * vs[kk][h * HD + d];
        g_ao[(size_t)(b * 8 + qx) * DG + h * HD + d] = __float2bfloat16_rn(o);
    }
}

// ---------------- host launcher ----------------
template<int EPI, int GA, int NMT>
static void launch_one(const bf16* A, const bf16* B, void* C, int M, int N, int K,
                       const float* extraf, const bf16* extrab,
                       const int* gidx, const int* gidx2, int ldex, float* aggout) {
    static bool attr_done = false;
    if (!attr_done) {
        cudaFuncSetAttribute((tmma_k<EPI, GA, NMT>), cudaFuncAttributeMaxDynamicSharedMemorySize,
                             GEMM_SMEM_OF(NMT));
        attr_done = true;
    }
    dim3 grid((N + TBN - 1) / TBN, M / (NMT * 32)), blk(256);
    tmma_k<EPI, GA, NMT><<<grid, blk, GEMM_SMEM_OF(NMT)>>>(A, B, C, M, N, K, extraf, extrab,
                                                           gidx, gidx2, ldex, aggout);
}

template <typename T>
static T* sym_addr(const void* sym) {
    void* p = nullptr;
    cudaGetSymbolAddress(&p, sym);
    return (T*)p;
}

extern "C" void kernel_launch(void* const* d_in, const int* in_sizes, int n_in,
                              void* d_out, int out_size) {
    const int*   node_tokens = (const int*)d_in[0];
    const int*   edge_tokens = (const int*)d_in[1];
    const int*   edge_index  = (const int*)d_in[2];
    const void*  mask_rows   = d_in[3];
    const float* emb    = (const float*)d_in[4];
    const float* W_msg  = (const float*)d_in[5];
    const float* W_node = (const float*)d_in[6];
    const float* lc1_w  = (const float*)d_in[7];
    const float* lc1_b  = (const float*)d_in[8];
    const float* lc2_w  = (const float*)d_in[9];
    const float* lc2_b  = (const float*)d_in[10];
    const float* Wq  = (const float*)d_in[11];
    const float* Wk  = (const float*)d_in[12];
    const float* Wv  = (const float*)d_in[13];
    const float* Wo  = (const float*)d_in[14];
    const float* Wf1 = (const float*)d_in[15];
    const float* Wf2 = (const float*)d_in[16];

    float* out = (float*)d_out;
    bool concat = (out_size != ROWS * VOCAB);
    float* labels_out = concat ? out : nullptr;
    float* probs      = concat ? out + ROWS : out;

    const int* src = edge_index;
    const int* dst = edge_index + N_EDGES;

    bf16* px   = sym_addr<bf16>(g_x);
    bf16* pe   = sym_addr<bf16>(g_e);
    float* pagg= sym_addr<float>(g_agg);
    bf16* ph   = sym_addr<bf16>(g_h);
    bf16* pzg  = sym_addr<bf16>(g_zg);
    bf16* pqkv = sym_addr<bf16>(g_qkv);
    bf16* pao  = sym_addr<bf16>(g_ao);
    bf16* px1  = sym_addr<bf16>(g_x1);
    bf16* pffn = sym_addr<bf16>(g_ffn);
    bf16* px2  = sym_addr<bf16>(g_x2);
    bf16* pwmsg = sym_addr<bf16>(g_wmsg);
    bf16* pwnode= sym_addr<bf16>(g_wnode);
    bf16* plc1w = sym_addr<bf16>(g_lc1w);
    bf16* pwo   = sym_addr<bf16>(g_wo);
    bf16* pwf1  = sym_addr<bf16>(g_wf1);
    bf16* pwf2  = sym_addr<bf16>(g_wf2);
    bf16* pwqkv = sym_addr<bf16>(g_wqkv);

    // 1. mask dtype detect + merged prep + agg clear
    detect_mask_kernel<<<1, 512>>>((const int*)mask_rows);
    prep_all_kernel<<<(PREP_TOTAL + 255) / 256, 256>>>(W_msg, W_node, lc1_w, lc2_w,
                                                       Wo, Wf1, Wf2, emb, Wq, Wk, Wv);
    cudaMemsetAsync(pagg, 0, (size_t)N_NODES * FD * sizeof(float));

    // 2. merged embeddings
    embed_all_kernel<<<(N16 + E16 + 255) / 256, 256>>>(node_tokens, edge_tokens,
                                                       mask_rows, labels_out);

    // 3. GNN
    launch_one<3,0,1>(pe, pwmsg, nullptr, N_EDGES, FD, FD, nullptr, px, src, dst, FD, pagg);
    launch_one<2,0,4>(px, pwnode, ph, N_NODES, FD, FD, pagg, nullptr, nullptr, nullptr, FD, nullptr);

    // 4. lc1 with fused edge gather
    launch_one<1,1,4>(nullptr, plc1w, pzg, ROWS, DG, D_GNN, lc1_b, nullptr, src, dst, 0, nullptr);

    // 5. transformer
    launch_one<0,0,4>(pzg, pwqkv, pqkv, ROWS, 3 * DG, DG, nullptr, nullptr, nullptr, nullptr, 0, nullptr);
    attention_kernel<<<N_EDGES, 256>>>();
    launch_one<4,0,4>(pao, pwo, px1, ROWS, DG, DG, nullptr, pzg, nullptr, nullptr, DG, nullptr);
    launch_one<5,0,4>(px1, pwf1, pffn, ROWS, 4 * DG, DG, nullptr, nullptr, nullptr, nullptr, 0, nullptr);
    launch_one<4,0,4>(pffn, pwf2, px2, ROWS, DG, 4 * DG, nullptr, px1, nullptr, nullptr, DG, nullptr);

    // 6. fused LM head (base-2 logits, exp2f)
    {
        static bool lm_attr = false;
        if (!lm_attr) {
            cudaFuncSetAttribute(lm_fused, cudaFuncAttributeMaxDynamicSharedMemorySize,
                                 LM_SMEM_TOT);
            lm_attr = true;
        }
        lm_fused<<<ROWS / 64, 256, LM_SMEM_TOT>>>(probs, lc2_b);
    }
}